// round 1
// baseline (speedup 1.0000x reference)
#include <cuda_runtime.h>
#include <math.h>
#include <math_constants.h>

// Problem dims (fixed by setup_inputs)
#define M_TOK 16384      // B*S = 8*2048
#define DM    1024       // d_model
#define DR    128        // d_reason
#define NOPS  32
#define NSLOTS 16
#define OPSZ  (DR*DR)            // 16384
#define NASSIGN (M_TOK*2)        // 32768 (top_k=2)
#define DEPTH 2

// ---------------- scratch (__device__ globals; no allocation allowed) -------
__device__ float g_reason [M_TOK*DR];
__device__ float g_tmp    [M_TOK*DR];
__device__ float g_key    [M_TOK*DR];
__device__ float g_cat    [M_TOK*2*DR];     // [op_out | mem_out] per token
__device__ float g_contrib[NASSIGN*DR];
__device__ float g_WdownE [DR*DM];
__device__ float g_WupE   [DM*DR];
__device__ float g_WrouterE[NOPS*DR];
__device__ float g_opsE   [NOPS*OPSZ];
__device__ float g_Wsum   [OPSZ];
__device__ float g_scales [NOPS+4];
__device__ int   g_idx    [NASSIGN];
__device__ float g_w      [NASSIGN];
__device__ int   g_counts [NOPS];
__device__ int   g_offsets[NOPS+1];
__device__ int   g_cursor [NOPS];
__device__ int   g_perm   [NASSIGN];
__device__ int   g_pos    [NASSIGN];

// ---------------- quantization --------------------------------------------
// scale = max(mean|w|, 1e-5) per matrix; blockIdx.x selects matrix (stride n)
__global__ void absmean_kernel(const float* __restrict__ w, int n, int slot) {
    const float* p = w + (size_t)blockIdx.x * n;
    float s = 0.f;
    for (int i = threadIdx.x; i < n; i += blockDim.x) s += fabsf(p[i]);
    __shared__ float red[32];
    int lane = threadIdx.x & 31, wid = threadIdx.x >> 5;
    #pragma unroll
    for (int o = 16; o; o >>= 1) s += __shfl_xor_sync(~0u, s, o);
    if (lane == 0) red[wid] = s;
    __syncthreads();
    if (wid == 0) {
        int nw = blockDim.x >> 5;
        s = (lane < nw) ? red[lane] : 0.f;
        #pragma unroll
        for (int o = 16; o; o >>= 1) s += __shfl_xor_sync(~0u, s, o);
        if (lane == 0) g_scales[slot + blockIdx.x] = fmaxf(s / (float)n, 1e-5f);
    }
}

// w_eff = clip(round(w/scale),-1,1)*scale   (rintf = round-half-even = jnp.round)
__global__ void quant_kernel(const float* __restrict__ w, float* __restrict__ o,
                             int per, int slot, int n) {
    int i = blockIdx.x * blockDim.x + threadIdx.x;
    if (i < n) {
        float s = g_scales[slot + i / per];
        float q = rintf(w[i] / s);
        q = fminf(1.f, fmaxf(-1.f, q));
        o[i] = q * s;
    }
}

__global__ void wsum_kernel() {
    int i = blockIdx.x * blockDim.x + threadIdx.x;
    if (i < OPSZ) {
        float s = 0.f;
        #pragma unroll
        for (int n = 0; n < NOPS; n++) s += g_opsE[n * OPSZ + i];
        g_Wsum[i] = s;
    }
}

// ---------------- generic tiled SGEMM: C = alpha * A(MxK) @ B(NxK)^T (+res) --
// BM=BN=128, BK=16, 256 threads, 8x8 micro-tile. All dims divisible.
__global__ void __launch_bounds__(256)
gemm_tn(const float* __restrict__ A, int lda,
        const float* __restrict__ B, int ldb,
        float* __restrict__ C, int ldc,
        int K, float alpha,
        const float* __restrict__ res, int ldr) {
    __shared__ float As[16][128];
    __shared__ float Bs[16][128];
    const int bm = blockIdx.x * 128;
    const int bn = blockIdx.y * 128;
    const int tid = threadIdx.x;
    const int tx = tid & 15, ty = tid >> 4;
    float acc[8][8] = {};
    for (int k0 = 0; k0 < K; k0 += 16) {
        #pragma unroll
        for (int i = 0; i < 2; i++) {
            int idx = tid + i * 256;          // 0..511 float4 slots
            int row = idx >> 2;               // 0..127
            int c4  = (idx & 3) * 4;          // 0,4,8,12
            float4 a = *(const float4*)(A + (size_t)(bm + row) * lda + k0 + c4);
            As[c4+0][row] = a.x; As[c4+1][row] = a.y; As[c4+2][row] = a.z; As[c4+3][row] = a.w;
            float4 b = *(const float4*)(B + (size_t)(bn + row) * ldb + k0 + c4);
            Bs[c4+0][row] = b.x; Bs[c4+1][row] = b.y; Bs[c4+2][row] = b.z; Bs[c4+3][row] = b.w;
        }
        __syncthreads();
        #pragma unroll
        for (int k = 0; k < 16; k++) {
            float a[8], b[8];
            #pragma unroll
            for (int i = 0; i < 8; i++) a[i] = As[k][ty * 8 + i];
            #pragma unroll
            for (int j = 0; j < 8; j++) b[j] = Bs[k][tx * 8 + j];
            #pragma unroll
            for (int i = 0; i < 8; i++)
                #pragma unroll
                for (int j = 0; j < 8; j++) acc[i][j] += a[i] * b[j];
        }
        __syncthreads();
    }
    #pragma unroll
    for (int i = 0; i < 8; i++) {
        int r = bm + ty * 8 + i;
        #pragma unroll
        for (int j = 0; j < 8; j += 4) {
            int c = bn + tx * 8 + j;
            float4 v;
            v.x = alpha * acc[i][j+0];
            v.y = alpha * acc[i][j+1];
            v.z = alpha * acc[i][j+2];
            v.w = alpha * acc[i][j+3];
            if (res) {
                const float* rp = res + (size_t)r * ldr + c;
                v.x += rp[0]; v.y += rp[1]; v.z += rp[2]; v.w += rp[3];
            }
            *(float4*)(C + (size_t)r * ldc + c) = v;
        }
    }
}

// ---------------- router: logits -> top2 -> softmax weights + histogram -----
__global__ void __launch_bounds__(128)
router_kernel() {
    __shared__ float Wsm[NOPS][DR + 1];
    __shared__ float rsm[4][DR];
    int tid = threadIdx.x;
    for (int i = tid; i < NOPS * DR; i += 128) Wsm[i >> 7][i & 127] = g_WrouterE[i];
    __syncthreads();
    int warp = tid >> 5, lane = tid & 31;
    for (int t = blockIdx.x * 4 + warp; t < M_TOK; t += gridDim.x * 4) {
        float4 v = ((const float4*)(g_reason + (size_t)t * DR))[lane];
        ((float4*)rsm[warp])[lane] = v;
        __syncwarp();
        float logit = 0.f;
        #pragma unroll 8
        for (int k = 0; k < DR; k++) logit += rsm[warp][k] * Wsm[lane][k];
        // top-1 (tie -> lower index, matching top_k)
        float m1 = logit; int i1 = lane;
        #pragma unroll
        for (int o = 16; o; o >>= 1) {
            float om = __shfl_xor_sync(~0u, m1, o);
            int   oi = __shfl_xor_sync(~0u, i1, o);
            if (om > m1 || (om == m1 && oi < i1)) { m1 = om; i1 = oi; }
        }
        float l2 = (lane == i1) ? -CUDART_INF_F : logit;
        float m2 = l2; int i2 = lane;
        #pragma unroll
        for (int o = 16; o; o >>= 1) {
            float om = __shfl_xor_sync(~0u, m2, o);
            int   oi = __shfl_xor_sync(~0u, i2, o);
            if (om > m2 || (om == m2 && oi < i2)) { m2 = om; i2 = oi; }
        }
        if (lane == 0) {
            float e = expf(m2 - m1);
            g_idx[2*t]   = i1; g_idx[2*t+1] = i2;
            g_w[2*t]     = 1.f / (1.f + e);
            g_w[2*t+1]   = e / (1.f + e);
            atomicAdd(&g_counts[i1], 1);
            atomicAdd(&g_counts[i2], 1);
        }
        __syncwarp();
    }
}

__global__ void zero_counts_kernel() { if (threadIdx.x < NOPS) g_counts[threadIdx.x] = 0; }

__global__ void scan_kernel() {
    int lane = threadIdx.x;  // 32 threads
    int c = g_counts[lane];
    int x = c;
    #pragma unroll
    for (int o = 1; o < 32; o <<= 1) {
        int n = __shfl_up_sync(~0u, x, o);
        if (lane >= o) x += n;
    }
    g_offsets[lane + 1] = x;
    if (lane == 0) g_offsets[0] = 0;
    g_cursor[lane] = x - c;
}

__global__ void scatter_kernel() {
    int i = blockIdx.x * blockDim.x + threadIdx.x;
    if (i < NASSIGN) {
        int op = g_idx[i];
        int p = atomicAdd(&g_cursor[op], 1);
        g_perm[p] = i >> 1;      // token id
        g_pos[i]  = p;
    }
}

// ---------------- expert GEMM: contrib[pos] = reason[perm[pos]] @ opsE[o]^T --
__global__ void __launch_bounds__(256)
expert_gemm() {
    int o = blockIdx.y;
    int start = g_offsets[o];
    int cnt = g_offsets[o + 1] - start;
    const float* Bw = g_opsE + (size_t)o * OPSZ;
    __shared__ float As[16][128];
    __shared__ float Bs[16][128];
    __shared__ int   rowid[128];
    int tid = threadIdx.x;
    int tx = tid & 15, ty = tid >> 4;
    for (int t0 = blockIdx.x * 128; t0 < cnt; t0 += gridDim.x * 128) {
        if (tid < 128) rowid[tid] = (t0 + tid < cnt) ? g_perm[start + t0 + tid] : -1;
        __syncthreads();
        float acc[8][8] = {};
        for (int k0 = 0; k0 < DR; k0 += 16) {
            #pragma unroll
            for (int i = 0; i < 2; i++) {
                int idx = tid + i * 256;
                int row = idx >> 2;
                int c4  = (idx & 3) * 4;
                int gt = rowid[row];
                float4 a = (gt >= 0) ? *(const float4*)(g_reason + (size_t)gt * DR + k0 + c4)
                                     : make_float4(0.f, 0.f, 0.f, 0.f);
                As[c4+0][row] = a.x; As[c4+1][row] = a.y; As[c4+2][row] = a.z; As[c4+3][row] = a.w;
                float4 b = *(const float4*)(Bw + (size_t)row * DR + k0 + c4);
                Bs[c4+0][row] = b.x; Bs[c4+1][row] = b.y; Bs[c4+2][row] = b.z; Bs[c4+3][row] = b.w;
            }
            __syncthreads();
            #pragma unroll
            for (int k = 0; k < 16; k++) {
                float a[8], b[8];
                #pragma unroll
                for (int i = 0; i < 8; i++) a[i] = As[k][ty * 8 + i];
                #pragma unroll
                for (int j = 0; j < 8; j++) b[j] = Bs[k][tx * 8 + j];
                #pragma unroll
                for (int i = 0; i < 8; i++)
                    #pragma unroll
                    for (int j = 0; j < 8; j++) acc[i][j] += a[i] * b[j];
            }
            __syncthreads();
        }
        #pragma unroll
        for (int i = 0; i < 8; i++) {
            int r = t0 + ty * 8 + i;
            if (r < cnt) {
                float* cp = g_contrib + (size_t)(start + r) * DR + tx * 8;
                #pragma unroll
                for (int j = 0; j < 8; j += 4) {
                    float4 v = make_float4(acc[i][j], acc[i][j+1], acc[i][j+2], acc[i][j+3]);
                    *(float4*)(cp + j) = v;
                }
            }
        }
        __syncthreads();
    }
}

// ---------------- combine: op_out += w0*contrib[p0] + w1*contrib[p1] --------
__global__ void combine_kernel() {
    int t = blockIdx.x, d = threadIdx.x;  // 16384 blocks x 128
    float w0 = g_w[2*t], w1 = g_w[2*t+1];
    int p0 = g_pos[2*t], p1 = g_pos[2*t+1];
    g_cat[(size_t)t * 256 + d] += w0 * g_contrib[(size_t)p0 * DR + d]
                                + w1 * g_contrib[(size_t)p1 * DR + d];
}

// ---------------- memory read: attn over slots from g_key ------------------
__global__ void __launch_bounds__(128)
memread_kernel(const float* __restrict__ slots) {
    __shared__ float ssm[NSLOTS][DR + 1];
    __shared__ float rsm[4][DR];
    __shared__ float attn_s[4][NSLOTS];
    int tid = threadIdx.x;
    for (int i = tid; i < NSLOTS * DR; i += 128) ssm[i >> 7][i & 127] = slots[i];
    __syncthreads();
    int warp = tid >> 5, lane = tid & 31;
    const float inv_sqrt_d = 0.08838834764831845f;  // 1/sqrt(128)
    for (int t = blockIdx.x * 4 + warp; t < M_TOK; t += gridDim.x * 4) {
        float4 v = ((const float4*)(g_key + (size_t)t * DR))[lane];
        ((float4*)rsm[warp])[lane] = v;
        __syncwarp();
        float logit = -CUDART_INF_F;
        if (lane < NSLOTS) {
            float s = 0.f;
            #pragma unroll 8
            for (int k = 0; k < DR; k++) s += rsm[warp][k] * ssm[lane][k];
            logit = s * inv_sqrt_d;
        }
        float mx = logit;
        #pragma unroll
        for (int o = 16; o; o >>= 1) mx = fmaxf(mx, __shfl_xor_sync(~0u, mx, o));
        float e = (lane < NSLOTS) ? expf(logit - mx) : 0.f;
        float se = e;
        #pragma unroll
        for (int o = 16; o; o >>= 1) se += __shfl_xor_sync(~0u, se, o);
        if (lane < NSLOTS) attn_s[warp][lane] = e / se;
        __syncwarp();
        float o0 = 0.f, o1 = 0.f, o2 = 0.f, o3 = 0.f;
        #pragma unroll
        for (int s2 = 0; s2 < NSLOTS; s2++) {
            float a = attn_s[warp][s2];
            o0 += a * ssm[s2][lane*4+0];
            o1 += a * ssm[s2][lane*4+1];
            o2 += a * ssm[s2][lane*4+2];
            o3 += a * ssm[s2][lane*4+3];
        }
        ((float4*)(g_cat + (size_t)t * 256 + 128))[lane] = make_float4(o0, o1, o2, o3);
        __syncwarp();
    }
}

// ---------------- layernorm: g_reason = LN(g_tmp) * gamma + beta ------------
__global__ void __launch_bounds__(128)
ln_kernel(const float* __restrict__ gamma, const float* __restrict__ beta) {
    int warp = threadIdx.x >> 5, lane = threadIdx.x & 31;
    for (int t = blockIdx.x * 4 + warp; t < M_TOK; t += gridDim.x * 4) {
        float4 v = ((const float4*)(g_tmp + (size_t)t * DR))[lane];
        float s = v.x + v.y + v.z + v.w;
        float q = v.x*v.x + v.y*v.y + v.z*v.z + v.w*v.w;
        #pragma unroll
        for (int o = 16; o; o >>= 1) {
            s += __shfl_xor_sync(~0u, s, o);
            q += __shfl_xor_sync(~0u, q, o);
        }
        float mean = s * (1.f / 128.f);
        float var = q * (1.f / 128.f) - mean * mean;
        float rs = rsqrtf(var + 1e-5f);
        float4 g = ((const float4*)gamma)[lane];
        float4 b = ((const float4*)beta)[lane];
        float4 o4;
        o4.x = (v.x - mean) * rs * g.x + b.x;
        o4.y = (v.y - mean) * rs * g.y + b.y;
        o4.z = (v.z - mean) * rs * g.z + b.z;
        o4.w = (v.w - mean) * rs * g.w + b.w;
        ((float4*)(g_reason + (size_t)t * DR))[lane] = o4;
    }
}

// ---------------- write signal: reason += ws*(wg*wv + 0.1*addr@slots) -------
// g_key holds wk rows, g_tmp holds wv rows
__global__ void __launch_bounds__(128)
write_kernel(const float* __restrict__ slots, const float* __restrict__ Wg,
             const float* __restrict__ wsp) {
    __shared__ float ssm[NSLOTS][DR + 1];
    __shared__ float wgs[DR];
    __shared__ float rsm[4][DR];
    __shared__ float attn_s[4][NSLOTS];
    int tid = threadIdx.x;
    for (int i = tid; i < NSLOTS * DR; i += 128) ssm[i >> 7][i & 127] = slots[i];
    wgs[tid] = Wg[tid];
    __syncthreads();
    int warp = tid >> 5, lane = tid & 31;
    float ws = *wsp;
    const float inv_sqrt_d = 0.08838834764831845f;
    for (int t = blockIdx.x * 4 + warp; t < M_TOK; t += gridDim.x * 4) {
        float4 r = ((const float4*)(g_reason + (size_t)t * DR))[lane];
        float4 wg4 = ((const float4*)wgs)[lane];
        float gd = r.x*wg4.x + r.y*wg4.y + r.z*wg4.z + r.w*wg4.w;
        #pragma unroll
        for (int o = 16; o; o >>= 1) gd += __shfl_xor_sync(~0u, gd, o);
        float wg = 1.f / (1.f + expf(-gd));
        float4 k4 = ((const float4*)(g_key + (size_t)t * DR))[lane];
        ((float4*)rsm[warp])[lane] = k4;
        __syncwarp();
        float logit = -CUDART_INF_F;
        if (lane < NSLOTS) {
            float sdot = 0.f;
            #pragma unroll 8
            for (int k = 0; k < DR; k++) sdot += rsm[warp][k] * ssm[lane][k];
            logit = sdot * inv_sqrt_d;
        }
        float mx = logit;
        #pragma unroll
        for (int o = 16; o; o >>= 1) mx = fmaxf(mx, __shfl_xor_sync(~0u, mx, o));
        float e = (lane < NSLOTS) ? expf(logit - mx) : 0.f;
        float se = e;
        #pragma unroll
        for (int o = 16; o; o >>= 1) se += __shfl_xor_sync(~0u, se, o);
        if (lane < NSLOTS) attn_s[warp][lane] = e / se;
        __syncwarp();
        float4 wv = ((const float4*)(g_tmp + (size_t)t * DR))[lane];
        float o0 = wg * wv.x, o1 = wg * wv.y, o2 = wg * wv.z, o3 = wg * wv.w;
        #pragma unroll
        for (int s2 = 0; s2 < NSLOTS; s2++) {
            float a = 0.1f * attn_s[warp][s2];
            o0 += a * ssm[s2][lane*4+0];
            o1 += a * ssm[s2][lane*4+1];
            o2 += a * ssm[s2][lane*4+2];
            o3 += a * ssm[s2][lane*4+3];
        }
        float4 out4;
        out4.x = r.x + ws * o0; out4.y = r.y + ws * o1;
        out4.z = r.z + ws * o2; out4.w = r.w + ws * o3;
        ((float4*)(g_reason + (size_t)t * DR))[lane] = out4;
        __syncwarp();
    }
}

// ---------------- launch --------------------------------------------------
extern "C" void kernel_launch(void* const* d_in, const int* in_sizes, int n_in,
                              void* d_out, int out_size) {
    const float* hidden   = (const float*)d_in[0];
    // d_in[1] = force_depth (fixed at 2; loop unrolled host-side)
    const float* W_down   = (const float*)d_in[2];
    const float* W_up     = (const float*)d_in[3];
    const float* ops      = (const float*)d_in[4];
    const float* W_router = (const float*)d_in[5];
    const float* slots    = (const float*)d_in[6];
    const float* W_read   = (const float*)d_in[7];
    const float* W_wk     = (const float*)d_in[8];
    const float* W_wg     = (const float*)d_in[9];
    const float* W_wv     = (const float*)d_in[10];
    const float* W_mix    = (const float*)d_in[11];
    const float* gamma    = (const float*)d_in[12];
    const float* beta     = (const float*)d_in[13];
    const float* wscale   = (const float*)d_in[14];
    float* out = (float*)d_out;

    float *pReason, *pTmp, *pKey, *pCat, *pWdownE, *pWupE, *pWrouterE, *pOpsE, *pWsum;
    cudaGetSymbolAddress((void**)&pReason,   g_reason);
    cudaGetSymbolAddress((void**)&pTmp,      g_tmp);
    cudaGetSymbolAddress((void**)&pKey,      g_key);
    cudaGetSymbolAddress((void**)&pCat,      g_cat);
    cudaGetSymbolAddress((void**)&pWdownE,   g_WdownE);
    cudaGetSymbolAddress((void**)&pWupE,     g_WupE);
    cudaGetSymbolAddress((void**)&pWrouterE, g_WrouterE);
    cudaGetSymbolAddress((void**)&pOpsE,     g_opsE);
    cudaGetSymbolAddress((void**)&pWsum,     g_Wsum);

    // --- quantize weights ---
    absmean_kernel<<<1, 512>>>(W_down, DR * DM, 0);
    absmean_kernel<<<1, 512>>>(W_up, DM * DR, 1);
    absmean_kernel<<<1, 256>>>(W_router, NOPS * DR, 2);
    absmean_kernel<<<NOPS, 256>>>(ops, OPSZ, 3);
    quant_kernel<<<(DR*DM + 255)/256, 256>>>(W_down, pWdownE, DR*DM, 0, DR*DM);
    quant_kernel<<<(DM*DR + 255)/256, 256>>>(W_up, pWupE, DM*DR, 1, DM*DR);
    quant_kernel<<<(NOPS*DR + 255)/256, 256>>>(W_router, pWrouterE, NOPS*DR, 2, NOPS*DR);
    quant_kernel<<<(NOPS*OPSZ + 255)/256, 256>>>(ops, pOpsE, OPSZ, 3, NOPS*OPSZ);
    wsum_kernel<<<(OPSZ + 255)/256, 256>>>();

    // --- down: reason = hidden @ WdownE^T ---
    gemm_tn<<<dim3(M_TOK/128, 1), 256>>>(hidden, DM, pWdownE, DM, pReason, DR,
                                         DM, 1.f, (const float*)nullptr, 0);

    // --- reasoning passes (force_depth = 2) ---
    for (int pass = 0; pass < DEPTH; pass++) {
        zero_counts_kernel<<<1, 32>>>();
        router_kernel<<<148, 128>>>();
        scan_kernel<<<1, 32>>>();
        scatter_kernel<<<NASSIGN/256, 256>>>();
        expert_gemm<<<dim3(16, NOPS), 256>>>();
        // op_out base: (1e-5/32) * reason @ Wsum^T  -> g_cat[:, :128]
        gemm_tn<<<dim3(M_TOK/128, 1), 256>>>(pReason, DR, pWsum, DR, pCat, 256,
                                             DR, 1e-5f / NOPS, (const float*)nullptr, 0);
        combine_kernel<<<M_TOK, 128>>>();
        // mem read: key = reason @ W_read^T (NOT quantized)
        gemm_tn<<<dim3(M_TOK/128, 1), 256>>>(pReason, DR, W_read, DR, pKey, DR,
                                             DR, 1.f, (const float*)nullptr, 0);
        memread_kernel<<<148, 128>>>(slots);
        // mix: tmp = reason + cat @ W_mix^T ; reason = LN(tmp)
        gemm_tn<<<dim3(M_TOK/128, 1), 256>>>(pCat, 2*DR, W_mix, 2*DR, pTmp, DR,
                                             2*DR, 1.f, pReason, DR);
        ln_kernel<<<148, 128>>>(gamma, beta);
    }

    // --- write signal ---
    gemm_tn<<<dim3(M_TOK/128, 1), 256>>>(pReason, DR, W_wk, DR, pKey, DR,
                                         DR, 1.f, (const float*)nullptr, 0);
    gemm_tn<<<dim3(M_TOK/128, 1), 256>>>(pReason, DR, W_wv, DR, pTmp, DR,
                                         DR, 1.f, (const float*)nullptr, 0);
    write_kernel<<<148, 128>>>(slots, W_wg, wscale);

    // --- up: out = hidden + reason @ WupE^T ---
    gemm_tn<<<dim3(M_TOK/128, DM/128), 256>>>(pReason, DR, pWupE, DR, out, DM,
                                              DR, 1.f, hidden, DM);
}

// round 5
// speedup vs baseline: 1.9128x; 1.9128x over previous
#include <cuda_runtime.h>
#include <cuda_bf16.h>
#include <math.h>
#include <math_constants.h>
#include <stdint.h>

// Problem dims (fixed by setup_inputs)
#define M_TOK 16384      // B*S = 8*2048
#define DM    1024       // d_model
#define DR    128        // d_reason
#define NOPS  32
#define NSLOTS 16
#define OPSZ  (DR*DR)            // 16384
#define NASSIGN (M_TOK*2)        // 32768 (top_k=2)
#define DEPTH 2

typedef __nv_bfloat16 bf16;

#define AS_STRIDE 72   // bf16 elements per smem row (64 data + 8 pad)

// ======================= mma.sync helpers (sm_80+, legal on compute_103) ====
__device__ __forceinline__ uint32_t smem_u32(const void* p) {
    uint32_t a;
    asm("{ .reg .u64 t; cvta.to.shared.u64 t, %1; cvt.u32.u64 %0, t; }" : "=r"(a) : "l"(p));
    return a;
}
__device__ __forceinline__ void ldsm_x4(uint32_t& r0, uint32_t& r1, uint32_t& r2,
                                        uint32_t& r3, uint32_t addr) {
    asm volatile("ldmatrix.sync.aligned.m8n8.x4.shared.b16 {%0,%1,%2,%3}, [%4];"
                 : "=r"(r0), "=r"(r1), "=r"(r2), "=r"(r3) : "r"(addr));
}
__device__ __forceinline__ void ldsm_x2(uint32_t& r0, uint32_t& r1, uint32_t addr) {
    asm volatile("ldmatrix.sync.aligned.m8n8.x2.shared.b16 {%0,%1}, [%2];"
                 : "=r"(r0), "=r"(r1) : "r"(addr));
}
__device__ __forceinline__ void mma_bf16(float* d, const uint32_t* a, const uint32_t* b) {
    asm volatile(
        "mma.sync.aligned.m16n8k16.row.col.f32.bf16.bf16.f32 "
        "{%0,%1,%2,%3}, {%4,%5,%6,%7}, {%8,%9}, {%0,%1,%2,%3};"
        : "+f"(d[0]), "+f"(d[1]), "+f"(d[2]), "+f"(d[3])
        : "r"(a[0]), "r"(a[1]), "r"(a[2]), "r"(a[3]), "r"(b[0]), "r"(b[1]));
}

// ======================= scratch (__device__ globals) ======================
__device__ float g_reason [M_TOK*DR];
__device__ float g_tmp    [M_TOK*DR];
__device__ float g_key    [M_TOK*DR];
__device__ float g_opbase [M_TOK*DR];
__device__ float g_contrib[NASSIGN*DR];
__device__ bf16  g_hid_h  [M_TOK*DM];
__device__ bf16  g_hid_l  [M_TOK*DM];
__device__ bf16  g_reason_h[M_TOK*DR];
__device__ bf16  g_reason_l[M_TOK*DR];
__device__ bf16  g_cat_h  [M_TOK*2*DR];
__device__ bf16  g_cat_l  [M_TOK*2*DR];
__device__ bf16  g_qdown  [DR*DM];
__device__ bf16  g_qup    [DM*DR];
__device__ bf16  g_qops   [NOPS*OPSZ];
__device__ bf16  g_wsum_h [OPSZ];
__device__ bf16  g_wread_h[OPSZ],  g_wread_l[OPSZ];
__device__ bf16  g_wwk_h  [OPSZ],  g_wwk_l  [OPSZ];
__device__ bf16  g_wwv_h  [OPSZ],  g_wwv_l  [OPSZ];
__device__ bf16  g_wmix_h [DR*2*DR], g_wmix_l[DR*2*DR];
__device__ float g_WrouterE[NOPS*DR];
__device__ float g_scales [40];
__device__ float g_part   [40*16];
__device__ int   g_idx    [NASSIGN];
__device__ float g_w      [NASSIGN];
__device__ int   g_counts [NOPS];
__device__ int   g_offsets[NOPS+1];
__device__ int   g_cursor [NOPS];
__device__ int   g_perm   [NASSIGN];
__device__ int   g_pos    [NASSIGN];

// ======================= scale computation (deterministic) =================
__global__ void absmean_p1(const float* __restrict__ w, int n, int slotBase) {
    int mat = blockIdx.y, seg = blockIdx.x;      // 16 segs
    int segn = n >> 4;
    const float* p = w + (size_t)mat * n + (size_t)seg * segn;
    float s = 0.f;
    for (int i = threadIdx.x; i < segn; i += blockDim.x) s += fabsf(p[i]);
    __shared__ float red[8];
    int lane = threadIdx.x & 31, wid = threadIdx.x >> 5;
    #pragma unroll
    for (int o = 16; o; o >>= 1) s += __shfl_xor_sync(~0u, s, o);
    if (lane == 0) red[wid] = s;
    __syncthreads();
    if (threadIdx.x == 0) {
        float t = 0.f;
        for (int k = 0; k < (int)(blockDim.x >> 5); k++) t += red[k];
        g_part[(slotBase + mat) * 16 + seg] = t;
    }
}
__global__ void absmean_p2() {
    int slot = threadIdx.x;
    if (slot < 35) {
        float s = 0.f;
        #pragma unroll
        for (int k = 0; k < 16; k++) s += g_part[slot * 16 + k];
        int n = (slot < 2) ? (DR * DM) : (slot == 2 ? (NOPS * DR) : OPSZ);
        g_scales[slot] = fmaxf(s / (float)n, 1e-5f);
    }
}

// ternary quantize -> exact bf16 in {-1,0,1} (scale folded into GEMM alpha)
__global__ void quantb_kernel(const float* __restrict__ w, bf16* __restrict__ q,
                              int per, int slotBase, int n) {
    int i = blockIdx.x * blockDim.x + threadIdx.x;
    if (i < n) {
        float s = g_scales[slotBase + i / per];
        float qq = fminf(1.f, fmaxf(-1.f, rintf(w[i] / s)));
        q[i] = __float2bfloat16(qq);
    }
}
__global__ void quantr_kernel(const float* __restrict__ w) {
    int i = blockIdx.x * blockDim.x + threadIdx.x;
    if (i < NOPS * DR) {
        float s = g_scales[2];
        float qq = fminf(1.f, fmaxf(-1.f, rintf(w[i] / s)));
        g_WrouterE[i] = qq * s;
    }
}
__global__ void wsumh_kernel() {
    int i = blockIdx.x * blockDim.x + threadIdx.x;
    if (i < OPSZ) {
        float s = 0.f;
        #pragma unroll
        for (int n = 0; n < NOPS; n++)
            s += __bfloat162float(g_qops[n * OPSZ + i]) * g_scales[3 + n];
        g_wsum_h[i] = __float2bfloat16(s);
    }
}
__global__ void split_kernel(const float* __restrict__ x, bf16* __restrict__ h,
                             bf16* __restrict__ l, int n) {
    int i = blockIdx.x * blockDim.x + threadIdx.x;
    if (i < n) {
        float v = x[i];
        bf16 hh = __float2bfloat16(v);
        h[i] = hh;
        l[i] = __float2bfloat16(v - __bfloat162float(hh));
    }
}

// ======================= bf16 HMMA GEMM ====================================
// C[128-tile, 128-tile] = alpha * sum_terms( A_t @ B_t^T ) (+res).
// terms: 1={Ah,Bh}; 2=+{Al,Bh}; 3=+{Ah,Bl}. 256 thr, warps 4(M)x2(N), warp 32x64.
__global__ void __launch_bounds__(256)
mma_gemm(const bf16* __restrict__ Ah, const bf16* __restrict__ Al, int lda,
         const bf16* __restrict__ Bh, const bf16* __restrict__ Bl, int ldb,
         float* __restrict__ C, int ldc, int K, int terms,
         float alphaC, const float* __restrict__ alphaPtr,
         const float* __restrict__ res, int ldr,
         bf16* __restrict__ Ch, bf16* __restrict__ Cl)
{
    __shared__ __align__(16) bf16 As[128 * AS_STRIDE];
    __shared__ __align__(16) bf16 Bs[128 * AS_STRIDE];
    const uint32_t sA = smem_u32(As), sB = smem_u32(Bs);
    const int tid = threadIdx.x, lane = tid & 31, wid = tid >> 5;
    const int wm = wid & 3, wn = wid >> 2;
    const int bm = blockIdx.x * 128, bn = blockIdx.y * 128;

    float acc[2][8][4];
    #pragma unroll
    for (int i = 0; i < 2; i++)
        #pragma unroll
        for (int j = 0; j < 8; j++)
            #pragma unroll
            for (int k = 0; k < 4; k++) acc[i][j][k] = 0.f;

    const bf16* Asrc[3] = {Ah, Al, Ah};
    const bf16* Bsrc[3] = {Bh, Bh, Bl};

    // ldmatrix source addresses (element offsets -> bytes)
    const uint32_t aAddrBase = sA + (uint32_t)(((wm * 32 + (lane & 15)) * AS_STRIDE + (lane >> 4) * 8) * 2);
    const uint32_t bAddrBase = sB + (uint32_t)(((wn * 64 + (lane & 7)) * AS_STRIDE + ((lane >> 3) & 1) * 8) * 2);

    for (int t = 0; t < terms; t++) {
        const bf16* A = Asrc[t] + (size_t)bm * lda;
        const bf16* B = Bsrc[t] + (size_t)bn * ldb;
        for (int k0 = 0; k0 < K; k0 += 64) {
            __syncthreads();
            #pragma unroll
            for (int i = 0; i < 4; i++) {
                int slot = i * 256 + tid;        // 0..1023
                int row = slot >> 3;             // 0..127
                int kq = (slot & 7) * 8;         // 0..56
                *(float4*)(As + row * AS_STRIDE + kq) =
                    *(const float4*)(A + (size_t)row * lda + k0 + kq);
                *(float4*)(Bs + row * AS_STRIDE + kq) =
                    *(const float4*)(B + (size_t)row * ldb + k0 + kq);
            }
            __syncthreads();
            #pragma unroll
            for (int kk = 0; kk < 4; kk++) {
                uint32_t a[2][4], b[8][2];
                #pragma unroll
                for (int mf = 0; mf < 2; mf++)
                    ldsm_x4(a[mf][0], a[mf][1], a[mf][2], a[mf][3],
                            aAddrBase + (uint32_t)((mf * 16 * AS_STRIDE + kk * 16) * 2));
                #pragma unroll
                for (int nf = 0; nf < 8; nf++)
                    ldsm_x2(b[nf][0], b[nf][1],
                            bAddrBase + (uint32_t)((nf * 8 * AS_STRIDE + kk * 16) * 2));
                #pragma unroll
                for (int mf = 0; mf < 2; mf++)
                    #pragma unroll
                    for (int nf = 0; nf < 8; nf++)
                        mma_bf16(acc[mf][nf], a[mf], b[nf]);
            }
        }
    }

    float alpha = alphaC * (alphaPtr ? *alphaPtr : 1.0f);
    const int row0 = bm + wm * 32, col0 = bn + wn * 64;
    #pragma unroll
    for (int mf = 0; mf < 2; mf++) {
        #pragma unroll
        for (int half = 0; half < 2; half++) {
            int r = row0 + mf * 16 + (lane >> 2) + half * 8;
            #pragma unroll
            for (int nf = 0; nf < 8; nf++) {
                int c = col0 + nf * 8 + (lane & 3) * 2;
                float vx = alpha * acc[mf][nf][half * 2];
                float vy = alpha * acc[mf][nf][half * 2 + 1];
                if (res) {
                    const float* rp = res + (size_t)r * ldr + c;
                    vx += rp[0]; vy += rp[1];
                }
                float* cp = C + (size_t)r * ldc + c;
                cp[0] = vx; cp[1] = vy;
                if (Ch) {
                    size_t o = (size_t)r * ldc + c;
                    bf16 h0 = __float2bfloat16(vx), h1 = __float2bfloat16(vy);
                    Ch[o] = h0; Ch[o + 1] = h1;
                    Cl[o]     = __float2bfloat16(vx - __bfloat162float(h0));
                    Cl[o + 1] = __float2bfloat16(vy - __bfloat162float(h1));
                }
            }
        }
    }
}

// ======================= expert (gathered) HMMA GEMM ========================
// contrib[pos] = scale_op * reason_split[perm[pos]] @ qops[op]^T
__global__ void __launch_bounds__(256)
expert_mma() {
    int op = blockIdx.y;
    int start = g_offsets[op];
    int cnt = g_offsets[op + 1] - start;
    __shared__ __align__(16) bf16 As[128 * AS_STRIDE];
    __shared__ __align__(16) bf16 Bs[128 * AS_STRIDE];
    __shared__ int rowid[128];
    const uint32_t sA = smem_u32(As), sB = smem_u32(Bs);
    const int tid = threadIdx.x, lane = tid & 31, wid = tid >> 5;
    const int wm = wid & 3, wn = wid >> 2;
    float alpha = g_scales[3 + op];
    const bf16* B0 = g_qops + (size_t)op * OPSZ;

    const uint32_t aAddrBase = sA + (uint32_t)(((wm * 32 + (lane & 15)) * AS_STRIDE + (lane >> 4) * 8) * 2);
    const uint32_t bAddrBase = sB + (uint32_t)(((wn * 64 + (lane & 7)) * AS_STRIDE + ((lane >> 3) & 1) * 8) * 2);

    // B tile (128x128) is tile-invariant: load all 128 k once? K=128 needs 2 chunks.
    for (int t0 = blockIdx.x * 128; t0 < cnt; t0 += gridDim.x * 128) {
        __syncthreads();
        if (tid < 128) rowid[tid] = (t0 + tid < cnt) ? g_perm[start + t0 + tid] : -1;
        __syncthreads();
        float acc[2][8][4];
        #pragma unroll
        for (int i = 0; i < 2; i++)
            #pragma unroll
            for (int j = 0; j < 8; j++)
                #pragma unroll
                for (int k = 0; k < 4; k++) acc[i][j][k] = 0.f;

        #pragma unroll
        for (int t = 0; t < 2; t++) {
            const bf16* Areas = t ? g_reason_l : g_reason_h;
            for (int k0 = 0; k0 < DR; k0 += 64) {
                __syncthreads();
                #pragma unroll
                for (int i = 0; i < 4; i++) {
                    int slot = i * 256 + tid;
                    int row = slot >> 3;
                    int kq = (slot & 7) * 8;
                    int grow = rowid[row];
                    float4 av = (grow >= 0)
                        ? *(const float4*)(Areas + (size_t)grow * DR + k0 + kq)
                        : make_float4(0.f, 0.f, 0.f, 0.f);
                    *(float4*)(As + row * AS_STRIDE + kq) = av;
                    *(float4*)(Bs + row * AS_STRIDE + kq) =
                        *(const float4*)(B0 + (size_t)row * DR + k0 + kq);
                }
                __syncthreads();
                #pragma unroll
                for (int kk = 0; kk < 4; kk++) {
                    uint32_t a[2][4], b[8][2];
                    #pragma unroll
                    for (int mf = 0; mf < 2; mf++)
                        ldsm_x4(a[mf][0], a[mf][1], a[mf][2], a[mf][3],
                                aAddrBase + (uint32_t)((mf * 16 * AS_STRIDE + kk * 16) * 2));
                    #pragma unroll
                    for (int nf = 0; nf < 8; nf++)
                        ldsm_x2(b[nf][0], b[nf][1],
                                bAddrBase + (uint32_t)((nf * 8 * AS_STRIDE + kk * 16) * 2));
                    #pragma unroll
                    for (int mf = 0; mf < 2; mf++)
                        #pragma unroll
                        for (int nf = 0; nf < 8; nf++)
                            mma_bf16(acc[mf][nf], a[mf], b[nf]);
                }
            }
        }
        const int row0 = wm * 32, col0 = wn * 64;
        #pragma unroll
        for (int mf = 0; mf < 2; mf++) {
            #pragma unroll
            for (int half = 0; half < 2; half++) {
                int rl = row0 + mf * 16 + (lane >> 2) + half * 8;
                if (t0 + rl < cnt) {
                    float* cp0 = g_contrib + (size_t)(start + t0 + rl) * DR;
                    #pragma unroll
                    for (int nf = 0; nf < 8; nf++) {
                        int c = col0 + nf * 8 + (lane & 3) * 2;
                        cp0[c]     = alpha * acc[mf][nf][half * 2];
                        cp0[c + 1] = alpha * acc[mf][nf][half * 2 + 1];
                    }
                }
            }
        }
    }
}

// ======================= router / moe bookkeeping ==========================
__global__ void __launch_bounds__(128)
router_kernel() {
    __shared__ float Wsm[NOPS][DR + 1];
    __shared__ float rsm[4][DR];
    int tid = threadIdx.x;
    for (int i = tid; i < NOPS * DR; i += 128) Wsm[i >> 7][i & 127] = g_WrouterE[i];
    __syncthreads();
    int warp = tid >> 5, lane = tid & 31;
    for (int t = blockIdx.x * 4 + warp; t < M_TOK; t += gridDim.x * 4) {
        float4 v = ((const float4*)(g_reason + (size_t)t * DR))[lane];
        ((float4*)rsm[warp])[lane] = v;
        __syncwarp();
        float logit = 0.f;
        #pragma unroll 8
        for (int k = 0; k < DR; k++) logit += rsm[warp][k] * Wsm[lane][k];
        float m1 = logit; int i1 = lane;
        #pragma unroll
        for (int o = 16; o; o >>= 1) {
            float om = __shfl_xor_sync(~0u, m1, o);
            int   oi = __shfl_xor_sync(~0u, i1, o);
            if (om > m1 || (om == m1 && oi < i1)) { m1 = om; i1 = oi; }
        }
        float l2 = (lane == i1) ? -CUDART_INF_F : logit;
        float m2 = l2; int i2 = lane;
        #pragma unroll
        for (int o = 16; o; o >>= 1) {
            float om = __shfl_xor_sync(~0u, m2, o);
            int   oi = __shfl_xor_sync(~0u, i2, o);
            if (om > m2 || (om == m2 && oi < i2)) { m2 = om; i2 = oi; }
        }
        if (lane == 0) {
            float e = expf(m2 - m1);
            g_idx[2*t]   = i1; g_idx[2*t+1] = i2;
            g_w[2*t]     = 1.f / (1.f + e);
            g_w[2*t+1]   = e / (1.f + e);
            atomicAdd(&g_counts[i1], 1);
            atomicAdd(&g_counts[i2], 1);
        }
        __syncwarp();
    }
}
__global__ void zero_counts_kernel() { if (threadIdx.x < NOPS) g_counts[threadIdx.x] = 0; }
__global__ void scan_kernel() {
    int lane = threadIdx.x;
    int c = g_counts[lane];
    int x = c;
    #pragma unroll
    for (int o = 1; o < 32; o <<= 1) {
        int n = __shfl_up_sync(~0u, x, o);
        if (lane >= o) x += n;
    }
    g_offsets[lane + 1] = x;
    if (lane == 0) g_offsets[0] = 0;
    g_cursor[lane] = x - c;
}
__global__ void scatter_kernel() {
    int i = blockIdx.x * blockDim.x + threadIdx.x;
    if (i < NASSIGN) {
        int opx = g_idx[i];
        int p = atomicAdd(&g_cursor[opx], 1);
        g_perm[p] = i >> 1;
        g_pos[i]  = p;
    }
}

// combine: cat[:, :128] = opbase + w0*c0 + w1*c1 (written as bf16 hi/lo)
__global__ void __launch_bounds__(128)
combine_kernel() {
    int d = threadIdx.x;
    for (int t = blockIdx.x; t < M_TOK; t += gridDim.x) {
        float v = g_opbase[(size_t)t * DR + d]
                + g_w[2*t]   * g_contrib[(size_t)g_pos[2*t]   * DR + d]
                + g_w[2*t+1] * g_contrib[(size_t)g_pos[2*t+1] * DR + d];
        bf16 h = __float2bfloat16(v);
        size_t o = (size_t)t * 256 + d;
        g_cat_h[o] = h;
        g_cat_l[o] = __float2bfloat16(v - __bfloat162float(h));
    }
}

// mem read: attn over slots from g_key -> cat[:, 128:256] (bf16 hi/lo)
__global__ void __launch_bounds__(128)
memread_kernel(const float* __restrict__ slots) {
    __shared__ float ssm[NSLOTS][DR + 1];
    __shared__ float rsm[4][DR];
    __shared__ float attn_s[4][NSLOTS];
    int tid = threadIdx.x;
    for (int i = tid; i < NSLOTS * DR; i += 128) ssm[i >> 7][i & 127] = slots[i];
    __syncthreads();
    int warp = tid >> 5, lane = tid & 31;
    const float inv_sqrt_d = 0.08838834764831845f;
    for (int t = blockIdx.x * 4 + warp; t < M_TOK; t += gridDim.x * 4) {
        float4 v = ((const float4*)(g_key + (size_t)t * DR))[lane];
        ((float4*)rsm[warp])[lane] = v;
        __syncwarp();
        float logit = -CUDART_INF_F;
        if (lane < NSLOTS) {
            float s = 0.f;
            #pragma unroll 8
            for (int k = 0; k < DR; k++) s += rsm[warp][k] * ssm[lane][k];
            logit = s * inv_sqrt_d;
        }
        float mx = logit;
        #pragma unroll
        for (int o = 16; o; o >>= 1) mx = fmaxf(mx, __shfl_xor_sync(~0u, mx, o));
        float e = (lane < NSLOTS) ? expf(logit - mx) : 0.f;
        float se = e;
        #pragma unroll
        for (int o = 16; o; o >>= 1) se += __shfl_xor_sync(~0u, se, o);
        if (lane < NSLOTS) attn_s[warp][lane] = e / se;
        __syncwarp();
        float ov[4] = {0.f, 0.f, 0.f, 0.f};
        #pragma unroll
        for (int s2 = 0; s2 < NSLOTS; s2++) {
            float a = attn_s[warp][s2];
            ov[0] += a * ssm[s2][lane*4+0];
            ov[1] += a * ssm[s2][lane*4+1];
            ov[2] += a * ssm[s2][lane*4+2];
            ov[3] += a * ssm[s2][lane*4+3];
        }
        size_t o = (size_t)t * 256 + 128 + lane * 4;
        #pragma unroll
        for (int e2 = 0; e2 < 4; e2++) {
            bf16 h = __float2bfloat16(ov[e2]);
            g_cat_h[o + e2] = h;
            g_cat_l[o + e2] = __float2bfloat16(ov[e2] - __bfloat162float(h));
        }
        __syncwarp();
    }
}

// layernorm of g_tmp -> g_reason (+ bf16 hi/lo split)
__global__ void __launch_bounds__(128)
ln_kernel(const float* __restrict__ gamma, const float* __restrict__ beta) {
    int warp = threadIdx.x >> 5, lane = threadIdx.x & 31;
    for (int t = blockIdx.x * 4 + warp; t < M_TOK; t += gridDim.x * 4) {
        float4 v = ((const float4*)(g_tmp + (size_t)t * DR))[lane];
        float s = v.x + v.y + v.z + v.w;
        float q = v.x*v.x + v.y*v.y + v.z*v.z + v.w*v.w;
        #pragma unroll
        for (int o = 16; o; o >>= 1) {
            s += __shfl_xor_sync(~0u, s, o);
            q += __shfl_xor_sync(~0u, q, o);
        }
        float mean = s * (1.f / 128.f);
        float var = q * (1.f / 128.f) - mean * mean;
        float rs = rsqrtf(var + 1e-5f);
        float4 g = ((const float4*)gamma)[lane];
        float4 b = ((const float4*)beta)[lane];
        float o4[4];
        o4[0] = (v.x - mean) * rs * g.x + b.x;
        o4[1] = (v.y - mean) * rs * g.y + b.y;
        o4[2] = (v.z - mean) * rs * g.z + b.z;
        o4[3] = (v.w - mean) * rs * g.w + b.w;
        size_t o = (size_t)t * DR + lane * 4;
        *(float4*)(g_reason + o) = make_float4(o4[0], o4[1], o4[2], o4[3]);
        #pragma unroll
        for (int e2 = 0; e2 < 4; e2++) {
            bf16 h = __float2bfloat16(o4[e2]);
            g_reason_h[o + e2] = h;
            g_reason_l[o + e2] = __float2bfloat16(o4[e2] - __bfloat162float(h));
        }
    }
}

// write signal: reason += ws*(wg*wv + 0.1*addr@slots)  (+ split)
__global__ void __launch_bounds__(128)
write_kernel(const float* __restrict__ slots, const float* __restrict__ Wg,
             const float* __restrict__ wsp) {
    __shared__ float ssm[NSLOTS][DR + 1];
    __shared__ float wgs[DR];
    __shared__ float rsm[4][DR];
    __shared__ float attn_s[4][NSLOTS];
    int tid = threadIdx.x;
    for (int i = tid; i < NSLOTS * DR; i += 128) ssm[i >> 7][i & 127] = slots[i];
    wgs[tid] = Wg[tid];
    __syncthreads();
    int warp = tid >> 5, lane = tid & 31;
    float ws = *wsp;
    const float inv_sqrt_d = 0.08838834764831845f;
    for (int t = blockIdx.x * 4 + warp; t < M_TOK; t += gridDim.x * 4) {
        float4 r = ((const float4*)(g_reason + (size_t)t * DR))[lane];
        float4 wg4 = ((const float4*)wgs)[lane];
        float gd = r.x*wg4.x + r.y*wg4.y + r.z*wg4.z + r.w*wg4.w;
        #pragma unroll
        for (int o = 16; o; o >>= 1) gd += __shfl_xor_sync(~0u, gd, o);
        float wg = 1.f / (1.f + expf(-gd));
        float4 k4 = ((const float4*)(g_key + (size_t)t * DR))[lane];
        ((float4*)rsm[warp])[lane] = k4;
        __syncwarp();
        float logit = -CUDART_INF_F;
        if (lane < NSLOTS) {
            float sdot = 0.f;
            #pragma unroll 8
            for (int k = 0; k < DR; k++) sdot += rsm[warp][k] * ssm[lane][k];
            logit = sdot * inv_sqrt_d;
        }
        float mx = logit;
        #pragma unroll
        for (int o = 16; o; o >>= 1) mx = fmaxf(mx, __shfl_xor_sync(~0u, mx, o));
        float e = (lane < NSLOTS) ? expf(logit - mx) : 0.f;
        float se = e;
        #pragma unroll
        for (int o = 16; o; o >>= 1) se += __shfl_xor_sync(~0u, se, o);
        if (lane < NSLOTS) attn_s[warp][lane] = e / se;
        __syncwarp();
        float4 wv = ((const float4*)(g_tmp + (size_t)t * DR))[lane];
        float ov[4];
        ov[0] = wg * wv.x; ov[1] = wg * wv.y; ov[2] = wg * wv.z; ov[3] = wg * wv.w;
        #pragma unroll
        for (int s2 = 0; s2 < NSLOTS; s2++) {
            float a = 0.1f * attn_s[warp][s2];
            ov[0] += a * ssm[s2][lane*4+0];
            ov[1] += a * ssm[s2][lane*4+1];
            ov[2] += a * ssm[s2][lane*4+2];
            ov[3] += a * ssm[s2][lane*4+3];
        }
        float o4[4];
        o4[0] = r.x + ws * ov[0]; o4[1] = r.y + ws * ov[1];
        o4[2] = r.z + ws * ov[2]; o4[3] = r.w + ws * ov[3];
        size_t o = (size_t)t * DR + lane * 4;
        *(float4*)(g_reason + o) = make_float4(o4[0], o4[1], o4[2], o4[3]);
        #pragma unroll
        for (int e2 = 0; e2 < 4; e2++) {
            bf16 h = __float2bfloat16(o4[e2]);
            g_reason_h[o + e2] = h;
            g_reason_l[o + e2] = __float2bfloat16(o4[e2] - __bfloat162float(h));
        }
        __syncwarp();
    }
}

// ======================= launch ============================================
extern "C" void kernel_launch(void* const* d_in, const int* in_sizes, int n_in,
                              void* d_out, int out_size) {
    const float* hidden   = (const float*)d_in[0];
    const float* W_down   = (const float*)d_in[2];
    const float* W_up     = (const float*)d_in[3];
    const float* ops      = (const float*)d_in[4];
    const float* W_router = (const float*)d_in[5];
    const float* slots    = (const float*)d_in[6];
    const float* W_read   = (const float*)d_in[7];
    const float* W_wk     = (const float*)d_in[8];
    const float* W_wg     = (const float*)d_in[9];
    const float* W_wv     = (const float*)d_in[10];
    const float* W_mix    = (const float*)d_in[11];
    const float* gamma    = (const float*)d_in[12];
    const float* beta     = (const float*)d_in[13];
    const float* wscale   = (const float*)d_in[14];
    float* out = (float*)d_out;

    float *pReason, *pTmp, *pKey, *pOpbase, *pScales;
    bf16 *pHidH, *pHidL, *pReasH, *pReasL, *pCatH, *pCatL;
    bf16 *pQdown, *pQup, *pQops, *pWsumH;
    bf16 *pWreadH, *pWreadL, *pWwkH, *pWwkL, *pWwvH, *pWwvL, *pWmixH, *pWmixL;
    cudaGetSymbolAddress((void**)&pReason, g_reason);
    cudaGetSymbolAddress((void**)&pTmp,    g_tmp);
    cudaGetSymbolAddress((void**)&pKey,    g_key);
    cudaGetSymbolAddress((void**)&pOpbase, g_opbase);
    cudaGetSymbolAddress((void**)&pScales, g_scales);
    cudaGetSymbolAddress((void**)&pHidH,   g_hid_h);
    cudaGetSymbolAddress((void**)&pHidL,   g_hid_l);
    cudaGetSymbolAddress((void**)&pReasH,  g_reason_h);
    cudaGetSymbolAddress((void**)&pReasL,  g_reason_l);
    cudaGetSymbolAddress((void**)&pCatH,   g_cat_h);
    cudaGetSymbolAddress((void**)&pCatL,   g_cat_l);
    cudaGetSymbolAddress((void**)&pQdown,  g_qdown);
    cudaGetSymbolAddress((void**)&pQup,    g_qup);
    cudaGetSymbolAddress((void**)&pQops,   g_qops);
    cudaGetSymbolAddress((void**)&pWsumH,  g_wsum_h);
    cudaGetSymbolAddress((void**)&pWreadH, g_wread_h);
    cudaGetSymbolAddress((void**)&pWreadL, g_wread_l);
    cudaGetSymbolAddress((void**)&pWwkH,   g_wwk_h);
    cudaGetSymbolAddress((void**)&pWwkL,   g_wwk_l);
    cudaGetSymbolAddress((void**)&pWwvH,   g_wwv_h);
    cudaGetSymbolAddress((void**)&pWwvL,   g_wwv_l);
    cudaGetSymbolAddress((void**)&pWmixH,  g_wmix_h);
    cudaGetSymbolAddress((void**)&pWmixL,  g_wmix_l);

    // --- scales (deterministic two-stage) ---
    absmean_p1<<<dim3(16, 1), 256>>>(W_down,   DR * DM,   0);
    absmean_p1<<<dim3(16, 1), 256>>>(W_up,     DM * DR,   1);
    absmean_p1<<<dim3(16, 1), 256>>>(W_router, NOPS * DR, 2);
    absmean_p1<<<dim3(16, NOPS), 256>>>(ops,   OPSZ,      3);
    absmean_p2<<<1, 64>>>();

    // --- quantize / split weights ---
    quantb_kernel<<<(DR*DM + 255)/256, 256>>>(W_down, pQdown, DR*DM, 0, DR*DM);
    quantb_kernel<<<(DM*DR + 255)/256, 256>>>(W_up,   pQup,   DM*DR, 1, DM*DR);
    quantb_kernel<<<(NOPS*OPSZ + 255)/256, 256>>>(ops, pQops, OPSZ, 3, NOPS*OPSZ);
    quantr_kernel<<<(NOPS*DR + 255)/256, 256>>>(W_router);
    wsumh_kernel<<<(OPSZ + 255)/256, 256>>>();
    split_kernel<<<(M_TOK*DM + 255)/256, 256>>>(hidden, pHidH, pHidL, M_TOK*DM);
    split_kernel<<<(OPSZ + 255)/256, 256>>>(W_read, pWreadH, pWreadL, OPSZ);
    split_kernel<<<(OPSZ + 255)/256, 256>>>(W_wk,   pWwkH,   pWwkL,   OPSZ);
    split_kernel<<<(OPSZ + 255)/256, 256>>>(W_wv,   pWwvH,   pWwvL,   OPSZ);
    split_kernel<<<(DR*2*DR + 255)/256, 256>>>(W_mix, pWmixH, pWmixL, DR*2*DR);

    // --- down: reason = s_down * hidden_split @ q_down^T (+ split) ---
    mma_gemm<<<dim3(M_TOK/128, 1), 256>>>(pHidH, pHidL, DM, pQdown, nullptr, DM,
        pReason, DR, DM, 2, 1.f, pScales + 0, nullptr, 0, pReasH, pReasL);

    // --- reasoning passes ---
    for (int pass = 0; pass < DEPTH; pass++) {
        zero_counts_kernel<<<1, 32>>>();
        router_kernel<<<148, 128>>>();
        scan_kernel<<<1, 32>>>();
        scatter_kernel<<<NASSIGN/256, 256>>>();
        expert_mma<<<dim3(8, NOPS), 256>>>();
        // opbase = (1e-5/32) * reason_hi @ wsum_hi^T (tiny term: 1-term suffices)
        mma_gemm<<<dim3(M_TOK/128, 1), 256>>>(pReasH, nullptr, DR, pWsumH, nullptr, DR,
            pOpbase, DR, DR, 1, 1e-5f / NOPS, nullptr, nullptr, 0, nullptr, nullptr);
        combine_kernel<<<4096, 128>>>();
        // key = reason @ W_read^T (3-term)
        mma_gemm<<<dim3(M_TOK/128, 1), 256>>>(pReasH, pReasL, DR, pWreadH, pWreadL, DR,
            pKey, DR, DR, 3, 1.f, nullptr, nullptr, 0, nullptr, nullptr);
        memread_kernel<<<148, 128>>>(slots);
        // tmp = reason + cat @ W_mix^T (3-term)
        mma_gemm<<<dim3(M_TOK/128, 1), 256>>>(pCatH, pCatL, 2*DR, pWmixH, pWmixL, 2*DR,
            pTmp, DR, 2*DR, 3, 1.f, nullptr, pReason, DR, nullptr, nullptr);
        ln_kernel<<<148, 128>>>(gamma, beta);
    }

    // --- write signal ---
    mma_gemm<<<dim3(M_TOK/128, 1), 256>>>(pReasH, pReasL, DR, pWwkH, pWwkL, DR,
        pKey, DR, DR, 3, 1.f, nullptr, nullptr, 0, nullptr, nullptr);
    mma_gemm<<<dim3(M_TOK/128, 1), 256>>>(pReasH, pReasL, DR, pWwvH, pWwvL, DR,
        pTmp, DR, DR, 3, 1.f, nullptr, nullptr, 0, nullptr, nullptr);
    write_kernel<<<148, 128>>>(slots, W_wg, wscale);

    // --- up: out = hidden + s_up * reason_split @ q_up^T ---
    mma_gemm<<<dim3(M_TOK/128, DM/128), 256>>>(pReasH, pReasL, DR, pQup, nullptr, DR,
        out, DM, DR, 2, 1.f, pScales + 1, hidden, DM, nullptr, nullptr);
}

// round 6
// speedup vs baseline: 2.7468x; 1.4360x over previous
#include <cuda_runtime.h>
#include <cuda_bf16.h>
#include <math.h>
#include <math_constants.h>
#include <stdint.h>

// Problem dims (fixed by setup_inputs)
#define M_TOK 16384      // B*S = 8*2048
#define DM    1024       // d_model
#define DR    128        // d_reason
#define NOPS  32
#define NSLOTS 16
#define OPSZ  (DR*DR)            // 16384
#define NASSIGN (M_TOK*2)        // 32768 (top_k=2)
#define DEPTH 2

typedef __nv_bfloat16 bf16;

#define AS_STRIDE 72            // bf16 elems per smem row (64 data + 8 pad; 144B row = 9*16B)
#define TILE_BYTES (128 * AS_STRIDE * 2)   // 18432 B per matrix per stage
#define STAGE_BYTES (2 * TILE_BYTES)       // A + B per stage
#define SMEM_PIPE (2 * STAGE_BYTES)        // 73728 B total

// ======================= PTX helpers =======================================
__device__ __forceinline__ uint32_t smem_u32(const void* p) {
    uint32_t a;
    asm("{ .reg .u64 t; cvta.to.shared.u64 t, %1; cvt.u32.u64 %0, t; }" : "=r"(a) : "l"(p));
    return a;
}
__device__ __forceinline__ void ldsm_x4(uint32_t& r0, uint32_t& r1, uint32_t& r2,
                                        uint32_t& r3, uint32_t addr) {
    asm volatile("ldmatrix.sync.aligned.m8n8.x4.shared.b16 {%0,%1,%2,%3}, [%4];"
                 : "=r"(r0), "=r"(r1), "=r"(r2), "=r"(r3) : "r"(addr));
}
__device__ __forceinline__ void ldsm_x2(uint32_t& r0, uint32_t& r1, uint32_t addr) {
    asm volatile("ldmatrix.sync.aligned.m8n8.x2.shared.b16 {%0,%1}, [%2];"
                 : "=r"(r0), "=r"(r1) : "r"(addr));
}
__device__ __forceinline__ void mma_bf16(float* d, const uint32_t* a, const uint32_t* b) {
    asm volatile(
        "mma.sync.aligned.m16n8k16.row.col.f32.bf16.bf16.f32 "
        "{%0,%1,%2,%3}, {%4,%5,%6,%7}, {%8,%9}, {%0,%1,%2,%3};"
        : "+f"(d[0]), "+f"(d[1]), "+f"(d[2]), "+f"(d[3])
        : "r"(a[0]), "r"(a[1]), "r"(a[2]), "r"(a[3]), "r"(b[0]), "r"(b[1]));
}
__device__ __forceinline__ void cp16(uint32_t smem, const void* gmem) {
    asm volatile("cp.async.cg.shared.global [%0], [%1], 16;" :: "r"(smem), "l"(gmem));
}
#define CP_COMMIT() asm volatile("cp.async.commit_group;" ::: "memory")
#define CP_WAIT1()  asm volatile("cp.async.wait_group 1;" ::: "memory")
#define CP_WAIT0()  asm volatile("cp.async.wait_group 0;" ::: "memory")

// ======================= scratch (__device__ globals) ======================
__device__ float g_reason [M_TOK*DR];
__device__ float g_tmp    [M_TOK*DR];
__device__ float g_key    [M_TOK*DR];
__device__ float g_opbase [M_TOK*DR];
__device__ float g_contrib[NASSIGN*DR];
__device__ bf16  g_hid_h  [M_TOK*DM];
__device__ bf16  g_hid_l  [M_TOK*DM];
__device__ bf16  g_reason_h[M_TOK*DR];
__device__ bf16  g_reason_l[M_TOK*DR];
__device__ bf16  g_cat_h  [M_TOK*2*DR];
__device__ bf16  g_cat_l  [M_TOK*2*DR];
__device__ bf16  g_qdown  [DR*DM];
__device__ bf16  g_qup    [DM*DR];
__device__ bf16  g_qops   [NOPS*OPSZ];
__device__ bf16  g_wsum_h [OPSZ];
__device__ bf16  g_wread_h[OPSZ];
__device__ bf16  g_wwk_h  [OPSZ];
__device__ bf16  g_wwv_h  [OPSZ];
__device__ bf16  g_wmix_h [DR*2*DR];
__device__ float g_WrouterE[NOPS*DR];
__device__ float g_scales [40];
__device__ float g_part   [40*16];
__device__ int   g_idx    [NASSIGN];
__device__ float g_w      [NASSIGN];
__device__ int   g_counts [NOPS];
__device__ int   g_offsets[NOPS+1];
__device__ int   g_cursor [NOPS];
__device__ int   g_perm   [NASSIGN];
__device__ int   g_pos    [NASSIGN];

// ======================= scale computation (deterministic) =================
__global__ void absmean_p1(const float* __restrict__ w, int n, int slotBase) {
    int mat = blockIdx.y, seg = blockIdx.x;      // 16 segs
    int segn = n >> 4;
    const float* p = w + (size_t)mat * n + (size_t)seg * segn;
    float s = 0.f;
    for (int i = threadIdx.x; i < segn; i += blockDim.x) s += fabsf(p[i]);
    __shared__ float red[8];
    int lane = threadIdx.x & 31, wid = threadIdx.x >> 5;
    #pragma unroll
    for (int o = 16; o; o >>= 1) s += __shfl_xor_sync(~0u, s, o);
    if (lane == 0) red[wid] = s;
    __syncthreads();
    if (threadIdx.x == 0) {
        float t = 0.f;
        for (int k = 0; k < (int)(blockDim.x >> 5); k++) t += red[k];
        g_part[(slotBase + mat) * 16 + seg] = t;
    }
}
__global__ void absmean_p2() {
    int slot = threadIdx.x;
    if (slot < 35) {
        float s = 0.f;
        #pragma unroll
        for (int k = 0; k < 16; k++) s += g_part[slot * 16 + k];
        int n = (slot < 2) ? (DR * DM) : (slot == 2 ? (NOPS * DR) : OPSZ);
        g_scales[slot] = fmaxf(s / (float)n, 1e-5f);
    }
}
__global__ void quantb_kernel(const float* __restrict__ w, bf16* __restrict__ q,
                              int per, int slotBase, int n) {
    int i = blockIdx.x * blockDim.x + threadIdx.x;
    if (i < n) {
        float s = g_scales[slotBase + i / per];
        float qq = fminf(1.f, fmaxf(-1.f, rintf(w[i] / s)));
        q[i] = __float2bfloat16(qq);
    }
}
__global__ void quantr_kernel(const float* __restrict__ w) {
    int i = blockIdx.x * blockDim.x + threadIdx.x;
    if (i < NOPS * DR) {
        float s = g_scales[2];
        float qq = fminf(1.f, fmaxf(-1.f, rintf(w[i] / s)));
        g_WrouterE[i] = qq * s;
    }
}
__global__ void wsumh_kernel() {
    int i = blockIdx.x * blockDim.x + threadIdx.x;
    if (i < OPSZ) {
        float s = 0.f;
        #pragma unroll
        for (int n = 0; n < NOPS; n++)
            s += __bfloat162float(g_qops[n * OPSZ + i]) * g_scales[3 + n];
        g_wsum_h[i] = __float2bfloat16(s);
    }
}
__global__ void split_kernel(const float* __restrict__ x, bf16* __restrict__ h,
                             bf16* __restrict__ l, int n) {
    int i = blockIdx.x * blockDim.x + threadIdx.x;
    if (i < n) {
        float v = x[i];
        bf16 hh = __float2bfloat16(v);
        h[i] = hh;
        l[i] = __float2bfloat16(v - __bfloat162float(hh));
    }
}
__global__ void tobf16_kernel(const float* __restrict__ x, bf16* __restrict__ h, int n) {
    int i = blockIdx.x * blockDim.x + threadIdx.x;
    if (i < n) h[i] = __float2bfloat16(x[i]);
}

// ======================= pipelined bf16 HMMA GEMM ==========================
// C[128,128-tile] = alpha * sum_terms( A_t @ B_t^T ) (+res).
// terms: 1={Ah,Bh}; 2=+{Al,Bh}; 3=+{Ah,Bl}. 256 thr, warps 4(M)x2(N).
// 2-stage cp.async pipeline over (term, k-chunk) sequence.
__global__ void __launch_bounds__(256)
mma_gemm(const bf16* __restrict__ Ah, const bf16* __restrict__ Al, int lda,
         const bf16* __restrict__ Bh, const bf16* __restrict__ Bl, int ldb,
         float* __restrict__ C, int ldc, int K, int terms,
         float alphaC, const float* __restrict__ alphaPtr,
         const float* __restrict__ res, int ldr,
         bf16* __restrict__ Ch, bf16* __restrict__ Cl)
{
    extern __shared__ __align__(16) bf16 smp[];
    const uint32_t sBase = smem_u32(smp);
    const int tid = threadIdx.x, lane = tid & 31, wid = tid >> 5;
    const int wm = wid & 3, wn = wid >> 2;
    const int bm = blockIdx.x * 128, bn = blockIdx.y * 128;
    const int nk = K >> 6;
    const int total = terms * nk;

    float acc[2][8][4];
    #pragma unroll
    for (int i = 0; i < 2; i++)
        #pragma unroll
        for (int j = 0; j < 8; j++)
            #pragma unroll
            for (int k = 0; k < 4; k++) acc[i][j][k] = 0.f;

    // per-thread staging slots (4 x 16B per matrix)
    int srow[4], skq[4];
    #pragma unroll
    for (int i = 0; i < 4; i++) {
        int slot = i * 256 + tid;
        srow[i] = slot >> 3;
        skq[i]  = (slot & 7) * 8;
    }

    auto load = [&](int c, int s) {
        int t = c / nk, k0 = (c - t * nk) << 6;
        const bf16 *Ab, *Bb;
        if (t == 0)      { Ab = Ah; Bb = Bh; }
        else if (t == 1) { Ab = Al; Bb = Bh; }
        else             { Ab = Ah; Bb = Bl; }
        const bf16* A = Ab + (size_t)bm * lda + k0;
        const bf16* B = Bb + (size_t)bn * ldb + k0;
        uint32_t dA = sBase + s * STAGE_BYTES;
        uint32_t dB = dA + TILE_BYTES;
        #pragma unroll
        for (int i = 0; i < 4; i++) {
            uint32_t off = (uint32_t)(srow[i] * AS_STRIDE + skq[i]) * 2;
            cp16(dA + off, A + (size_t)srow[i] * lda + skq[i]);
            cp16(dB + off, B + (size_t)srow[i] * ldb + skq[i]);
        }
        CP_COMMIT();
    };

    const uint32_t aOff = (uint32_t)(((wm * 32 + (lane & 15)) * AS_STRIDE + (lane >> 4) * 8) * 2);
    const uint32_t bOff = (uint32_t)(((wn * 64 + (lane & 7)) * AS_STRIDE + ((lane >> 3) & 1) * 8) * 2);

    load(0, 0);
    for (int c = 0; c < total; c++) {
        int s = c & 1;
        if (c + 1 < total) { load(c + 1, (c + 1) & 1); CP_WAIT1(); }
        else CP_WAIT0();
        __syncthreads();
        uint32_t aAddr = sBase + s * STAGE_BYTES + aOff;
        uint32_t bAddr = sBase + s * STAGE_BYTES + TILE_BYTES + bOff;
        #pragma unroll
        for (int kk = 0; kk < 4; kk++) {
            uint32_t a[2][4], b[8][2];
            #pragma unroll
            for (int mf = 0; mf < 2; mf++)
                ldsm_x4(a[mf][0], a[mf][1], a[mf][2], a[mf][3],
                        aAddr + (uint32_t)((mf * 16 * AS_STRIDE + kk * 16) * 2));
            #pragma unroll
            for (int nf = 0; nf < 8; nf++)
                ldsm_x2(b[nf][0], b[nf][1],
                        bAddr + (uint32_t)((nf * 8 * AS_STRIDE + kk * 16) * 2));
            #pragma unroll
            for (int mf = 0; mf < 2; mf++)
                #pragma unroll
                for (int nf = 0; nf < 8; nf++)
                    mma_bf16(acc[mf][nf], a[mf], b[nf]);
        }
        __syncthreads();
    }

    float alpha = alphaC * (alphaPtr ? *alphaPtr : 1.0f);
    const int row0 = bm + wm * 32, col0 = bn + wn * 64;
    #pragma unroll
    for (int mf = 0; mf < 2; mf++) {
        #pragma unroll
        for (int half = 0; half < 2; half++) {
            int r = row0 + mf * 16 + (lane >> 2) + half * 8;
            #pragma unroll
            for (int nf = 0; nf < 8; nf++) {
                int c = col0 + nf * 8 + (lane & 3) * 2;
                float vx = alpha * acc[mf][nf][half * 2];
                float vy = alpha * acc[mf][nf][half * 2 + 1];
                if (res) {
                    const float* rp = res + (size_t)r * ldr + c;
                    vx += rp[0]; vy += rp[1];
                }
                float* cp = C + (size_t)r * ldc + c;
                cp[0] = vx; cp[1] = vy;
                if (Ch) {
                    size_t o = (size_t)r * ldc + c;
                    bf16 h0 = __float2bfloat16(vx), h1 = __float2bfloat16(vy);
                    Ch[o] = h0; Ch[o + 1] = h1;
                    Cl[o]     = __float2bfloat16(vx - __bfloat162float(h0));
                    Cl[o + 1] = __float2bfloat16(vy - __bfloat162float(h1));
                }
            }
        }
    }
}

// Dual-B 1-term variant: blockIdx.y selects {B0->C0,alpha0} or {B1->C1,alpha1}.
__global__ void __launch_bounds__(256)
mma_gemm2(const bf16* __restrict__ A, int lda,
          const bf16* __restrict__ B0, const bf16* __restrict__ B1, int ldb,
          float* __restrict__ C0, float* __restrict__ C1, int ldc, int K,
          float alpha0, float alpha1)
{
    extern __shared__ __align__(16) bf16 smp[];
    const uint32_t sBase = smem_u32(smp);
    const int tid = threadIdx.x, lane = tid & 31, wid = tid >> 5;
    const int wm = wid & 3, wn = wid >> 2;
    const int bm = blockIdx.x * 128;
    const bf16* B = blockIdx.y ? B1 : B0;
    float* C = blockIdx.y ? C1 : C0;
    const float alpha = blockIdx.y ? alpha1 : alpha0;
    const int nk = K >> 6;

    float acc[2][8][4];
    #pragma unroll
    for (int i = 0; i < 2; i++)
        #pragma unroll
        for (int j = 0; j < 8; j++)
            #pragma unroll
            for (int k = 0; k < 4; k++) acc[i][j][k] = 0.f;

    int srow[4], skq[4];
    #pragma unroll
    for (int i = 0; i < 4; i++) {
        int slot = i * 256 + tid;
        srow[i] = slot >> 3;
        skq[i]  = (slot & 7) * 8;
    }
    auto load = [&](int c, int s) {
        int k0 = c << 6;
        const bf16* Ap = A + (size_t)bm * lda + k0;
        const bf16* Bp = B + k0;
        uint32_t dA = sBase + s * STAGE_BYTES;
        uint32_t dB = dA + TILE_BYTES;
        #pragma unroll
        for (int i = 0; i < 4; i++) {
            uint32_t off = (uint32_t)(srow[i] * AS_STRIDE + skq[i]) * 2;
            cp16(dA + off, Ap + (size_t)srow[i] * lda + skq[i]);
            cp16(dB + off, Bp + (size_t)srow[i] * ldb + skq[i]);
        }
        CP_COMMIT();
    };
    const uint32_t aOff = (uint32_t)(((wm * 32 + (lane & 15)) * AS_STRIDE + (lane >> 4) * 8) * 2);
    const uint32_t bOff = (uint32_t)(((wn * 64 + (lane & 7)) * AS_STRIDE + ((lane >> 3) & 1) * 8) * 2);

    load(0, 0);
    for (int c = 0; c < nk; c++) {
        int s = c & 1;
        if (c + 1 < nk) { load(c + 1, (c + 1) & 1); CP_WAIT1(); }
        else CP_WAIT0();
        __syncthreads();
        uint32_t aAddr = sBase + s * STAGE_BYTES + aOff;
        uint32_t bAddr = sBase + s * STAGE_BYTES + TILE_BYTES + bOff;
        #pragma unroll
        for (int kk = 0; kk < 4; kk++) {
            uint32_t a[2][4], b[8][2];
            #pragma unroll
            for (int mf = 0; mf < 2; mf++)
                ldsm_x4(a[mf][0], a[mf][1], a[mf][2], a[mf][3],
                        aAddr + (uint32_t)((mf * 16 * AS_STRIDE + kk * 16) * 2));
            #pragma unroll
            for (int nf = 0; nf < 8; nf++)
                ldsm_x2(b[nf][0], b[nf][1],
                        bAddr + (uint32_t)((nf * 8 * AS_STRIDE + kk * 16) * 2));
            #pragma unroll
            for (int mf = 0; mf < 2; mf++)
                #pragma unroll
                for (int nf = 0; nf < 8; nf++)
                    mma_bf16(acc[mf][nf], a[mf], b[nf]);
        }
        __syncthreads();
    }
    const int row0 = bm + wm * 32, col0 = wn * 64;
    #pragma unroll
    for (int mf = 0; mf < 2; mf++) {
        #pragma unroll
        for (int half = 0; half < 2; half++) {
            int r = row0 + mf * 16 + (lane >> 2) + half * 8;
            #pragma unroll
            for (int nf = 0; nf < 8; nf++) {
                int c = col0 + nf * 8 + (lane & 3) * 2;
                float* cp = C + (size_t)r * ldc + c;
                cp[0] = alpha * acc[mf][nf][half * 2];
                cp[1] = alpha * acc[mf][nf][half * 2 + 1];
            }
        }
    }
}

// ======================= expert (gathered) pipelined HMMA ==================
__global__ void __launch_bounds__(256)
expert_mma() {
    int op = blockIdx.y;
    int start = g_offsets[op];
    int cnt = g_offsets[op + 1] - start;
    extern __shared__ __align__(16) bf16 smp[];
    __shared__ int rowid[128];
    const uint32_t sBase = smem_u32(smp);
    const int tid = threadIdx.x, lane = tid & 31, wid = tid >> 5;
    const int wm = wid & 3, wn = wid >> 2;
    float alpha = g_scales[3 + op];
    const bf16* B0 = g_qops + (size_t)op * OPSZ;

    int srow[4], skq[4];
    #pragma unroll
    for (int i = 0; i < 4; i++) {
        int slot = i * 256 + tid;
        srow[i] = slot >> 3;
        skq[i]  = (slot & 7) * 8;
    }
    const uint32_t aOff = (uint32_t)(((wm * 32 + (lane & 15)) * AS_STRIDE + (lane >> 4) * 8) * 2);
    const uint32_t bOff = (uint32_t)(((wn * 64 + (lane & 7)) * AS_STRIDE + ((lane >> 3) & 1) * 8) * 2);

    // chunk c in [0,4): term = c>>1 (0=hi,1=lo), k0 = (c&1)*64
    auto load = [&](int c, int s) {
        const bf16* Areas = (c >> 1) ? g_reason_l : g_reason_h;
        int k0 = (c & 1) << 6;
        uint32_t dA = sBase + s * STAGE_BYTES;
        uint32_t dB = dA + TILE_BYTES;
        #pragma unroll
        for (int i = 0; i < 4; i++) {
            int grow = rowid[srow[i]];
            if (grow < 0) grow = 0;   // garbage rows only affect unwritten C rows
            uint32_t off = (uint32_t)(srow[i] * AS_STRIDE + skq[i]) * 2;
            cp16(dA + off, Areas + (size_t)grow * DR + k0 + skq[i]);
            cp16(dB + off, B0 + (size_t)srow[i] * DR + k0 + skq[i]);
        }
        CP_COMMIT();
    };

    for (int t0 = blockIdx.x * 128; t0 < cnt; t0 += gridDim.x * 128) {
        __syncthreads();
        if (tid < 128) rowid[tid] = (t0 + tid < cnt) ? g_perm[start + t0 + tid] : -1;
        __syncthreads();
        float acc[2][8][4];
        #pragma unroll
        for (int i = 0; i < 2; i++)
            #pragma unroll
            for (int j = 0; j < 8; j++)
                #pragma unroll
                for (int k = 0; k < 4; k++) acc[i][j][k] = 0.f;

        load(0, 0);
        #pragma unroll
        for (int c = 0; c < 4; c++) {
            int s = c & 1;
            if (c < 3) { load(c + 1, (c + 1) & 1); CP_WAIT1(); }
            else CP_WAIT0();
            __syncthreads();
            uint32_t aAddr = sBase + s * STAGE_BYTES + aOff;
            uint32_t bAddr = sBase + s * STAGE_BYTES + TILE_BYTES + bOff;
            #pragma unroll
            for (int kk = 0; kk < 4; kk++) {
                uint32_t a[2][4], b[8][2];
                #pragma unroll
                for (int mf = 0; mf < 2; mf++)
                    ldsm_x4(a[mf][0], a[mf][1], a[mf][2], a[mf][3],
                            aAddr + (uint32_t)((mf * 16 * AS_STRIDE + kk * 16) * 2));
                #pragma unroll
                for (int nf = 0; nf < 8; nf++)
                    ldsm_x2(b[nf][0], b[nf][1],
                            bAddr + (uint32_t)((nf * 8 * AS_STRIDE + kk * 16) * 2));
                #pragma unroll
                for (int mf = 0; mf < 2; mf++)
                    #pragma unroll
                    for (int nf = 0; nf < 8; nf++)
                        mma_bf16(acc[mf][nf], a[mf], b[nf]);
            }
            __syncthreads();
        }
        const int row0 = wm * 32, col0 = wn * 64;
        #pragma unroll
        for (int mf = 0; mf < 2; mf++) {
            #pragma unroll
            for (int half = 0; half < 2; half++) {
                int rl = row0 + mf * 16 + (lane >> 2) + half * 8;
                if (t0 + rl < cnt) {
                    float* cp0 = g_contrib + (size_t)(start + t0 + rl) * DR;
                    #pragma unroll
                    for (int nf = 0; nf < 8; nf++) {
                        int c = col0 + nf * 8 + (lane & 3) * 2;
                        cp0[c]     = alpha * acc[mf][nf][half * 2];
                        cp0[c + 1] = alpha * acc[mf][nf][half * 2 + 1];
                    }
                }
            }
        }
    }
}

// ======================= router / moe bookkeeping ==========================
__global__ void __launch_bounds__(128)
router_kernel() {
    __shared__ float Wsm[NOPS][DR + 1];
    __shared__ float rsm[4][DR];
    int tid = threadIdx.x;
    for (int i = tid; i < NOPS * DR; i += 128) Wsm[i >> 7][i & 127] = g_WrouterE[i];
    __syncthreads();
    int warp = tid >> 5, lane = tid & 31;
    for (int t = blockIdx.x * 4 + warp; t < M_TOK; t += gridDim.x * 4) {
        float4 v = ((const float4*)(g_reason + (size_t)t * DR))[lane];
        ((float4*)rsm[warp])[lane] = v;
        __syncwarp();
        float logit = 0.f;
        #pragma unroll 8
        for (int k = 0; k < DR; k++) logit += rsm[warp][k] * Wsm[lane][k];
        float m1 = logit; int i1 = lane;
        #pragma unroll
        for (int o = 16; o; o >>= 1) {
            float om = __shfl_xor_sync(~0u, m1, o);
            int   oi = __shfl_xor_sync(~0u, i1, o);
            if (om > m1 || (om == m1 && oi < i1)) { m1 = om; i1 = oi; }
        }
        float l2 = (lane == i1) ? -CUDART_INF_F : logit;
        float m2 = l2; int i2 = lane;
        #pragma unroll
        for (int o = 16; o; o >>= 1) {
            float om = __shfl_xor_sync(~0u, m2, o);
            int   oi = __shfl_xor_sync(~0u, i2, o);
            if (om > m2 || (om == m2 && oi < i2)) { m2 = om; i2 = oi; }
        }
        if (lane == 0) {
            float e = expf(m2 - m1);
            g_idx[2*t]   = i1; g_idx[2*t+1] = i2;
            g_w[2*t]     = 1.f / (1.f + e);
            g_w[2*t+1]   = e / (1.f + e);
            atomicAdd(&g_counts[i1], 1);
            atomicAdd(&g_counts[i2], 1);
        }
        __syncwarp();
    }
}
__global__ void zero_counts_kernel() { if (threadIdx.x < NOPS) g_counts[threadIdx.x] = 0; }
__global__ void scan_kernel() {
    int lane = threadIdx.x;
    int c = g_counts[lane];
    int x = c;
    #pragma unroll
    for (int o = 1; o < 32; o <<= 1) {
        int n = __shfl_up_sync(~0u, x, o);
        if (lane >= o) x += n;
    }
    g_offsets[lane + 1] = x;
    if (lane == 0) g_offsets[0] = 0;
    g_cursor[lane] = x - c;
}
__global__ void scatter_kernel() {
    int i = blockIdx.x * blockDim.x + threadIdx.x;
    if (i < NASSIGN) {
        int opx = g_idx[i];
        int p = atomicAdd(&g_cursor[opx], 1);
        g_perm[p] = i >> 1;
        g_pos[i]  = p;
    }
}
__global__ void __launch_bounds__(128)
combine_kernel() {
    int d = threadIdx.x;
    for (int t = blockIdx.x; t < M_TOK; t += gridDim.x) {
        float v = g_opbase[(size_t)t * DR + d]
                + g_w[2*t]   * g_contrib[(size_t)g_pos[2*t]   * DR + d]
                + g_w[2*t+1] * g_contrib[(size_t)g_pos[2*t+1] * DR + d];
        bf16 h = __float2bfloat16(v);
        size_t o = (size_t)t * 256 + d;
        g_cat_h[o] = h;
        g_cat_l[o] = __float2bfloat16(v - __bfloat162float(h));
    }
}
__global__ void __launch_bounds__(128)
memread_kernel(const float* __restrict__ slots) {
    __shared__ float ssm[NSLOTS][DR + 1];
    __shared__ float rsm[4][DR];
    __shared__ float attn_s[4][NSLOTS];
    int tid = threadIdx.x;
    for (int i = tid; i < NSLOTS * DR; i += 128) ssm[i >> 7][i & 127] = slots[i];
    __syncthreads();
    int warp = tid >> 5, lane = tid & 31;
    const float inv_sqrt_d = 0.08838834764831845f;
    for (int t = blockIdx.x * 4 + warp; t < M_TOK; t += gridDim.x * 4) {
        float4 v = ((const float4*)(g_key + (size_t)t * DR))[lane];
        ((float4*)rsm[warp])[lane] = v;
        __syncwarp();
        float logit = -CUDART_INF_F;
        if (lane < NSLOTS) {
            float s = 0.f;
            #pragma unroll 8
            for (int k = 0; k < DR; k++) s += rsm[warp][k] * ssm[lane][k];
            logit = s * inv_sqrt_d;
        }
        float mx = logit;
        #pragma unroll
        for (int o = 16; o; o >>= 1) mx = fmaxf(mx, __shfl_xor_sync(~0u, mx, o));
        float e = (lane < NSLOTS) ? expf(logit - mx) : 0.f;
        float se = e;
        #pragma unroll
        for (int o = 16; o; o >>= 1) se += __shfl_xor_sync(~0u, se, o);
        if (lane < NSLOTS) attn_s[warp][lane] = e / se;
        __syncwarp();
        float ov[4] = {0.f, 0.f, 0.f, 0.f};
        #pragma unroll
        for (int s2 = 0; s2 < NSLOTS; s2++) {
            float a = attn_s[warp][s2];
            ov[0] += a * ssm[s2][lane*4+0];
            ov[1] += a * ssm[s2][lane*4+1];
            ov[2] += a * ssm[s2][lane*4+2];
            ov[3] += a * ssm[s2][lane*4+3];
        }
        size_t o = (size_t)t * 256 + 128 + lane * 4;
        #pragma unroll
        for (int e2 = 0; e2 < 4; e2++) {
            bf16 h = __float2bfloat16(ov[e2]);
            g_cat_h[o + e2] = h;
            g_cat_l[o + e2] = __float2bfloat16(ov[e2] - __bfloat162float(h));
        }
        __syncwarp();
    }
}
__global__ void __launch_bounds__(128)
ln_kernel(const float* __restrict__ gamma, const float* __restrict__ beta) {
    int warp = threadIdx.x >> 5, lane = threadIdx.x & 31;
    for (int t = blockIdx.x * 4 + warp; t < M_TOK; t += gridDim.x * 4) {
        float4 v = ((const float4*)(g_tmp + (size_t)t * DR))[lane];
        float s = v.x + v.y + v.z + v.w;
        float q = v.x*v.x + v.y*v.y + v.z*v.z + v.w*v.w;
        #pragma unroll
        for (int o = 16; o; o >>= 1) {
            s += __shfl_xor_sync(~0u, s, o);
            q += __shfl_xor_sync(~0u, q, o);
        }
        float mean = s * (1.f / 128.f);
        float var = q * (1.f / 128.f) - mean * mean;
        float rs = rsqrtf(var + 1e-5f);
        float4 g = ((const float4*)gamma)[lane];
        float4 b = ((const float4*)beta)[lane];
        float o4[4];
        o4[0] = (v.x - mean) * rs * g.x + b.x;
        o4[1] = (v.y - mean) * rs * g.y + b.y;
        o4[2] = (v.z - mean) * rs * g.z + b.z;
        o4[3] = (v.w - mean) * rs * g.w + b.w;
        size_t o = (size_t)t * DR + lane * 4;
        *(float4*)(g_reason + o) = make_float4(o4[0], o4[1], o4[2], o4[3]);
        #pragma unroll
        for (int e2 = 0; e2 < 4; e2++) {
            bf16 h = __float2bfloat16(o4[e2]);
            g_reason_h[o + e2] = h;
            g_reason_l[o + e2] = __float2bfloat16(o4[e2] - __bfloat162float(h));
        }
    }
}
__global__ void __launch_bounds__(128)
write_kernel(const float* __restrict__ slots, const float* __restrict__ Wg,
             const float* __restrict__ wsp) {
    __shared__ float ssm[NSLOTS][DR + 1];
    __shared__ float wgs[DR];
    __shared__ float rsm[4][DR];
    __shared__ float attn_s[4][NSLOTS];
    int tid = threadIdx.x;
    for (int i = tid; i < NSLOTS * DR; i += 128) ssm[i >> 7][i & 127] = slots[i];
    wgs[tid] = Wg[tid];
    __syncthreads();
    int warp = tid >> 5, lane = tid & 31;
    float ws = *wsp;
    const float inv_sqrt_d = 0.08838834764831845f;
    for (int t = blockIdx.x * 4 + warp; t < M_TOK; t += gridDim.x * 4) {
        float4 r = ((const float4*)(g_reason + (size_t)t * DR))[lane];
        float4 wg4 = ((const float4*)wgs)[lane];
        float gd = r.x*wg4.x + r.y*wg4.y + r.z*wg4.z + r.w*wg4.w;
        #pragma unroll
        for (int o = 16; o; o >>= 1) gd += __shfl_xor_sync(~0u, gd, o);
        float wg = 1.f / (1.f + expf(-gd));
        float4 k4 = ((const float4*)(g_key + (size_t)t * DR))[lane];
        ((float4*)rsm[warp])[lane] = k4;
        __syncwarp();
        float logit = -CUDART_INF_F;
        if (lane < NSLOTS) {
            float sdot = 0.f;
            #pragma unroll 8
            for (int k = 0; k < DR; k++) sdot += rsm[warp][k] * ssm[lane][k];
            logit = sdot * inv_sqrt_d;
        }
        float mx = logit;
        #pragma unroll
        for (int o = 16; o; o >>= 1) mx = fmaxf(mx, __shfl_xor_sync(~0u, mx, o));
        float e = (lane < NSLOTS) ? expf(logit - mx) : 0.f;
        float se = e;
        #pragma unroll
        for (int o = 16; o; o >>= 1) se += __shfl_xor_sync(~0u, se, o);
        if (lane < NSLOTS) attn_s[warp][lane] = e / se;
        __syncwarp();
        float4 wv = ((const float4*)(g_tmp + (size_t)t * DR))[lane];
        float ov[4];
        ov[0] = wg * wv.x; ov[1] = wg * wv.y; ov[2] = wg * wv.z; ov[3] = wg * wv.w;
        #pragma unroll
        for (int s2 = 0; s2 < NSLOTS; s2++) {
            float a = 0.1f * attn_s[warp][s2];
            ov[0] += a * ssm[s2][lane*4+0];
            ov[1] += a * ssm[s2][lane*4+1];
            ov[2] += a * ssm[s2][lane*4+2];
            ov[3] += a * ssm[s2][lane*4+3];
        }
        float o4[4];
        o4[0] = r.x + ws * ov[0]; o4[1] = r.y + ws * ov[1];
        o4[2] = r.z + ws * ov[2]; o4[3] = r.w + ws * ov[3];
        size_t o = (size_t)t * DR + lane * 4;
        *(float4*)(g_reason + o) = make_float4(o4[0], o4[1], o4[2], o4[3]);
        #pragma unroll
        for (int e2 = 0; e2 < 4; e2++) {
            bf16 h = __float2bfloat16(o4[e2]);
            g_reason_h[o + e2] = h;
            g_reason_l[o + e2] = __float2bfloat16(o4[e2] - __bfloat162float(h));
        }
        __syncwarp();
    }
}

// ======================= launch ============================================
extern "C" void kernel_launch(void* const* d_in, const int* in_sizes, int n_in,
                              void* d_out, int out_size) {
    const float* hidden   = (const float*)d_in[0];
    const float* W_down   = (const float*)d_in[2];
    const float* W_up     = (const float*)d_in[3];
    const float* ops      = (const float*)d_in[4];
    const float* W_router = (const float*)d_in[5];
    const float* slots    = (const float*)d_in[6];
    const float* W_read   = (const float*)d_in[7];
    const float* W_wk     = (const float*)d_in[8];
    const float* W_wg     = (const float*)d_in[9];
    const float* W_wv     = (const float*)d_in[10];
    const float* W_mix    = (const float*)d_in[11];
    const float* gamma    = (const float*)d_in[12];
    const float* beta     = (const float*)d_in[13];
    const float* wscale   = (const float*)d_in[14];
    float* out = (float*)d_out;

    static bool attr_done = false;
    if (!attr_done) {
        cudaFuncSetAttribute(mma_gemm,  cudaFuncAttributeMaxDynamicSharedMemorySize, SMEM_PIPE);
        cudaFuncSetAttribute(mma_gemm2, cudaFuncAttributeMaxDynamicSharedMemorySize, SMEM_PIPE);
        cudaFuncSetAttribute(expert_mma, cudaFuncAttributeMaxDynamicSharedMemorySize, SMEM_PIPE);
        attr_done = true;
    }

    float *pReason, *pTmp, *pKey, *pOpbase, *pScales;
    bf16 *pHidH, *pHidL, *pReasH, *pReasL, *pCatH, *pCatL;
    bf16 *pQdown, *pQup, *pQops, *pWsumH, *pWreadH, *pWwkH, *pWwvH, *pWmixH;
    cudaGetSymbolAddress((void**)&pReason, g_reason);
    cudaGetSymbolAddress((void**)&pTmp,    g_tmp);
    cudaGetSymbolAddress((void**)&pKey,    g_key);
    cudaGetSymbolAddress((void**)&pOpbase, g_opbase);
    cudaGetSymbolAddress((void**)&pScales, g_scales);
    cudaGetSymbolAddress((void**)&pHidH,   g_hid_h);
    cudaGetSymbolAddress((void**)&pHidL,   g_hid_l);
    cudaGetSymbolAddress((void**)&pReasH,  g_reason_h);
    cudaGetSymbolAddress((void**)&pReasL,  g_reason_l);
    cudaGetSymbolAddress((void**)&pCatH,   g_cat_h);
    cudaGetSymbolAddress((void**)&pCatL,   g_cat_l);
    cudaGetSymbolAddress((void**)&pQdown,  g_qdown);
    cudaGetSymbolAddress((void**)&pQup,    g_qup);
    cudaGetSymbolAddress((void**)&pQops,   g_qops);
    cudaGetSymbolAddress((void**)&pWsumH,  g_wsum_h);
    cudaGetSymbolAddress((void**)&pWreadH, g_wread_h);
    cudaGetSymbolAddress((void**)&pWwkH,   g_wwk_h);
    cudaGetSymbolAddress((void**)&pWwvH,   g_wwv_h);
    cudaGetSymbolAddress((void**)&pWmixH,  g_wmix_h);

    // --- scales ---
    absmean_p1<<<dim3(16, 1), 256>>>(W_down,   DR * DM,   0);
    absmean_p1<<<dim3(16, 1), 256>>>(W_up,     DM * DR,   1);
    absmean_p1<<<dim3(16, 1), 256>>>(W_router, NOPS * DR, 2);
    absmean_p1<<<dim3(16, NOPS), 256>>>(ops,   OPSZ,      3);
    absmean_p2<<<1, 64>>>();

    // --- quantize / convert weights ---
    quantb_kernel<<<(DR*DM + 255)/256, 256>>>(W_down, pQdown, DR*DM, 0, DR*DM);
    quantb_kernel<<<(DM*DR + 255)/256, 256>>>(W_up,   pQup,   DM*DR, 1, DM*DR);
    quantb_kernel<<<(NOPS*OPSZ + 255)/256, 256>>>(ops, pQops, OPSZ, 3, NOPS*OPSZ);
    quantr_kernel<<<(NOPS*DR + 255)/256, 256>>>(W_router);
    wsumh_kernel<<<(OPSZ + 255)/256, 256>>>();
    split_kernel<<<(M_TOK*DM + 255)/256, 256>>>(hidden, pHidH, pHidL, M_TOK*DM);
    tobf16_kernel<<<(OPSZ + 255)/256, 256>>>(W_read, pWreadH, OPSZ);
    tobf16_kernel<<<(OPSZ + 255)/256, 256>>>(W_wk,   pWwkH,   OPSZ);
    tobf16_kernel<<<(OPSZ + 255)/256, 256>>>(W_wv,   pWwvH,   OPSZ);
    tobf16_kernel<<<(DR*2*DR + 255)/256, 256>>>(W_mix, pWmixH, DR*2*DR);

    // --- down: reason = s_down * hidden_split @ q_down^T (+ split) ---
    mma_gemm<<<dim3(M_TOK/128, 1), 256, SMEM_PIPE>>>(pHidH, pHidL, DM, pQdown, nullptr, DM,
        pReason, DR, DM, 2, 1.f, pScales + 0, nullptr, 0, pReasH, pReasL);

    // --- reasoning passes ---
    for (int pass = 0; pass < DEPTH; pass++) {
        zero_counts_kernel<<<1, 32>>>();
        router_kernel<<<148, 128>>>();
        scan_kernel<<<1, 32>>>();
        scatter_kernel<<<NASSIGN/256, 256>>>();
        expert_mma<<<dim3(8, NOPS), 256, SMEM_PIPE>>>();
        // opbase (y=0) + key (y=1), both 1-term off reasonH
        mma_gemm2<<<dim3(M_TOK/128, 2), 256, SMEM_PIPE>>>(pReasH, DR, pWsumH, pWreadH, DR,
            pOpbase, pKey, DR, DR, 1e-5f / NOPS, 1.f);
        combine_kernel<<<4096, 128>>>();
        memread_kernel<<<148, 128>>>(slots);
        // tmp = reason + cat @ W_mix^T (2-term: catH + catL vs wmixH)
        mma_gemm<<<dim3(M_TOK/128, 1), 256, SMEM_PIPE>>>(pCatH, pCatL, 2*DR, pWmixH, nullptr, 2*DR,
            pTmp, DR, 2*DR, 2, 1.f, nullptr, pReason, DR, nullptr, nullptr);
        ln_kernel<<<148, 128>>>(gamma, beta);
    }

    // --- write signal: wk (y=0 -> key) + wv (y=1 -> tmp), 1-term ---
    mma_gemm2<<<dim3(M_TOK/128, 2), 256, SMEM_PIPE>>>(pReasH, DR, pWwkH, pWwvH, DR,
        pKey, pTmp, DR, DR, 1.f, 1.f);
    write_kernel<<<148, 128>>>(slots, W_wg, wscale);

    // --- up: out = hidden + s_up * reason_split @ q_up^T ---
    mma_gemm<<<dim3(M_TOK/128, DM/128), 256, SMEM_PIPE>>>(pReasH, pReasL, DR, pQup, nullptr, DR,
        out, DM, DR, 2, 1.f, pScales + 1, hidden, DM, nullptr, nullptr);
}

// round 8
// speedup vs baseline: 2.9994x; 1.0920x over previous
#include <cuda_runtime.h>
#include <cuda_bf16.h>
#include <math.h>
#include <math_constants.h>
#include <stdint.h>

#define M_TOK 16384
#define DM    1024
#define DR    128
#define NOPS  32
#define NSLOTS 16
#define OPSZ  (DR*DR)
#define NASSIGN (M_TOK*2)
#define DEPTH 2

typedef __nv_bfloat16 bf16;

#define AS_STRIDE 72
#define TILE_BYTES (128 * AS_STRIDE * 2)
#define STAGE_BYTES (2 * TILE_BYTES)
#define SMEM_PIPE (2 * STAGE_BYTES)        // 73728 B

// ======================= PTX helpers =======================================
__device__ __forceinline__ uint32_t smem_u32(const void* p) {
    uint32_t a;
    asm("{ .reg .u64 t; cvta.to.shared.u64 t, %1; cvt.u32.u64 %0, t; }" : "=r"(a) : "l"(p));
    return a;
}
__device__ __forceinline__ void ldsm_x4(uint32_t& r0, uint32_t& r1, uint32_t& r2,
                                        uint32_t& r3, uint32_t addr) {
    asm volatile("ldmatrix.sync.aligned.m8n8.x4.shared.b16 {%0,%1,%2,%3}, [%4];"
                 : "=r"(r0), "=r"(r1), "=r"(r2), "=r"(r3) : "r"(addr));
}
__device__ __forceinline__ void mma_bf16(float* d, const uint32_t* a, const uint32_t* b) {
    asm volatile(
        "mma.sync.aligned.m16n8k16.row.col.f32.bf16.bf16.f32 "
        "{%0,%1,%2,%3}, {%4,%5,%6,%7}, {%8,%9}, {%0,%1,%2,%3};"
        : "+f"(d[0]), "+f"(d[1]), "+f"(d[2]), "+f"(d[3])
        : "r"(a[0]), "r"(a[1]), "r"(a[2]), "r"(a[3]), "r"(b[0]), "r"(b[1]));
}
__device__ __forceinline__ void cp16(uint32_t smem, const void* gmem) {
    asm volatile("cp.async.cg.shared.global [%0], [%1], 16;" :: "r"(smem), "l"(gmem));
}
#define CP_COMMIT() asm volatile("cp.async.commit_group;" ::: "memory")
#define CP_WAIT1()  asm volatile("cp.async.wait_group 1;" ::: "memory")
#define CP_WAIT0()  asm volatile("cp.async.wait_group 0;" ::: "memory")

// A fragments: row=wm*32+(lane&15), k-half=(lane>>4)*8
// B fragments (x4, two n8-groups): row=wn*64+nfp*16+((lane>>4)&1)*8+(lane&7), k-half=((lane>>3)&1)*8
#define A_OFF(wm, lane) ((uint32_t)((((wm) * 32 + ((lane) & 15)) * AS_STRIDE + ((lane) >> 4) * 8) * 2))
#define B_OFF(wn, lane) ((uint32_t)((((wn) * 64 + (((lane) >> 4) & 1) * 8 + ((lane) & 7)) * AS_STRIDE + (((lane) >> 3) & 1) * 8) * 2))

// One K=64 chunk of 128x128: 4 k-steps, acc[2][8][4]
__device__ __forceinline__ void compute_chunk(uint32_t aAddr, uint32_t bAddr,
                                              float acc[2][8][4]) {
    #pragma unroll
    for (int kk = 0; kk < 4; kk++) {
        uint32_t a[2][4], b[4][4];
        #pragma unroll
        for (int mf = 0; mf < 2; mf++)
            ldsm_x4(a[mf][0], a[mf][1], a[mf][2], a[mf][3],
                    aAddr + (uint32_t)((mf * 16 * AS_STRIDE + kk * 16) * 2));
        #pragma unroll
        for (int nfp = 0; nfp < 4; nfp++)
            ldsm_x4(b[nfp][0], b[nfp][1], b[nfp][2], b[nfp][3],
                    bAddr + (uint32_t)((nfp * 16 * AS_STRIDE + kk * 16) * 2));
        #pragma unroll
        for (int mf = 0; mf < 2; mf++)
            #pragma unroll
            for (int nf = 0; nf < 8; nf++)
                mma_bf16(acc[mf][nf], a[mf], &b[nf >> 1][(nf & 1) * 2]);
    }
}

// ======================= scratch ===========================================
__device__ float g_reason [M_TOK*DR];
__device__ float g_tmp    [M_TOK*DR];      // wv at end
__device__ float g_key    [M_TOK*DR];
__device__ float g_contrib[NASSIGN*DR];
__device__ bf16  g_hid_h  [M_TOK*DM];
__device__ bf16  g_hid_l  [M_TOK*DM];
__device__ bf16  g_reason_h[M_TOK*DR];
__device__ bf16  g_cat_h  [M_TOK*2*DR];
__device__ bf16  g_qdown  [DR*DM];
__device__ bf16  g_qup    [DM*DR];
__device__ bf16  g_qops   [NOPS*OPSZ];
__device__ bf16  g_wread_h[OPSZ];
__device__ bf16  g_wwk_h  [OPSZ];
__device__ bf16  g_wwv_h  [OPSZ];
__device__ bf16  g_wmix_h [DR*2*DR];
__device__ float g_WrouterE[NOPS*DR];
__device__ float g_scales [40];
__device__ float g_part   [40*16];
__device__ int   g_idx    [NASSIGN];
__device__ float g_w      [NASSIGN];
__device__ int   g_counts [NOPS];
__device__ int   g_offsets[NOPS+1];
__device__ int   g_cursor [NOPS];
__device__ int   g_perm   [NASSIGN];
__device__ int   g_pos    [NASSIGN];

// ======================= scales / quantization =============================
__global__ void absmean_p1(const float* __restrict__ w, int n, int slotBase) {
    int mat = blockIdx.y, seg = blockIdx.x;
    int segn = n >> 4;
    const float* p = w + (size_t)mat * n + (size_t)seg * segn;
    float s = 0.f;
    for (int i = threadIdx.x; i < segn; i += blockDim.x) s += fabsf(p[i]);
    __shared__ float red[8];
    int lane = threadIdx.x & 31, wid = threadIdx.x >> 5;
    #pragma unroll
    for (int o = 16; o; o >>= 1) s += __shfl_xor_sync(~0u, s, o);
    if (lane == 0) red[wid] = s;
    __syncthreads();
    if (threadIdx.x == 0) {
        float t = 0.f;
        for (int k = 0; k < (int)(blockDim.x >> 5); k++) t += red[k];
        g_part[(slotBase + mat) * 16 + seg] = t;
    }
}
__global__ void absmean_p2() {
    int slot = threadIdx.x;
    if (slot < 35) {
        float s = 0.f;
        #pragma unroll
        for (int k = 0; k < 16; k++) s += g_part[slot * 16 + k];
        int n = (slot < 2) ? (DR * DM) : (slot == 2 ? (NOPS * DR) : OPSZ);
        g_scales[slot] = fmaxf(s / (float)n, 1e-5f);
    }
}
__global__ void quantb_kernel(const float* __restrict__ w, bf16* __restrict__ q,
                              int per, int slotBase, int n) {
    int i = blockIdx.x * blockDim.x + threadIdx.x;
    if (i < n) {
        float s = g_scales[slotBase + i / per];
        q[i] = __float2bfloat16(fminf(1.f, fmaxf(-1.f, rintf(w[i] / s))));
    }
}
__global__ void quantr_kernel(const float* __restrict__ w) {
    int i = blockIdx.x * blockDim.x + threadIdx.x;
    if (i < NOPS * DR) {
        float s = g_scales[2];
        g_WrouterE[i] = fminf(1.f, fmaxf(-1.f, rintf(w[i] / s))) * s;
    }
}
__global__ void split_kernel(const float* __restrict__ x, bf16* __restrict__ h,
                             bf16* __restrict__ l, int n) {
    int i = blockIdx.x * blockDim.x + threadIdx.x;
    if (i < n) {
        float v = x[i];
        bf16 hh = __float2bfloat16(v);
        h[i] = hh;
        l[i] = __float2bfloat16(v - __bfloat162float(hh));
    }
}
__global__ void tobf16_kernel(const float* __restrict__ x, bf16* __restrict__ h, int n) {
    int i = blockIdx.x * blockDim.x + threadIdx.x;
    if (i < n) h[i] = __float2bfloat16(x[i]);
}

// ======================= generic pipelined HMMA GEMM =======================
// C = alpha * sum_t( A_t @ Bh^T ) (+res); terms: 1={Ah}, 2=+{Al}. Optional Ch.
__global__ void __launch_bounds__(256)
mma_gemm(const bf16* __restrict__ Ah, const bf16* __restrict__ Al, int lda,
         const bf16* __restrict__ Bh, int ldb,
         float* __restrict__ C, int ldc, int K, int terms,
         float alphaC, const float* __restrict__ alphaPtr,
         const float* __restrict__ res, int ldr, bf16* __restrict__ Ch)
{
    extern __shared__ __align__(16) bf16 smp[];
    const uint32_t sBase = smem_u32(smp);
    const int tid = threadIdx.x, lane = tid & 31, wid = tid >> 5;
    const int wm = wid & 3, wn = wid >> 2;
    const int bm = blockIdx.x * 128, bn = blockIdx.y * 128;
    const int nk = K >> 6;
    const int total = terms * nk;

    float acc[2][8][4];
    #pragma unroll
    for (int i = 0; i < 2; i++)
        #pragma unroll
        for (int j = 0; j < 8; j++)
            #pragma unroll
            for (int k = 0; k < 4; k++) acc[i][j][k] = 0.f;

    int srow[4], skq[4];
    #pragma unroll
    for (int i = 0; i < 4; i++) {
        int slot = i * 256 + tid;
        srow[i] = slot >> 3;
        skq[i]  = (slot & 7) * 8;
    }
    auto load = [&](int c, int s) {
        int t = c / nk, k0 = (c - t * nk) << 6;
        const bf16* A = (t ? Al : Ah) + (size_t)bm * lda + k0;
        const bf16* B = Bh + (size_t)bn * ldb + k0;
        uint32_t dA = sBase + s * STAGE_BYTES;
        uint32_t dB = dA + TILE_BYTES;
        #pragma unroll
        for (int i = 0; i < 4; i++) {
            uint32_t off = (uint32_t)(srow[i] * AS_STRIDE + skq[i]) * 2;
            cp16(dA + off, A + (size_t)srow[i] * lda + skq[i]);
            cp16(dB + off, B + (size_t)srow[i] * ldb + skq[i]);
        }
        CP_COMMIT();
    };
    const uint32_t aOff = A_OFF(wm, lane), bOff = B_OFF(wn, lane);

    load(0, 0);
    for (int c = 0; c < total; c++) {
        int s = c & 1;
        if (c + 1 < total) { load(c + 1, (c + 1) & 1); CP_WAIT1(); }
        else CP_WAIT0();
        __syncthreads();
        compute_chunk(sBase + s * STAGE_BYTES + aOff,
                      sBase + s * STAGE_BYTES + TILE_BYTES + bOff, acc);
        __syncthreads();
    }

    float alpha = alphaC * (alphaPtr ? *alphaPtr : 1.0f);
    const int row0 = bm + wm * 32, col0 = bn + wn * 64;
    #pragma unroll
    for (int mf = 0; mf < 2; mf++) {
        #pragma unroll
        for (int half = 0; half < 2; half++) {
            int r = row0 + mf * 16 + (lane >> 2) + half * 8;
            #pragma unroll
            for (int nf = 0; nf < 8; nf++) {
                int c = col0 + nf * 8 + (lane & 3) * 2;
                float vx = alpha * acc[mf][nf][half * 2];
                float vy = alpha * acc[mf][nf][half * 2 + 1];
                if (res) {
                    const float* rp = res + (size_t)r * ldr + c;
                    vx += rp[0]; vy += rp[1];
                }
                float* cp = C + (size_t)r * ldc + c;
                cp[0] = vx; cp[1] = vy;
                if (Ch) {
                    size_t o = (size_t)r * ldc + c;
                    Ch[o]     = __float2bfloat16(vx);
                    Ch[o + 1] = __float2bfloat16(vy);
                }
            }
        }
    }
}

// Dual-B 1-term: blockIdx.y selects {B0->C0} or {B1->C1}
__global__ void __launch_bounds__(256)
mma_gemm2(const bf16* __restrict__ A, int lda,
          const bf16* __restrict__ B0, const bf16* __restrict__ B1, int ldb,
          float* __restrict__ C0, float* __restrict__ C1, int ldc, int K)
{
    extern __shared__ __align__(16) bf16 smp[];
    const uint32_t sBase = smem_u32(smp);
    const int tid = threadIdx.x, lane = tid & 31, wid = tid >> 5;
    const int wm = wid & 3, wn = wid >> 2;
    const int bm = blockIdx.x * 128;
    const bf16* B = blockIdx.y ? B1 : B0;
    float* C = blockIdx.y ? C1 : C0;
    const int nk = K >> 6;

    float acc[2][8][4];
    #pragma unroll
    for (int i = 0; i < 2; i++)
        #pragma unroll
        for (int j = 0; j < 8; j++)
            #pragma unroll
            for (int k = 0; k < 4; k++) acc[i][j][k] = 0.f;

    int srow[4], skq[4];
    #pragma unroll
    for (int i = 0; i < 4; i++) {
        int slot = i * 256 + tid;
        srow[i] = slot >> 3;
        skq[i]  = (slot & 7) * 8;
    }
    auto load = [&](int c, int s) {
        int k0 = c << 6;
        const bf16* Ap = A + (size_t)bm * lda + k0;
        const bf16* Bp = B + k0;
        uint32_t dA = sBase + s * STAGE_BYTES;
        uint32_t dB = dA + TILE_BYTES;
        #pragma unroll
        for (int i = 0; i < 4; i++) {
            uint32_t off = (uint32_t)(srow[i] * AS_STRIDE + skq[i]) * 2;
            cp16(dA + off, Ap + (size_t)srow[i] * lda + skq[i]);
            cp16(dB + off, Bp + (size_t)srow[i] * ldb + skq[i]);
        }
        CP_COMMIT();
    };
    const uint32_t aOff = A_OFF(wm, lane), bOff = B_OFF(wn, lane);

    load(0, 0);
    for (int c = 0; c < nk; c++) {
        int s = c & 1;
        if (c + 1 < nk) { load(c + 1, (c + 1) & 1); CP_WAIT1(); }
        else CP_WAIT0();
        __syncthreads();
        compute_chunk(sBase + s * STAGE_BYTES + aOff,
                      sBase + s * STAGE_BYTES + TILE_BYTES + bOff, acc);
        __syncthreads();
    }
    const int row0 = bm + wm * 32, col0 = wn * 64;
    #pragma unroll
    for (int mf = 0; mf < 2; mf++) {
        #pragma unroll
        for (int half = 0; half < 2; half++) {
            int r = row0 + mf * 16 + (lane >> 2) + half * 8;
            #pragma unroll
            for (int nf = 0; nf < 8; nf++) {
                int c = col0 + nf * 8 + (lane & 3) * 2;
                float* cp = C + (size_t)r * ldc + c;
                cp[0] = acc[mf][nf][half * 2];
                cp[1] = acc[mf][nf][half * 2 + 1];
            }
        }
    }
}

// ======================= mix GEMM + fused LayerNorm ========================
// tmp = reason + cat_h @ wmix^T (1-term, K=256) -> row LN -> reason & reason_h
__global__ void __launch_bounds__(256)
mma_mix_ln(const bf16* __restrict__ A, const bf16* __restrict__ B,
           const float* __restrict__ gamma, const float* __restrict__ beta)
{
    extern __shared__ __align__(16) bf16 smp[];
    const uint32_t sBase = smem_u32(smp);
    float* tmpsm = (float*)smp;                 // reused after pipeline: 128x129 fp32
    __shared__ float musm[128], rssm[128];
    const int tid = threadIdx.x, lane = tid & 31, wid = tid >> 5;
    const int wm = wid & 3, wn = wid >> 2;
    const int bm = blockIdx.x * 128;
    const int nk = 4;                            // K=256

    float acc[2][8][4];
    #pragma unroll
    for (int i = 0; i < 2; i++)
        #pragma unroll
        for (int j = 0; j < 8; j++)
            #pragma unroll
            for (int k = 0; k < 4; k++) acc[i][j][k] = 0.f;

    int srow[4], skq[4];
    #pragma unroll
    for (int i = 0; i < 4; i++) {
        int slot = i * 256 + tid;
        srow[i] = slot >> 3;
        skq[i]  = (slot & 7) * 8;
    }
    auto load = [&](int c, int s) {
        int k0 = c << 6;
        const bf16* Ap = A + (size_t)bm * 256 + k0;
        const bf16* Bp = B + k0;
        uint32_t dA = sBase + s * STAGE_BYTES;
        uint32_t dB = dA + TILE_BYTES;
        #pragma unroll
        for (int i = 0; i < 4; i++) {
            uint32_t off = (uint32_t)(srow[i] * AS_STRIDE + skq[i]) * 2;
            cp16(dA + off, Ap + (size_t)srow[i] * 256 + skq[i]);
            cp16(dB + off, Bp + (size_t)srow[i] * 256 + skq[i]);
        }
        CP_COMMIT();
    };
    const uint32_t aOff = A_OFF(wm, lane), bOff = B_OFF(wn, lane);

    load(0, 0);
    for (int c = 0; c < nk; c++) {
        int s = c & 1;
        if (c + 1 < nk) { load(c + 1, (c + 1) & 1); CP_WAIT1(); }
        else CP_WAIT0();
        __syncthreads();
        compute_chunk(sBase + s * STAGE_BYTES + aOff,
                      sBase + s * STAGE_BYTES + TILE_BYTES + bOff, acc);
        __syncthreads();
    }

    // acc + reason -> tmpsm (stride 129, conflict-free row access)
    const int row0 = wm * 32, col0 = wn * 64;
    #pragma unroll
    for (int mf = 0; mf < 2; mf++) {
        #pragma unroll
        for (int half = 0; half < 2; half++) {
            int r = row0 + mf * 16 + (lane >> 2) + half * 8;
            #pragma unroll
            for (int nf = 0; nf < 8; nf++) {
                int c = col0 + nf * 8 + (lane & 3) * 2;
                const float* rp = g_reason + (size_t)(bm + r) * DR + c;
                tmpsm[r * 129 + c]     = acc[mf][nf][half * 2]     + rp[0];
                tmpsm[r * 129 + c + 1] = acc[mf][nf][half * 2 + 1] + rp[1];
            }
        }
    }
    __syncthreads();
    // row stats (threads 0-127, one row each)
    if (tid < 128) {
        float mu = 0.f, sq = 0.f;
        #pragma unroll 8
        for (int k = 0; k < 128; k++) {
            float v = tmpsm[tid * 129 + k];
            mu += v; sq += v * v;
        }
        mu *= (1.f / 128.f);
        float var = sq * (1.f / 128.f) - mu * mu;
        musm[tid] = mu;
        rssm[tid] = rsqrtf(var + 1e-5f);
    }
    __syncthreads();
    // coalesced normalized write
    for (int idx = tid; idx < 128 * 32; idx += 256) {
        int r = idx >> 5, c = (idx & 31) * 4;
        float mu = musm[r], rs = rssm[r];
        float o0 = (tmpsm[r * 129 + c]     - mu) * rs * gamma[c]     + beta[c];
        float o1 = (tmpsm[r * 129 + c + 1] - mu) * rs * gamma[c + 1] + beta[c + 1];
        float o2 = (tmpsm[r * 129 + c + 2] - mu) * rs * gamma[c + 2] + beta[c + 2];
        float o3 = (tmpsm[r * 129 + c + 3] - mu) * rs * gamma[c + 3] + beta[c + 3];
        size_t o = (size_t)(bm + r) * DR + c;
        *(float4*)(g_reason + o) = make_float4(o0, o1, o2, o3);
        g_reason_h[o]     = __float2bfloat16(o0);
        g_reason_h[o + 1] = __float2bfloat16(o1);
        g_reason_h[o + 2] = __float2bfloat16(o2);
        g_reason_h[o + 3] = __float2bfloat16(o3);
    }
}

// ======================= expert (gathered) HMMA, 1-term ====================
__global__ void __launch_bounds__(256)
expert_mma() {
    int op = blockIdx.y;
    int start = g_offsets[op];
    int cnt = g_offsets[op + 1] - start;
    extern __shared__ __align__(16) bf16 smp[];
    __shared__ int rowid[128];
    const uint32_t sBase = smem_u32(smp);
    const int tid = threadIdx.x, lane = tid & 31, wid = tid >> 5;
    const int wm = wid & 3, wn = wid >> 2;
    float alpha = g_scales[3 + op];
    const bf16* B0 = g_qops + (size_t)op * OPSZ;

    int srow[4], skq[4];
    #pragma unroll
    for (int i = 0; i < 4; i++) {
        int slot = i * 256 + tid;
        srow[i] = slot >> 3;
        skq[i]  = (slot & 7) * 8;
    }
    const uint32_t aOff = A_OFF(wm, lane), bOff = B_OFF(wn, lane);

    auto load = [&](int c, int s) {
        int k0 = c << 6;
        uint32_t dA = sBase + s * STAGE_BYTES;
        uint32_t dB = dA + TILE_BYTES;
        #pragma unroll
        for (int i = 0; i < 4; i++) {
            int grow = rowid[srow[i]];
            if (grow < 0) grow = 0;
            uint32_t off = (uint32_t)(srow[i] * AS_STRIDE + skq[i]) * 2;
            cp16(dA + off, g_reason_h + (size_t)grow * DR + k0 + skq[i]);
            cp16(dB + off, B0 + (size_t)srow[i] * DR + k0 + skq[i]);
        }
        CP_COMMIT();
    };

    for (int t0 = blockIdx.x * 128; t0 < cnt; t0 += gridDim.x * 128) {
        __syncthreads();
        if (tid < 128) rowid[tid] = (t0 + tid < cnt) ? g_perm[start + t0 + tid] : -1;
        __syncthreads();
        float acc[2][8][4];
        #pragma unroll
        for (int i = 0; i < 2; i++)
            #pragma unroll
            for (int j = 0; j < 8; j++)
                #pragma unroll
                for (int k = 0; k < 4; k++) acc[i][j][k] = 0.f;

        load(0, 0);
        #pragma unroll
        for (int c = 0; c < 2; c++) {
            int s = c & 1;
            if (c < 1) { load(c + 1, 1); CP_WAIT1(); }
            else CP_WAIT0();
            __syncthreads();
            compute_chunk(sBase + s * STAGE_BYTES + aOff,
                          sBase + s * STAGE_BYTES + TILE_BYTES + bOff, acc);
            __syncthreads();
        }
        const int row0 = wm * 32, col0 = wn * 64;
        #pragma unroll
        for (int mf = 0; mf < 2; mf++) {
            #pragma unroll
            for (int half = 0; half < 2; half++) {
                int rl = row0 + mf * 16 + (lane >> 2) + half * 8;
                if (t0 + rl < cnt) {
                    float* cp0 = g_contrib + (size_t)(start + t0 + rl) * DR;
                    #pragma unroll
                    for (int nf = 0; nf < 8; nf++) {
                        int c = col0 + nf * 8 + (lane & 3) * 2;
                        cp0[c]     = alpha * acc[mf][nf][half * 2];
                        cp0[c + 1] = alpha * acc[mf][nf][half * 2 + 1];
                    }
                }
            }
        }
    }
}

// ======================= router / bookkeeping ==============================
__global__ void __launch_bounds__(128)
router_kernel() {
    __shared__ float Wsm[NOPS][DR + 1];
    __shared__ float rsm[4][DR];
    int tid = threadIdx.x;
    for (int i = tid; i < NOPS * DR; i += 128) Wsm[i >> 7][i & 127] = g_WrouterE[i];
    __syncthreads();
    int warp = tid >> 5, lane = tid & 31;
    for (int t = blockIdx.x * 4 + warp; t < M_TOK; t += gridDim.x * 4) {
        float4 v = ((const float4*)(g_reason + (size_t)t * DR))[lane];
        ((float4*)rsm[warp])[lane] = v;
        __syncwarp();
        float logit = 0.f;
        #pragma unroll 8
        for (int k = 0; k < DR; k++) logit += rsm[warp][k] * Wsm[lane][k];
        float m1 = logit; int i1 = lane;
        #pragma unroll
        for (int o = 16; o; o >>= 1) {
            float om = __shfl_xor_sync(~0u, m1, o);
            int   oi = __shfl_xor_sync(~0u, i1, o);
            if (om > m1 || (om == m1 && oi < i1)) { m1 = om; i1 = oi; }
        }
        float l2 = (lane == i1) ? -CUDART_INF_F : logit;
        float m2 = l2; int i2 = lane;
        #pragma unroll
        for (int o = 16; o; o >>= 1) {
            float om = __shfl_xor_sync(~0u, m2, o);
            int   oi = __shfl_xor_sync(~0u, i2, o);
            if (om > m2 || (om == m2 && oi < i2)) { m2 = om; i2 = oi; }
        }
        if (lane == 0) {
            float e = expf(m2 - m1);
            g_idx[2*t]   = i1; g_idx[2*t+1] = i2;
            g_w[2*t]     = 1.f / (1.f + e);
            g_w[2*t+1]   = e / (1.f + e);
            atomicAdd(&g_counts[i1], 1);
            atomicAdd(&g_counts[i2], 1);
        }
        __syncwarp();
    }
}
__global__ void zero_counts_kernel() { if (threadIdx.x < NOPS) g_counts[threadIdx.x] = 0; }
__global__ void scan_kernel() {
    int lane = threadIdx.x;
    int c = g_counts[lane];
    int x = c;
    #pragma unroll
    for (int o = 1; o < 32; o <<= 1) {
        int n = __shfl_up_sync(~0u, x, o);
        if (lane >= o) x += n;
    }
    g_offsets[lane + 1] = x;
    if (lane == 0) g_offsets[0] = 0;
    g_cursor[lane] = x - c;
}
__global__ void scatter_kernel() {
    int i = blockIdx.x * blockDim.x + threadIdx.x;
    if (i < NASSIGN) {
        int opx = g_idx[i];
        int p = atomicAdd(&g_cursor[opx], 1);
        g_perm[p] = i >> 1;
        g_pos[i]  = p;
    }
}

// combine + memread fused: cat_h[:, :128] = w0*c0 + w1*c1; cat_h[:, 128:] = attn@slots
__global__ void __launch_bounds__(128)
combine_memread(const float* __restrict__ slots) {
    __shared__ float ssm[NSLOTS][DR + 1];
    __shared__ float rsm[4][DR];
    __shared__ float attn_s[4][NSLOTS];
    int tid = threadIdx.x;
    for (int i = tid; i < NSLOTS * DR; i += 128) ssm[i >> 7][i & 127] = slots[i];
    __syncthreads();
    int warp = tid >> 5, lane = tid & 31;
    const float inv_sqrt_d = 0.08838834764831845f;
    for (int t = blockIdx.x * 4 + warp; t < M_TOK; t += gridDim.x * 4) {
        // ---- op half ----
        int p0 = g_pos[2*t], p1 = g_pos[2*t+1];
        float w0 = g_w[2*t], w1 = g_w[2*t+1];
        float4 c0 = ((const float4*)(g_contrib + (size_t)p0 * DR))[lane];
        float4 c1 = ((const float4*)(g_contrib + (size_t)p1 * DR))[lane];
        size_t ob = (size_t)t * 256 + lane * 4;
        g_cat_h[ob]     = __float2bfloat16(w0 * c0.x + w1 * c1.x);
        g_cat_h[ob + 1] = __float2bfloat16(w0 * c0.y + w1 * c1.y);
        g_cat_h[ob + 2] = __float2bfloat16(w0 * c0.z + w1 * c1.z);
        g_cat_h[ob + 3] = __float2bfloat16(w0 * c0.w + w1 * c1.w);
        // ---- mem half ----
        float4 v = ((const float4*)(g_key + (size_t)t * DR))[lane];
        ((float4*)rsm[warp])[lane] = v;
        __syncwarp();
        float logit = -CUDART_INF_F;
        if (lane < NSLOTS) {
            float s = 0.f;
            #pragma unroll 8
            for (int k = 0; k < DR; k++) s += rsm[warp][k] * ssm[lane][k];
            logit = s * inv_sqrt_d;
        }
        float mx = logit;
        #pragma unroll
        for (int o = 16; o; o >>= 1) mx = fmaxf(mx, __shfl_xor_sync(~0u, mx, o));
        float e = (lane < NSLOTS) ? expf(logit - mx) : 0.f;
        float se = e;
        #pragma unroll
        for (int o = 16; o; o >>= 1) se += __shfl_xor_sync(~0u, se, o);
        if (lane < NSLOTS) attn_s[warp][lane] = e / se;
        __syncwarp();
        float ov[4] = {0.f, 0.f, 0.f, 0.f};
        #pragma unroll
        for (int s2 = 0; s2 < NSLOTS; s2++) {
            float a = attn_s[warp][s2];
            ov[0] += a * ssm[s2][lane*4+0];
            ov[1] += a * ssm[s2][lane*4+1];
            ov[2] += a * ssm[s2][lane*4+2];
            ov[3] += a * ssm[s2][lane*4+3];
        }
        g_cat_h[ob + 128] = __float2bfloat16(ov[0]);
        g_cat_h[ob + 129] = __float2bfloat16(ov[1]);
        g_cat_h[ob + 130] = __float2bfloat16(ov[2]);
        g_cat_h[ob + 131] = __float2bfloat16(ov[3]);
        __syncwarp();
    }
}

// write signal: reason += ws*(wg*wv + 0.1*addr@slots)
__global__ void __launch_bounds__(128)
write_kernel(const float* __restrict__ slots, const float* __restrict__ Wg,
             const float* __restrict__ wsp) {
    __shared__ float ssm[NSLOTS][DR + 1];
    __shared__ float wgs[DR];
    __shared__ float rsm[4][DR];
    __shared__ float attn_s[4][NSLOTS];
    int tid = threadIdx.x;
    for (int i = tid; i < NSLOTS * DR; i += 128) ssm[i >> 7][i & 127] = slots[i];
    wgs[tid] = Wg[tid];
    __syncthreads();
    int warp = tid >> 5, lane = tid & 31;
    float ws = *wsp;
    const float inv_sqrt_d = 0.08838834764831845f;
    for (int t = blockIdx.x * 4 + warp; t < M_TOK; t += gridDim.x * 4) {
        float4 r = ((const float4*)(g_reason + (size_t)t * DR))[lane];
        float4 wg4 = ((const float4*)wgs)[lane];
        float gd = r.x*wg4.x + r.y*wg4.y + r.z*wg4.z + r.w*wg4.w;
        #pragma unroll
        for (int o = 16; o; o >>= 1) gd += __shfl_xor_sync(~0u, gd, o);
        float wg = 1.f / (1.f + expf(-gd));
        float4 k4 = ((const float4*)(g_key + (size_t)t * DR))[lane];
        ((float4*)rsm[warp])[lane] = k4;
        __syncwarp();
        float logit = -CUDART_INF_F;
        if (lane < NSLOTS) {
            float sdot = 0.f;
            #pragma unroll 8
            for (int k = 0; k < DR; k++) sdot += rsm[warp][k] * ssm[lane][k];
            logit = sdot * inv_sqrt_d;
        }
        float mx = logit;
        #pragma unroll
        for (int o = 16; o; o >>= 1) mx = fmaxf(mx, __shfl_xor_sync(~0u, mx, o));
        float e = (lane < NSLOTS) ? expf(logit - mx) : 0.f;
        float se = e;
        #pragma unroll
        for (int o = 16; o; o >>= 1) se += __shfl_xor_sync(~0u, se, o);
        if (lane < NSLOTS) attn_s[warp][lane] = e / se;
        __syncwarp();
        float4 wv = ((const float4*)(g_tmp + (size_t)t * DR))[lane];
        float ov[4];
        ov[0] = wg * wv.x; ov[1] = wg * wv.y; ov[2] = wg * wv.z; ov[3] = wg * wv.w;
        #pragma unroll
        for (int s2 = 0; s2 < NSLOTS; s2++) {
            float a = 0.1f * attn_s[warp][s2];
            ov[0] += a * ssm[s2][lane*4+0];
            ov[1] += a * ssm[s2][lane*4+1];
            ov[2] += a * ssm[s2][lane*4+2];
            ov[3] += a * ssm[s2][lane*4+3];
        }
        float o4[4];
        o4[0] = r.x + ws * ov[0]; o4[1] = r.y + ws * ov[1];
        o4[2] = r.z + ws * ov[2]; o4[3] = r.w + ws * ov[3];
        size_t o = (size_t)t * DR + lane * 4;
        *(float4*)(g_reason + o) = make_float4(o4[0], o4[1], o4[2], o4[3]);
        g_reason_h[o]     = __float2bfloat16(o4[0]);
        g_reason_h[o + 1] = __float2bfloat16(o4[1]);
        g_reason_h[o + 2] = __float2bfloat16(o4[2]);
        g_reason_h[o + 3] = __float2bfloat16(o4[3]);
        __syncwarp();
    }
}

// ======================= launch ============================================
extern "C" void kernel_launch(void* const* d_in, const int* in_sizes, int n_in,
                              void* d_out, int out_size) {
    const float* hidden   = (const float*)d_in[0];
    const float* W_down   = (const float*)d_in[2];
    const float* W_up     = (const float*)d_in[3];
    const float* ops      = (const float*)d_in[4];
    const float* W_router = (const float*)d_in[5];
    const float* slots    = (const float*)d_in[6];
    const float* W_read   = (const float*)d_in[7];
    const float* W_wk     = (const float*)d_in[8];
    const float* W_wg     = (const float*)d_in[9];
    const float* W_wv     = (const float*)d_in[10];
    const float* W_mix    = (const float*)d_in[11];
    const float* gamma    = (const float*)d_in[12];
    const float* beta     = (const float*)d_in[13];
    const float* wscale   = (const float*)d_in[14];
    float* out = (float*)d_out;

    static bool attr_done = false;
    if (!attr_done) {
        cudaFuncSetAttribute(mma_gemm,   cudaFuncAttributeMaxDynamicSharedMemorySize, SMEM_PIPE);
        cudaFuncSetAttribute(mma_gemm2,  cudaFuncAttributeMaxDynamicSharedMemorySize, SMEM_PIPE);
        cudaFuncSetAttribute(mma_mix_ln, cudaFuncAttributeMaxDynamicSharedMemorySize, SMEM_PIPE);
        cudaFuncSetAttribute(expert_mma, cudaFuncAttributeMaxDynamicSharedMemorySize, SMEM_PIPE);
        attr_done = true;
    }

    float *pReason, *pTmp, *pKey, *pScales;
    bf16 *pHidH, *pHidL, *pReasH, *pCatH;
    bf16 *pQdown, *pQup, *pQops, *pWreadH, *pWwkH, *pWwvH, *pWmixH;
    cudaGetSymbolAddress((void**)&pReason, g_reason);
    cudaGetSymbolAddress((void**)&pTmp,    g_tmp);
    cudaGetSymbolAddress((void**)&pKey,    g_key);
    cudaGetSymbolAddress((void**)&pScales, g_scales);
    cudaGetSymbolAddress((void**)&pHidH,   g_hid_h);
    cudaGetSymbolAddress((void**)&pHidL,   g_hid_l);
    cudaGetSymbolAddress((void**)&pReasH,  g_reason_h);
    cudaGetSymbolAddress((void**)&pCatH,   g_cat_h);
    cudaGetSymbolAddress((void**)&pQdown,  g_qdown);
    cudaGetSymbolAddress((void**)&pQup,    g_qup);
    cudaGetSymbolAddress((void**)&pQops,   g_qops);
    cudaGetSymbolAddress((void**)&pWreadH, g_wread_h);
    cudaGetSymbolAddress((void**)&pWwkH,   g_wwk_h);
    cudaGetSymbolAddress((void**)&pWwvH,   g_wwv_h);
    cudaGetSymbolAddress((void**)&pWmixH,  g_wmix_h);

    // --- scales ---
    absmean_p1<<<dim3(16, 1), 256>>>(W_down,   DR * DM,   0);
    absmean_p1<<<dim3(16, 1), 256>>>(W_up,     DM * DR,   1);
    absmean_p1<<<dim3(16, 1), 256>>>(W_router, NOPS * DR, 2);
    absmean_p1<<<dim3(16, NOPS), 256>>>(ops,   OPSZ,      3);
    absmean_p2<<<1, 64>>>();

    // --- quantize / convert ---
    quantb_kernel<<<(DR*DM + 255)/256, 256>>>(W_down, pQdown, DR*DM, 0, DR*DM);
    quantb_kernel<<<(DM*DR + 255)/256, 256>>>(W_up,   pQup,   DM*DR, 1, DM*DR);
    quantb_kernel<<<(NOPS*OPSZ + 255)/256, 256>>>(ops, pQops, OPSZ, 3, NOPS*OPSZ);
    quantr_kernel<<<(NOPS*DR + 255)/256, 256>>>(W_router);
    split_kernel<<<(M_TOK*DM + 255)/256, 256>>>(hidden, pHidH, pHidL, M_TOK*DM);
    tobf16_kernel<<<(OPSZ + 255)/256, 256>>>(W_read, pWreadH, OPSZ);
    tobf16_kernel<<<(OPSZ + 255)/256, 256>>>(W_wk,   pWwkH,   OPSZ);
    tobf16_kernel<<<(OPSZ + 255)/256, 256>>>(W_wv,   pWwvH,   OPSZ);
    tobf16_kernel<<<(DR*2*DR + 255)/256, 256>>>(W_mix, pWmixH, DR*2*DR);

    // --- down: reason = s_down * (hidH+hidL) @ qdown^T (2-term, + reason_h) ---
    mma_gemm<<<dim3(M_TOK/128, 1), 256, SMEM_PIPE>>>(pHidH, pHidL, DM, pQdown, DM,
        pReason, DR, DM, 2, 1.f, pScales + 0, nullptr, 0, pReasH);

    // --- reasoning passes ---
    for (int pass = 0; pass < DEPTH; pass++) {
        zero_counts_kernel<<<1, 32>>>();
        router_kernel<<<148, 128>>>();
        scan_kernel<<<1, 32>>>();
        scatter_kernel<<<NASSIGN/256, 256>>>();
        expert_mma<<<dim3(8, NOPS), 256, SMEM_PIPE>>>();
        // key = reason_h @ wread^T (1-term)
        mma_gemm<<<dim3(M_TOK/128, 1), 256, SMEM_PIPE>>>(pReasH, nullptr, DR, pWreadH, DR,
            pKey, DR, DR, 1, 1.f, nullptr, nullptr, 0, nullptr);
        combine_memread<<<148, 128>>>(slots);
        // mix + LN fused
        mma_mix_ln<<<M_TOK/128, 256, SMEM_PIPE>>>(pCatH, pWmixH, gamma, beta);
    }

    // --- write signal: wk -> key, wv -> tmp ---
    mma_gemm2<<<dim3(M_TOK/128, 2), 256, SMEM_PIPE>>>(pReasH, DR, pWwkH, pWwvH, DR,
        pKey, pTmp, DR, DR);
    write_kernel<<<148, 128>>>(slots, W_wg, wscale);

    // --- up: out = hidden + s_up * reason_h @ qup^T (1-term) ---
    mma_gemm<<<dim3(M_TOK/128, DM/128), 256, SMEM_PIPE>>>(pReasH, nullptr, DR, pQup, DR,
        out, DM, DR, 1, 1.f, pScales + 1, hidden, DM, nullptr);
}

// round 10
// speedup vs baseline: 3.5649x; 1.1886x over previous
#include <cuda_runtime.h>
#include <cuda_bf16.h>
#include <math.h>
#include <math_constants.h>
#include <stdint.h>

#define M_TOK 16384
#define DM    1024
#define DR    128
#define NOPS  32
#define NSLOTS 16
#define OPSZ  (DR*DR)
#define NASSIGN (M_TOK*2)
#define DEPTH 2

typedef __nv_bfloat16 bf16;

#define AS_STRIDE 72
#define TILE_BYTES (128 * AS_STRIDE * 2)   // 18432
#define STAGE_BYTES (2 * TILE_BYTES)
#define SMEM_PIPE (2 * STAGE_BYTES)        // 73728

// mma_down smem layout: Ah | Al | B0 | B1 | F0 | F1
#define F_STRIDE 68                                  // fp32 elems per row (64+4 pad)
#define FTILE_BYTES (128 * F_STRIDE * 4)             // 34816
#define DOWN_AH   0
#define DOWN_AL   TILE_BYTES
#define DOWN_B0   (2 * TILE_BYTES)
#define DOWN_B1   (3 * TILE_BYTES)
#define DOWN_F0   (4 * TILE_BYTES)
#define DOWN_F1   (4 * TILE_BYTES + FTILE_BYTES)
#define SMEM_DOWN (4 * TILE_BYTES + 2 * FTILE_BYTES) // 143360

// single extern shared symbol for ALL kernels (char; cast locally)
extern __shared__ __align__(16) char smraw[];

// ======================= PTX helpers =======================================
__device__ __forceinline__ uint32_t smem_u32(const void* p) {
    uint32_t a;
    asm("{ .reg .u64 t; cvta.to.shared.u64 t, %1; cvt.u32.u64 %0, t; }" : "=r"(a) : "l"(p));
    return a;
}
__device__ __forceinline__ void ldsm_x4(uint32_t& r0, uint32_t& r1, uint32_t& r2,
                                        uint32_t& r3, uint32_t addr) {
    asm volatile("ldmatrix.sync.aligned.m8n8.x4.shared.b16 {%0,%1,%2,%3}, [%4];"
                 : "=r"(r0), "=r"(r1), "=r"(r2), "=r"(r3) : "r"(addr));
}
__device__ __forceinline__ void mma_bf16(float* d, const uint32_t* a, const uint32_t* b) {
    asm volatile(
        "mma.sync.aligned.m16n8k16.row.col.f32.bf16.bf16.f32 "
        "{%0,%1,%2,%3}, {%4,%5,%6,%7}, {%8,%9}, {%0,%1,%2,%3};"
        : "+f"(d[0]), "+f"(d[1]), "+f"(d[2]), "+f"(d[3])
        : "r"(a[0]), "r"(a[1]), "r"(a[2]), "r"(a[3]), "r"(b[0]), "r"(b[1]));
}
__device__ __forceinline__ void cp16(uint32_t smem, const void* gmem) {
    asm volatile("cp.async.cg.shared.global [%0], [%1], 16;" :: "r"(smem), "l"(gmem));
}
#define CP_COMMIT() asm volatile("cp.async.commit_group;" ::: "memory")
#define CP_WAIT1()  asm volatile("cp.async.wait_group 1;" ::: "memory")
#define CP_WAIT0()  asm volatile("cp.async.wait_group 0;" ::: "memory")

#define A_OFF(wm, lane) ((uint32_t)((((wm) * 32 + ((lane) & 15)) * AS_STRIDE + ((lane) >> 4) * 8) * 2))
#define B_OFF(wn, lane) ((uint32_t)((((wn) * 64 + (((lane) >> 4) & 1) * 8 + ((lane) & 7)) * AS_STRIDE + (((lane) >> 3) & 1) * 8) * 2))

__device__ __forceinline__ void compute_chunk(uint32_t aAddr, uint32_t bAddr,
                                              float acc[2][8][4]) {
    #pragma unroll
    for (int kk = 0; kk < 4; kk++) {
        uint32_t a[2][4], b[4][4];
        #pragma unroll
        for (int mf = 0; mf < 2; mf++)
            ldsm_x4(a[mf][0], a[mf][1], a[mf][2], a[mf][3],
                    aAddr + (uint32_t)((mf * 16 * AS_STRIDE + kk * 16) * 2));
        #pragma unroll
        for (int nfp = 0; nfp < 4; nfp++)
            ldsm_x4(b[nfp][0], b[nfp][1], b[nfp][2], b[nfp][3],
                    bAddr + (uint32_t)((nfp * 16 * AS_STRIDE + kk * 16) * 2));
        #pragma unroll
        for (int mf = 0; mf < 2; mf++)
            #pragma unroll
            for (int nf = 0; nf < 8; nf++)
                mma_bf16(acc[mf][nf], a[mf], &b[nf >> 1][(nf & 1) * 2]);
    }
}

// ======================= scratch ===========================================
__device__ float g_reason [M_TOK*DR];
__device__ float g_tmp    [M_TOK*DR];
__device__ float g_key    [M_TOK*DR];
__device__ float g_contrib[NASSIGN*DR];
__device__ bf16  g_reason_h[M_TOK*DR];
__device__ bf16  g_cat_h  [M_TOK*2*DR];
__device__ bf16  g_qdown  [DR*DM];
__device__ bf16  g_qup    [DM*DR];
__device__ bf16  g_qops   [NOPS*OPSZ];
__device__ bf16  g_wread_h[OPSZ];
__device__ bf16  g_wwk_h  [OPSZ];
__device__ bf16  g_wwv_h  [OPSZ];
__device__ bf16  g_wmix_h [DR*2*DR];
__device__ float g_WrouterE[NOPS*DR];
__device__ float g_scales [40];
__device__ float g_part   [40*16];
__device__ int   g_idx    [NASSIGN];
__device__ float g_w      [NASSIGN];
__device__ int   g_counts [NOPS];
__device__ int   g_cursor [NOPS];
__device__ int   g_perm   [NASSIGN];
__device__ int   g_pos    [NASSIGN];

// ======================= scale computation =================================
__global__ void absmean_all(const float* __restrict__ Wd, const float* __restrict__ Wu,
                            const float* __restrict__ Wr, const float* __restrict__ Wo) {
    int mat = blockIdx.y, seg = blockIdx.x;
    const float* src;
    int n;
    if (mat == 0)      { src = Wd; n = DR * DM; }
    else if (mat == 1) { src = Wu; n = DR * DM; }
    else if (mat == 2) { src = Wr; n = NOPS * DR; }
    else               { src = Wo + (size_t)(mat - 3) * OPSZ; n = OPSZ; }
    int segn = n >> 4;
    const float* p = src + (size_t)seg * segn;
    float s = 0.f;
    for (int i = threadIdx.x; i < segn; i += blockDim.x) s += fabsf(p[i]);
    __shared__ float red[8];
    int lane = threadIdx.x & 31, wid = threadIdx.x >> 5;
    #pragma unroll
    for (int o = 16; o; o >>= 1) s += __shfl_xor_sync(~0u, s, o);
    if (lane == 0) red[wid] = s;
    __syncthreads();
    if (threadIdx.x == 0) {
        float t = 0.f;
        for (int k = 0; k < (int)(blockDim.x >> 5); k++) t += red[k];
        g_part[mat * 16 + seg] = t;
    }
}
__global__ void absmean_p2() {
    int slot = threadIdx.x;
    if (slot < 35) {
        float s = 0.f;
        #pragma unroll
        for (int k = 0; k < 16; k++) s += g_part[slot * 16 + k];
        int n = (slot < 2) ? (DR * DM) : (slot == 2 ? (NOPS * DR) : OPSZ);
        g_scales[slot] = fmaxf(s / (float)n, 1e-5f);
    }
}

__device__ __forceinline__ float tern(float w, float s) {
    return fminf(1.f, fmaxf(-1.f, rintf(w / s)));
}
__global__ void prep_all(const float* __restrict__ Wd, const float* __restrict__ Wu,
                         const float* __restrict__ Wo, const float* __restrict__ Wr,
                         const float* __restrict__ Wread, const float* __restrict__ Wwk,
                         const float* __restrict__ Wwv, const float* __restrict__ Wmix) {
    int i = blockIdx.x * 256 + threadIdx.x;
    if (i < 131072) {
        g_qdown[i] = __float2bfloat16(tern(Wd[i], g_scales[0]));
    } else if (i < 262144) {
        int j = i - 131072;
        g_qup[j] = __float2bfloat16(tern(Wu[j], g_scales[1]));
    } else if (i < 786432) {
        int j = i - 262144;
        g_qops[j] = __float2bfloat16(tern(Wo[j], g_scales[3 + j / OPSZ]));
    } else if (i < 790528) {
        int j = i - 786432;
        g_WrouterE[j] = tern(Wr[j], g_scales[2]) * g_scales[2];
    } else if (i < 806912) {
        int j = i - 790528;
        g_wread_h[j] = __float2bfloat16(Wread[j]);
    } else if (i < 823296) {
        int j = i - 806912;
        g_wwk_h[j] = __float2bfloat16(Wwk[j]);
    } else if (i < 839680) {
        int j = i - 823296;
        g_wwv_h[j] = __float2bfloat16(Wwv[j]);
    } else if (i < 872448) {
        int j = i - 839680;
        g_wmix_h[j] = __float2bfloat16(Wmix[j]);
    } else if (i < 872480) {
        g_counts[i - 872448] = 0;
    } else if (i < 872512) {
        g_cursor[i - 872480] = 0;
    }
}

// ======================= down GEMM with fused fp32->hi/lo split ============
__global__ void __launch_bounds__(256)
mma_down(const float* __restrict__ hidden, const bf16* __restrict__ B,
         const float* __restrict__ alphaPtr) {
    char* smp = smraw;
    const uint32_t sBase = smem_u32(smp);
    const int tid = threadIdx.x, lane = tid & 31, wid = tid >> 5;
    const int wm = wid & 3, wn = wid >> 2;
    const int bm = blockIdx.x * 128;

    float acc[2][8][4];
    #pragma unroll
    for (int i = 0; i < 2; i++)
        #pragma unroll
        for (int j = 0; j < 8; j++)
            #pragma unroll
            for (int k = 0; k < 4; k++) acc[i][j][k] = 0.f;

    int arow[8], aq[8];
    #pragma unroll
    for (int i = 0; i < 8; i++) {
        int slot = i * 256 + tid;
        arow[i] = slot >> 4;
        aq[i]   = slot & 15;
    }
    int brow[4], bkq[4];
    #pragma unroll
    for (int i = 0; i < 4; i++) {
        int slot = i * 256 + tid;
        brow[i] = slot >> 3;
        bkq[i]  = (slot & 7) * 8;
    }
    auto load = [&](int c, int s) {
        int k0 = c << 6;
        uint32_t dF = sBase + (s ? DOWN_F1 : DOWN_F0);
        uint32_t dB = sBase + (s ? DOWN_B1 : DOWN_B0);
        #pragma unroll
        for (int i = 0; i < 8; i++)
            cp16(dF + (uint32_t)(arow[i] * F_STRIDE + aq[i] * 4) * 4,
                 hidden + (size_t)(bm + arow[i]) * DM + k0 + aq[i] * 4);
        #pragma unroll
        for (int i = 0; i < 4; i++)
            cp16(dB + (uint32_t)(brow[i] * AS_STRIDE + bkq[i]) * 2,
                 B + (size_t)brow[i] * DM + k0 + bkq[i]);
        CP_COMMIT();
    };
    const uint32_t aOff = A_OFF(wm, lane), bOff = B_OFF(wn, lane);

    load(0, 0);
    for (int c = 0; c < 16; c++) {
        int s = c & 1;
        if (c + 1 < 16) { load(c + 1, s ^ 1); CP_WAIT1(); }
        else CP_WAIT0();
        __syncthreads();
        const float* F = (const float*)(smp + (s ? DOWN_F1 : DOWN_F0));
        #pragma unroll
        for (int i = 0; i < 8; i++) {
            float4 v = *(const float4*)(F + arow[i] * F_STRIDE + aq[i] * 4);
            bf16 h0 = __float2bfloat16(v.x), h1 = __float2bfloat16(v.y);
            bf16 h2 = __float2bfloat16(v.z), h3 = __float2bfloat16(v.w);
            bf16 l0 = __float2bfloat16(v.x - __bfloat162float(h0));
            bf16 l1 = __float2bfloat16(v.y - __bfloat162float(h1));
            bf16 l2 = __float2bfloat16(v.z - __bfloat162float(h2));
            bf16 l3 = __float2bfloat16(v.w - __bfloat162float(h3));
            int eoff = arow[i] * AS_STRIDE + aq[i] * 4;
            bf16* pH = (bf16*)(smp + DOWN_AH) + eoff;
            bf16* pL = (bf16*)(smp + DOWN_AL) + eoff;
            pH[0] = h0; pH[1] = h1; pH[2] = h2; pH[3] = h3;
            pL[0] = l0; pL[1] = l1; pL[2] = l2; pL[3] = l3;
        }
        __syncthreads();
        uint32_t bAddr = sBase + (s ? DOWN_B1 : DOWN_B0) + bOff;
        compute_chunk(sBase + DOWN_AH + aOff, bAddr, acc);
        compute_chunk(sBase + DOWN_AL + aOff, bAddr, acc);
    }
    __syncthreads();

    float alpha = *alphaPtr;
    const int row0 = bm + wm * 32, col0 = wn * 64;
    #pragma unroll
    for (int mf = 0; mf < 2; mf++) {
        #pragma unroll
        for (int half = 0; half < 2; half++) {
            int r = row0 + mf * 16 + (lane >> 2) + half * 8;
            #pragma unroll
            for (int nf = 0; nf < 8; nf++) {
                int c = col0 + nf * 8 + (lane & 3) * 2;
                float vx = alpha * acc[mf][nf][half * 2];
                float vy = alpha * acc[mf][nf][half * 2 + 1];
                float* cp = g_reason + (size_t)r * DR + c;
                cp[0] = vx; cp[1] = vy;
                size_t o = (size_t)r * DR + c;
                g_reason_h[o]     = __float2bfloat16(vx);
                g_reason_h[o + 1] = __float2bfloat16(vy);
            }
        }
    }
}

// ======================= generic pipelined HMMA GEMM (up) ==================
__global__ void __launch_bounds__(256)
mma_gemm(const bf16* __restrict__ Ah, int lda,
         const bf16* __restrict__ Bh, int ldb,
         float* __restrict__ C, int ldc, int K,
         const float* __restrict__ alphaPtr,
         const float* __restrict__ res, int ldr)
{
    char* smp = smraw;
    const uint32_t sBase = smem_u32(smp);
    const int tid = threadIdx.x, lane = tid & 31, wid = tid >> 5;
    const int wm = wid & 3, wn = wid >> 2;
    const int bm = blockIdx.x * 128, bn = blockIdx.y * 128;
    const int nk = K >> 6;

    float acc[2][8][4];
    #pragma unroll
    for (int i = 0; i < 2; i++)
        #pragma unroll
        for (int j = 0; j < 8; j++)
            #pragma unroll
            for (int k = 0; k < 4; k++) acc[i][j][k] = 0.f;

    int srow[4], skq[4];
    #pragma unroll
    for (int i = 0; i < 4; i++) {
        int slot = i * 256 + tid;
        srow[i] = slot >> 3;
        skq[i]  = (slot & 7) * 8;
    }
    auto load = [&](int c, int s) {
        int k0 = c << 6;
        const bf16* A = Ah + (size_t)bm * lda + k0;
        const bf16* B = Bh + (size_t)bn * ldb + k0;
        uint32_t dA = sBase + s * STAGE_BYTES;
        uint32_t dB = dA + TILE_BYTES;
        #pragma unroll
        for (int i = 0; i < 4; i++) {
            uint32_t off = (uint32_t)(srow[i] * AS_STRIDE + skq[i]) * 2;
            cp16(dA + off, A + (size_t)srow[i] * lda + skq[i]);
            cp16(dB + off, B + (size_t)srow[i] * ldb + skq[i]);
        }
        CP_COMMIT();
    };
    const uint32_t aOff = A_OFF(wm, lane), bOff = B_OFF(wn, lane);

    load(0, 0);
    for (int c = 0; c < nk; c++) {
        int s = c & 1;
        if (c + 1 < nk) { load(c + 1, (c + 1) & 1); CP_WAIT1(); }
        else CP_WAIT0();
        __syncthreads();
        compute_chunk(sBase + s * STAGE_BYTES + aOff,
                      sBase + s * STAGE_BYTES + TILE_BYTES + bOff, acc);
        __syncthreads();
    }

    float alpha = alphaPtr ? *alphaPtr : 1.0f;
    const int row0 = bm + wm * 32, col0 = bn + wn * 64;
    #pragma unroll
    for (int mf = 0; mf < 2; mf++) {
        #pragma unroll
        for (int half = 0; half < 2; half++) {
            int r = row0 + mf * 16 + (lane >> 2) + half * 8;
            #pragma unroll
            for (int nf = 0; nf < 8; nf++) {
                int c = col0 + nf * 8 + (lane & 3) * 2;
                float vx = alpha * acc[mf][nf][half * 2];
                float vy = alpha * acc[mf][nf][half * 2 + 1];
                if (res) {
                    const float* rp = res + (size_t)r * ldr + c;
                    vx += rp[0]; vy += rp[1];
                }
                float* cp = C + (size_t)r * ldc + c;
                cp[0] = vx; cp[1] = vy;
            }
        }
    }
}

// Dual-B 1-term: blockIdx.y selects {B0->C0} or {B1->C1}
__global__ void __launch_bounds__(256)
mma_gemm2(const bf16* __restrict__ A, int lda,
          const bf16* __restrict__ B0, const bf16* __restrict__ B1, int ldb,
          float* __restrict__ C0, float* __restrict__ C1, int ldc, int K)
{
    char* smp = smraw;
    const uint32_t sBase = smem_u32(smp);
    const int tid = threadIdx.x, lane = tid & 31, wid = tid >> 5;
    const int wm = wid & 3, wn = wid >> 2;
    const int bm = blockIdx.x * 128;
    const bf16* B = blockIdx.y ? B1 : B0;
    float* C = blockIdx.y ? C1 : C0;
    const int nk = K >> 6;

    float acc[2][8][4];
    #pragma unroll
    for (int i = 0; i < 2; i++)
        #pragma unroll
        for (int j = 0; j < 8; j++)
            #pragma unroll
            for (int k = 0; k < 4; k++) acc[i][j][k] = 0.f;

    int srow[4], skq[4];
    #pragma unroll
    for (int i = 0; i < 4; i++) {
        int slot = i * 256 + tid;
        srow[i] = slot >> 3;
        skq[i]  = (slot & 7) * 8;
    }
    auto load = [&](int c, int s) {
        int k0 = c << 6;
        const bf16* Ap = A + (size_t)bm * lda + k0;
        const bf16* Bp = B + k0;
        uint32_t dA = sBase + s * STAGE_BYTES;
        uint32_t dB = dA + TILE_BYTES;
        #pragma unroll
        for (int i = 0; i < 4; i++) {
            uint32_t off = (uint32_t)(srow[i] * AS_STRIDE + skq[i]) * 2;
            cp16(dA + off, Ap + (size_t)srow[i] * lda + skq[i]);
            cp16(dB + off, Bp + (size_t)srow[i] * ldb + skq[i]);
        }
        CP_COMMIT();
    };
    const uint32_t aOff = A_OFF(wm, lane), bOff = B_OFF(wn, lane);

    load(0, 0);
    for (int c = 0; c < nk; c++) {
        int s = c & 1;
        if (c + 1 < nk) { load(c + 1, (c + 1) & 1); CP_WAIT1(); }
        else CP_WAIT0();
        __syncthreads();
        compute_chunk(sBase + s * STAGE_BYTES + aOff,
                      sBase + s * STAGE_BYTES + TILE_BYTES + bOff, acc);
        __syncthreads();
    }
    const int row0 = bm + wm * 32, col0 = wn * 64;
    #pragma unroll
    for (int mf = 0; mf < 2; mf++) {
        #pragma unroll
        for (int half = 0; half < 2; half++) {
            int r = row0 + mf * 16 + (lane >> 2) + half * 8;
            #pragma unroll
            for (int nf = 0; nf < 8; nf++) {
                int c = col0 + nf * 8 + (lane & 3) * 2;
                float* cp = C + (size_t)r * ldc + c;
                cp[0] = acc[mf][nf][half * 2];
                cp[1] = acc[mf][nf][half * 2 + 1];
            }
        }
    }
}

// ======================= unified expert + key launch =======================
__global__ void __launch_bounds__(256)
pass_gemm() {
    char* smp = smraw;
    __shared__ int rowid[128];
    const uint32_t sBase = smem_u32(smp);
    const int tid = threadIdx.x, lane = tid & 31, wid = tid >> 5;
    const int wm = wid & 3, wn = wid >> 2;
    const int b = blockIdx.x;

    int srow[4], skq[4];
    #pragma unroll
    for (int i = 0; i < 4; i++) {
        int slot = i * 256 + tid;
        srow[i] = slot >> 3;
        skq[i]  = (slot & 7) * 8;
    }
    const uint32_t aOff = A_OFF(wm, lane), bOff = B_OFF(wn, lane);

    if (b >= 256) {
        // ---- key = reason_h @ wread^T ----
        const int bm = (b - 256) * 128;
        float acc[2][8][4];
        #pragma unroll
        for (int i = 0; i < 2; i++)
            #pragma unroll
            for (int j = 0; j < 8; j++)
                #pragma unroll
                for (int k = 0; k < 4; k++) acc[i][j][k] = 0.f;
        auto load = [&](int c, int s) {
            int k0 = c << 6;
            uint32_t dA = sBase + s * STAGE_BYTES;
            uint32_t dB = dA + TILE_BYTES;
            #pragma unroll
            for (int i = 0; i < 4; i++) {
                uint32_t off = (uint32_t)(srow[i] * AS_STRIDE + skq[i]) * 2;
                cp16(dA + off, g_reason_h + (size_t)(bm + srow[i]) * DR + k0 + skq[i]);
                cp16(dB + off, g_wread_h + (size_t)srow[i] * DR + k0 + skq[i]);
            }
            CP_COMMIT();
        };
        load(0, 0);
        #pragma unroll
        for (int c = 0; c < 2; c++) {
            int s = c & 1;
            if (c < 1) { load(1, 1); CP_WAIT1(); }
            else CP_WAIT0();
            __syncthreads();
            compute_chunk(sBase + s * STAGE_BYTES + aOff,
                          sBase + s * STAGE_BYTES + TILE_BYTES + bOff, acc);
            __syncthreads();
        }
        const int row0 = bm + wm * 32, col0 = wn * 64;
        #pragma unroll
        for (int mf = 0; mf < 2; mf++) {
            #pragma unroll
            for (int half = 0; half < 2; half++) {
                int r = row0 + mf * 16 + (lane >> 2) + half * 8;
                #pragma unroll
                for (int nf = 0; nf < 8; nf++) {
                    int c = col0 + nf * 8 + (lane & 3) * 2;
                    float* cp = g_key + (size_t)r * DR + c;
                    cp[0] = acc[mf][nf][half * 2];
                    cp[1] = acc[mf][nf][half * 2 + 1];
                }
            }
        }
        return;
    }

    // ---- expert path ----
    const int op = b >> 3;
    int start = 0;
    #pragma unroll
    for (int k = 0; k < NOPS; k++) if (k < op) start += g_counts[k];
    const int cnt = g_counts[op];
    const float alpha = g_scales[3 + op];
    const bf16* B0 = g_qops + (size_t)op * OPSZ;

    auto load = [&](int c, int s) {
        int k0 = c << 6;
        uint32_t dA = sBase + s * STAGE_BYTES;
        uint32_t dB = dA + TILE_BYTES;
        #pragma unroll
        for (int i = 0; i < 4; i++) {
            int grow = rowid[srow[i]];
            if (grow < 0) grow = 0;
            uint32_t off = (uint32_t)(srow[i] * AS_STRIDE + skq[i]) * 2;
            cp16(dA + off, g_reason_h + (size_t)grow * DR + k0 + skq[i]);
            cp16(dB + off, B0 + (size_t)srow[i] * DR + k0 + skq[i]);
        }
        CP_COMMIT();
    };

    for (int t0 = (b & 7) * 128; t0 < cnt; t0 += 8 * 128) {
        __syncthreads();
        if (tid < 128) rowid[tid] = (t0 + tid < cnt) ? g_perm[start + t0 + tid] : -1;
        __syncthreads();
        float acc[2][8][4];
        #pragma unroll
        for (int i = 0; i < 2; i++)
            #pragma unroll
            for (int j = 0; j < 8; j++)
                #pragma unroll
                for (int k = 0; k < 4; k++) acc[i][j][k] = 0.f;

        load(0, 0);
        #pragma unroll
        for (int c = 0; c < 2; c++) {
            int s = c & 1;
            if (c < 1) { load(1, 1); CP_WAIT1(); }
            else CP_WAIT0();
            __syncthreads();
            compute_chunk(sBase + s * STAGE_BYTES + aOff,
                          sBase + s * STAGE_BYTES + TILE_BYTES + bOff, acc);
            __syncthreads();
        }
        const int row0 = wm * 32, col0 = wn * 64;
        #pragma unroll
        for (int mf = 0; mf < 2; mf++) {
            #pragma unroll
            for (int half = 0; half < 2; half++) {
                int rl = row0 + mf * 16 + (lane >> 2) + half * 8;
                if (t0 + rl < cnt) {
                    float* cp0 = g_contrib + (size_t)(start + t0 + rl) * DR;
                    #pragma unroll
                    for (int nf = 0; nf < 8; nf++) {
                        int c = col0 + nf * 8 + (lane & 3) * 2;
                        cp0[c]     = alpha * acc[mf][nf][half * 2];
                        cp0[c + 1] = alpha * acc[mf][nf][half * 2 + 1];
                    }
                }
            }
        }
    }
}

// ======================= mix GEMM + fused LayerNorm (+ counter reset) ======
__global__ void __launch_bounds__(256)
mma_mix_ln(const bf16* __restrict__ A, const bf16* __restrict__ B,
           const float* __restrict__ gamma, const float* __restrict__ beta)
{
    char* smp = smraw;
    const uint32_t sBase = smem_u32(smp);
    float* tmpsm = (float*)smp;
    __shared__ float musm[128], rssm[128];
    const int tid = threadIdx.x, lane = tid & 31, wid = tid >> 5;
    const int wm = wid & 3, wn = wid >> 2;
    const int bm = blockIdx.x * 128;
    const int nk = 4;

    float acc[2][8][4];
    #pragma unroll
    for (int i = 0; i < 2; i++)
        #pragma unroll
        for (int j = 0; j < 8; j++)
            #pragma unroll
            for (int k = 0; k < 4; k++) acc[i][j][k] = 0.f;

    int srow[4], skq[4];
    #pragma unroll
    for (int i = 0; i < 4; i++) {
        int slot = i * 256 + tid;
        srow[i] = slot >> 3;
        skq[i]  = (slot & 7) * 8;
    }
    auto load = [&](int c, int s) {
        int k0 = c << 6;
        const bf16* Ap = A + (size_t)bm * 256 + k0;
        const bf16* Bp = B + k0;
        uint32_t dA = sBase + s * STAGE_BYTES;
        uint32_t dB = dA + TILE_BYTES;
        #pragma unroll
        for (int i = 0; i < 4; i++) {
            uint32_t off = (uint32_t)(srow[i] * AS_STRIDE + skq[i]) * 2;
            cp16(dA + off, Ap + (size_t)srow[i] * 256 + skq[i]);
            cp16(dB + off, Bp + (size_t)srow[i] * 256 + skq[i]);
        }
        CP_COMMIT();
    };
    const uint32_t aOff = A_OFF(wm, lane), bOff = B_OFF(wn, lane);

    load(0, 0);
    for (int c = 0; c < nk; c++) {
        int s = c & 1;
        if (c + 1 < nk) { load(c + 1, (c + 1) & 1); CP_WAIT1(); }
        else CP_WAIT0();
        __syncthreads();
        compute_chunk(sBase + s * STAGE_BYTES + aOff,
                      sBase + s * STAGE_BYTES + TILE_BYTES + bOff, acc);
        __syncthreads();
    }

    const int row0 = wm * 32, col0 = wn * 64;
    #pragma unroll
    for (int mf = 0; mf < 2; mf++) {
        #pragma unroll
        for (int half = 0; half < 2; half++) {
            int r = row0 + mf * 16 + (lane >> 2) + half * 8;
            #pragma unroll
            for (int nf = 0; nf < 8; nf++) {
                int c = col0 + nf * 8 + (lane & 3) * 2;
                const float* rp = g_reason + (size_t)(bm + r) * DR + c;
                tmpsm[r * 129 + c]     = acc[mf][nf][half * 2]     + rp[0];
                tmpsm[r * 129 + c + 1] = acc[mf][nf][half * 2 + 1] + rp[1];
            }
        }
    }
    __syncthreads();
    if (tid < 128) {
        float mu = 0.f, sq = 0.f;
        #pragma unroll 8
        for (int k = 0; k < 128; k++) {
            float v = tmpsm[tid * 129 + k];
            mu += v; sq += v * v;
        }
        mu *= (1.f / 128.f);
        float var = sq * (1.f / 128.f) - mu * mu;
        musm[tid] = mu;
        rssm[tid] = rsqrtf(var + 1e-5f);
    }
    __syncthreads();
    for (int idx = tid; idx < 128 * 32; idx += 256) {
        int r = idx >> 5, c = (idx & 31) * 4;
        float mu = musm[r], rs = rssm[r];
        float o0 = (tmpsm[r * 129 + c]     - mu) * rs * gamma[c]     + beta[c];
        float o1 = (tmpsm[r * 129 + c + 1] - mu) * rs * gamma[c + 1] + beta[c + 1];
        float o2 = (tmpsm[r * 129 + c + 2] - mu) * rs * gamma[c + 2] + beta[c + 2];
        float o3 = (tmpsm[r * 129 + c + 3] - mu) * rs * gamma[c + 3] + beta[c + 3];
        size_t o = (size_t)(bm + r) * DR + c;
        *(float4*)(g_reason + o) = make_float4(o0, o1, o2, o3);
        g_reason_h[o]     = __float2bfloat16(o0);
        g_reason_h[o + 1] = __float2bfloat16(o1);
        g_reason_h[o + 2] = __float2bfloat16(o2);
        g_reason_h[o + 3] = __float2bfloat16(o3);
    }
    if (blockIdx.x == 0 && tid < NOPS) { g_counts[tid] = 0; g_cursor[tid] = 0; }
}

// ======================= router / bookkeeping ==============================
__global__ void __launch_bounds__(128)
router_kernel() {
    __shared__ float Wsm[NOPS][DR + 1];
    __shared__ float rsm[4][DR];
    int tid = threadIdx.x;
    for (int i = tid; i < NOPS * DR; i += 128) Wsm[i >> 7][i & 127] = g_WrouterE[i];
    __syncthreads();
    int warp = tid >> 5, lane = tid & 31;
    for (int t = blockIdx.x * 4 + warp; t < M_TOK; t += gridDim.x * 4) {
        float4 v = ((const float4*)(g_reason + (size_t)t * DR))[lane];
        ((float4*)rsm[warp])[lane] = v;
        __syncwarp();
        float logit = 0.f;
        #pragma unroll 8
        for (int k = 0; k < DR; k++) logit += rsm[warp][k] * Wsm[lane][k];
        float m1 = logit; int i1 = lane;
        #pragma unroll
        for (int o = 16; o; o >>= 1) {
            float om = __shfl_xor_sync(~0u, m1, o);
            int   oi = __shfl_xor_sync(~0u, i1, o);
            if (om > m1 || (om == m1 && oi < i1)) { m1 = om; i1 = oi; }
        }
        float l2 = (lane == i1) ? -CUDART_INF_F : logit;
        float m2 = l2; int i2 = lane;
        #pragma unroll
        for (int o = 16; o; o >>= 1) {
            float om = __shfl_xor_sync(~0u, m2, o);
            int   oi = __shfl_xor_sync(~0u, i2, o);
            if (om > m2 || (om == m2 && oi < i2)) { m2 = om; i2 = oi; }
        }
        if (lane == 0) {
            float e = expf(m2 - m1);
            g_idx[2*t]   = i1; g_idx[2*t+1] = i2;
            g_w[2*t]     = 1.f / (1.f + e);
            g_w[2*t+1]   = e / (1.f + e);
            atomicAdd(&g_counts[i1], 1);
            atomicAdd(&g_counts[i2], 1);
        }
        __syncwarp();
    }
}
__global__ void scatter2() {
    int i = blockIdx.x * blockDim.x + threadIdx.x;
    if (i < NASSIGN) {
        int op = g_idx[i];
        int base = 0;
        for (int k = 0; k < op; k++) base += g_counts[k];
        int p = base + atomicAdd(&g_cursor[op], 1);
        g_perm[p] = i >> 1;
        g_pos[i]  = p;
    }
}

__global__ void __launch_bounds__(128)
combine_memread(const float* __restrict__ slots) {
    __shared__ float ssm[NSLOTS][DR + 1];
    __shared__ float rsm[4][DR];
    __shared__ float attn_s[4][NSLOTS];
    int tid = threadIdx.x;
    for (int i = tid; i < NSLOTS * DR; i += 128) ssm[i >> 7][i & 127] = slots[i];
    __syncthreads();
    int warp = tid >> 5, lane = tid & 31;
    const float inv_sqrt_d = 0.08838834764831845f;
    for (int t = blockIdx.x * 4 + warp; t < M_TOK; t += gridDim.x * 4) {
        int p0 = g_pos[2*t], p1 = g_pos[2*t+1];
        float w0 = g_w[2*t], w1 = g_w[2*t+1];
        float4 c0 = ((const float4*)(g_contrib + (size_t)p0 * DR))[lane];
        float4 c1 = ((const float4*)(g_contrib + (size_t)p1 * DR))[lane];
        size_t ob = (size_t)t * 256 + lane * 4;
        g_cat_h[ob]     = __float2bfloat16(w0 * c0.x + w1 * c1.x);
        g_cat_h[ob + 1] = __float2bfloat16(w0 * c0.y + w1 * c1.y);
        g_cat_h[ob + 2] = __float2bfloat16(w0 * c0.z + w1 * c1.z);
        g_cat_h[ob + 3] = __float2bfloat16(w0 * c0.w + w1 * c1.w);
        float4 v = ((const float4*)(g_key + (size_t)t * DR))[lane];
        ((float4*)rsm[warp])[lane] = v;
        __syncwarp();
        float logit = -CUDART_INF_F;
        if (lane < NSLOTS) {
            float s = 0.f;
            #pragma unroll 8
            for (int k = 0; k < DR; k++) s += rsm[warp][k] * ssm[lane][k];
            logit = s * inv_sqrt_d;
        }
        float mx = logit;
        #pragma unroll
        for (int o = 16; o; o >>= 1) mx = fmaxf(mx, __shfl_xor_sync(~0u, mx, o));
        float e = (lane < NSLOTS) ? expf(logit - mx) : 0.f;
        float se = e;
        #pragma unroll
        for (int o = 16; o; o >>= 1) se += __shfl_xor_sync(~0u, se, o);
        if (lane < NSLOTS) attn_s[warp][lane] = e / se;
        __syncwarp();
        float ov[4] = {0.f, 0.f, 0.f, 0.f};
        #pragma unroll
        for (int s2 = 0; s2 < NSLOTS; s2++) {
            float a = attn_s[warp][s2];
            ov[0] += a * ssm[s2][lane*4+0];
            ov[1] += a * ssm[s2][lane*4+1];
            ov[2] += a * ssm[s2][lane*4+2];
            ov[3] += a * ssm[s2][lane*4+3];
        }
        g_cat_h[ob + 128] = __float2bfloat16(ov[0]);
        g_cat_h[ob + 129] = __float2bfloat16(ov[1]);
        g_cat_h[ob + 130] = __float2bfloat16(ov[2]);
        g_cat_h[ob + 131] = __float2bfloat16(ov[3]);
        __syncwarp();
    }
}

__global__ void __launch_bounds__(128)
write_kernel(const float* __restrict__ slots, const float* __restrict__ Wg,
             const float* __restrict__ wsp) {
    __shared__ float ssm[NSLOTS][DR + 1];
    __shared__ float wgs[DR];
    __shared__ float rsm[4][DR];
    __shared__ float attn_s[4][NSLOTS];
    int tid = threadIdx.x;
    for (int i = tid; i < NSLOTS * DR; i += 128) ssm[i >> 7][i & 127] = slots[i];
    wgs[tid] = Wg[tid];
    __syncthreads();
    int warp = tid >> 5, lane = tid & 31;
    float ws = *wsp;
    const float inv_sqrt_d = 0.08838834764831845f;
    for (int t = blockIdx.x * 4 + warp; t < M_TOK; t += gridDim.x * 4) {
        float4 r = ((const float4*)(g_reason + (size_t)t * DR))[lane];
        float4 wg4 = ((const float4*)wgs)[lane];
        float gd = r.x*wg4.x + r.y*wg4.y + r.z*wg4.z + r.w*wg4.w;
        #pragma unroll
        for (int o = 16; o; o >>= 1) gd += __shfl_xor_sync(~0u, gd, o);
        float wg = 1.f / (1.f + expf(-gd));
        float4 k4 = ((const float4*)(g_key + (size_t)t * DR))[lane];
        ((float4*)rsm[warp])[lane] = k4;
        __syncwarp();
        float logit = -CUDART_INF_F;
        if (lane < NSLOTS) {
            float sdot = 0.f;
            #pragma unroll 8
            for (int k = 0; k < DR; k++) sdot += rsm[warp][k] * ssm[lane][k];
            logit = sdot * inv_sqrt_d;
        }
        float mx = logit;
        #pragma unroll
        for (int o = 16; o; o >>= 1) mx = fmaxf(mx, __shfl_xor_sync(~0u, mx, o));
        float e = (lane < NSLOTS) ? expf(logit - mx) : 0.f;
        float se = e;
        #pragma unroll
        for (int o = 16; o; o >>= 1) se += __shfl_xor_sync(~0u, se, o);
        if (lane < NSLOTS) attn_s[warp][lane] = e / se;
        __syncwarp();
        float4 wv = ((const float4*)(g_tmp + (size_t)t * DR))[lane];
        float ov[4];
        ov[0] = wg * wv.x; ov[1] = wg * wv.y; ov[2] = wg * wv.z; ov[3] = wg * wv.w;
        #pragma unroll
        for (int s2 = 0; s2 < NSLOTS; s2++) {
            float a = 0.1f * attn_s[warp][s2];
            ov[0] += a * ssm[s2][lane*4+0];
            ov[1] += a * ssm[s2][lane*4+1];
            ov[2] += a * ssm[s2][lane*4+2];
            ov[3] += a * ssm[s2][lane*4+3];
        }
        float o4[4];
        o4[0] = r.x + ws * ov[0]; o4[1] = r.y + ws * ov[1];
        o4[2] = r.z + ws * ov[2]; o4[3] = r.w + ws * ov[3];
        size_t o = (size_t)t * DR + lane * 4;
        *(float4*)(g_reason + o) = make_float4(o4[0], o4[1], o4[2], o4[3]);
        g_reason_h[o]     = __float2bfloat16(o4[0]);
        g_reason_h[o + 1] = __float2bfloat16(o4[1]);
        g_reason_h[o + 2] = __float2bfloat16(o4[2]);
        g_reason_h[o + 3] = __float2bfloat16(o4[3]);
        __syncwarp();
    }
}

// ======================= launch ============================================
extern "C" void kernel_launch(void* const* d_in, const int* in_sizes, int n_in,
                              void* d_out, int out_size) {
    const float* hidden   = (const float*)d_in[0];
    const float* W_down   = (const float*)d_in[2];
    const float* W_up     = (const float*)d_in[3];
    const float* ops      = (const float*)d_in[4];
    const float* W_router = (const float*)d_in[5];
    const float* slots    = (const float*)d_in[6];
    const float* W_read   = (const float*)d_in[7];
    const float* W_wk     = (const float*)d_in[8];
    const float* W_wg     = (const float*)d_in[9];
    const float* W_wv     = (const float*)d_in[10];
    const float* W_mix    = (const float*)d_in[11];
    const float* gamma    = (const float*)d_in[12];
    const float* beta     = (const float*)d_in[13];
    const float* wscale   = (const float*)d_in[14];
    float* out = (float*)d_out;

    static bool attr_done = false;
    if (!attr_done) {
        cudaFuncSetAttribute(mma_down,   cudaFuncAttributeMaxDynamicSharedMemorySize, SMEM_DOWN);
        cudaFuncSetAttribute(mma_gemm,   cudaFuncAttributeMaxDynamicSharedMemorySize, SMEM_PIPE);
        cudaFuncSetAttribute(mma_gemm2,  cudaFuncAttributeMaxDynamicSharedMemorySize, SMEM_PIPE);
        cudaFuncSetAttribute(mma_mix_ln, cudaFuncAttributeMaxDynamicSharedMemorySize, SMEM_PIPE);
        cudaFuncSetAttribute(pass_gemm,  cudaFuncAttributeMaxDynamicSharedMemorySize, SMEM_PIPE);
        attr_done = true;
    }

    float *pTmp, *pKey, *pScales;
    bf16 *pReasH, *pCatH, *pQdown, *pQup, *pWwkH, *pWwvH, *pWmixH;
    cudaGetSymbolAddress((void**)&pTmp,    g_tmp);
    cudaGetSymbolAddress((void**)&pKey,    g_key);
    cudaGetSymbolAddress((void**)&pScales, g_scales);
    cudaGetSymbolAddress((void**)&pReasH,  g_reason_h);
    cudaGetSymbolAddress((void**)&pCatH,   g_cat_h);
    cudaGetSymbolAddress((void**)&pQdown,  g_qdown);
    cudaGetSymbolAddress((void**)&pQup,    g_qup);
    cudaGetSymbolAddress((void**)&pWwkH,   g_wwk_h);
    cudaGetSymbolAddress((void**)&pWwvH,   g_wwv_h);
    cudaGetSymbolAddress((void**)&pWmixH,  g_wmix_h);

    absmean_all<<<dim3(16, 35), 256>>>(W_down, W_up, W_router, ops);
    absmean_p2<<<1, 64>>>();
    prep_all<<<3409, 256>>>(W_down, W_up, ops, W_router, W_read, W_wk, W_wv, W_mix);

    mma_down<<<128, 256, SMEM_DOWN>>>(hidden, pQdown, pScales + 0);

    for (int pass = 0; pass < DEPTH; pass++) {
        router_kernel<<<148, 128>>>();
        scatter2<<<NASSIGN/256, 256>>>();
        pass_gemm<<<384, 256, SMEM_PIPE>>>();
        combine_memread<<<148, 128>>>(slots);
        mma_mix_ln<<<M_TOK/128, 256, SMEM_PIPE>>>(pCatH, pWmixH, gamma, beta);
    }

    mma_gemm2<<<dim3(M_TOK/128, 2), 256, SMEM_PIPE>>>(pReasH, DR, pWwkH, pWwvH, DR,
        pKey, pTmp, DR, DR);
    write_kernel<<<148, 128>>>(slots, W_wg, wscale);

    mma_gemm<<<dim3(M_TOK/128, DM/128), 256, SMEM_PIPE>>>(pReasH, DR, pQup, DR,
        out, DM, DR, pScales + 1, hidden, DM);
}

// round 15
// speedup vs baseline: 4.5043x; 1.2635x over previous
#include <cuda_runtime.h>
#include <cuda_bf16.h>
#include <math.h>
#include <math_constants.h>
#include <stdint.h>

#define M_TOK 16384
#define DM    1024
#define DR    128
#define NOPS  32
#define NSLOTS 16
#define OPSZ  (DR*DR)
#define NASSIGN (M_TOK*2)
#define DEPTH 2

typedef __nv_bfloat16 bf16;

#define AS_STRIDE 72
#define TILE_BYTES (128 * AS_STRIDE * 2)   // 18432
#define STAGE_BYTES (2 * TILE_BYTES)
#define SMEM_PIPE (2 * STAGE_BYTES)        // 73728

// mma_down smem layout (BM=128, round-10 proven): Ah | Al | B0 | B1 | F0 | F1
#define F_STRIDE 68                                  // fp32 elems per row (64+4 pad)
#define FTILE_BYTES (128 * F_STRIDE * 4)             // 34816
#define DOWN_AH   0
#define DOWN_AL   TILE_BYTES
#define DOWN_B0   (2 * TILE_BYTES)
#define DOWN_B1   (3 * TILE_BYTES)
#define DOWN_F0   (4 * TILE_BYTES)
#define DOWN_F1   (4 * TILE_BYTES + FTILE_BYTES)
#define SMEM_DOWN (4 * TILE_BYTES + 2 * FTILE_BYTES) // 143360

extern __shared__ __align__(16) char smraw[];

// ======================= PTX helpers =======================================
__device__ __forceinline__ uint32_t smem_u32(const void* p) {
    uint32_t a;
    asm("{ .reg .u64 t; cvta.to.shared.u64 t, %1; cvt.u32.u64 %0, t; }" : "=r"(a) : "l"(p));
    return a;
}
__device__ __forceinline__ void ldsm_x4(uint32_t& r0, uint32_t& r1, uint32_t& r2,
                                        uint32_t& r3, uint32_t addr) {
    asm volatile("ldmatrix.sync.aligned.m8n8.x4.shared.b16 {%0,%1,%2,%3}, [%4];"
                 : "=r"(r0), "=r"(r1), "=r"(r2), "=r"(r3) : "r"(addr));
}
__device__ __forceinline__ void mma_bf16(float* d, const uint32_t* a, const uint32_t* b) {
    asm volatile(
        "mma.sync.aligned.m16n8k16.row.col.f32.bf16.bf16.f32 "
        "{%0,%1,%2,%3}, {%4,%5,%6,%7}, {%8,%9}, {%0,%1,%2,%3};"
        : "+f"(d[0]), "+f"(d[1]), "+f"(d[2]), "+f"(d[3])
        : "r"(a[0]), "r"(a[1]), "r"(a[2]), "r"(a[3]), "r"(b[0]), "r"(b[1]));
}
__device__ __forceinline__ void cp16(uint32_t smem, const void* gmem) {
    asm volatile("cp.async.cg.shared.global [%0], [%1], 16;" :: "r"(smem), "l"(gmem));
}
#define CP_COMMIT() asm volatile("cp.async.commit_group;" ::: "memory")
#define CP_WAIT1()  asm volatile("cp.async.wait_group 1;" ::: "memory")
#define CP_WAIT0()  asm volatile("cp.async.wait_group 0;" ::: "memory")

#define A_OFF(wm, lane) ((uint32_t)((((wm) * 32 + ((lane) & 15)) * AS_STRIDE + ((lane) >> 4) * 8) * 2))
#define B_OFF(wn, lane) ((uint32_t)((((wn) * 64 + (((lane) >> 4) & 1) * 8 + ((lane) & 7)) * AS_STRIDE + (((lane) >> 3) & 1) * 8) * 2))

__device__ __forceinline__ void compute_chunk(uint32_t aAddr, uint32_t bAddr,
                                              float acc[2][8][4]) {
    #pragma unroll
    for (int kk = 0; kk < 4; kk++) {
        uint32_t a[2][4], b[4][4];
        #pragma unroll
        for (int mf = 0; mf < 2; mf++)
            ldsm_x4(a[mf][0], a[mf][1], a[mf][2], a[mf][3],
                    aAddr + (uint32_t)((mf * 16 * AS_STRIDE + kk * 16) * 2));
        #pragma unroll
        for (int nfp = 0; nfp < 4; nfp++)
            ldsm_x4(b[nfp][0], b[nfp][1], b[nfp][2], b[nfp][3],
                    bAddr + (uint32_t)((nfp * 16 * AS_STRIDE + kk * 16) * 2));
        #pragma unroll
        for (int mf = 0; mf < 2; mf++)
            #pragma unroll
            for (int nf = 0; nf < 8; nf++)
                mma_bf16(acc[mf][nf], a[mf], &b[nf >> 1][(nf & 1) * 2]);
    }
}

// ======================= scratch ===========================================
__device__ float g_reason [M_TOK*DR];
__device__ float g_tmp    [M_TOK*DR];
__device__ float g_key    [M_TOK*DR];
__device__ float g_contrib[NASSIGN*DR];
__device__ bf16  g_reason_h[M_TOK*DR];
__device__ bf16  g_cat_h  [M_TOK*2*DR];
__device__ bf16  g_qdown  [DR*DM];
__device__ bf16  g_qup    [DM*DR];
__device__ bf16  g_qops   [NOPS*OPSZ];
__device__ bf16  g_wread_h[OPSZ];
__device__ bf16  g_wwk_h  [OPSZ];
__device__ bf16  g_wwv_h  [OPSZ];
__device__ bf16  g_wmix_h [DR*2*DR];
__device__ float g_WrouterE[NOPS*DR];
__device__ float g_scales [40];
__device__ float g_part   [40*16];
__device__ int   g_idx    [NASSIGN];
__device__ float g_w      [NASSIGN];
__device__ int   g_counts [NOPS];
__device__ int   g_cursor [NOPS];
__device__ int   g_perm   [NASSIGN];
__device__ int   g_pos    [NASSIGN];

// ======================= scale computation =================================
__global__ void absmean_all(const float* __restrict__ Wd, const float* __restrict__ Wu,
                            const float* __restrict__ Wr, const float* __restrict__ Wo) {
    int mat = blockIdx.y, seg = blockIdx.x;
    const float* src;
    int n;
    if (mat == 0)      { src = Wd; n = DR * DM; }
    else if (mat == 1) { src = Wu; n = DR * DM; }
    else if (mat == 2) { src = Wr; n = NOPS * DR; }
    else               { src = Wo + (size_t)(mat - 3) * OPSZ; n = OPSZ; }
    int segn = n >> 4;
    const float* p = src + (size_t)seg * segn;
    float s = 0.f;
    for (int i = threadIdx.x; i < segn; i += blockDim.x) s += fabsf(p[i]);
    __shared__ float red[8];
    int lane = threadIdx.x & 31, wid = threadIdx.x >> 5;
    #pragma unroll
    for (int o = 16; o; o >>= 1) s += __shfl_xor_sync(~0u, s, o);
    if (lane == 0) red[wid] = s;
    __syncthreads();
    if (threadIdx.x == 0) {
        float t = 0.f;
        for (int k = 0; k < (int)(blockDim.x >> 5); k++) t += red[k];
        g_part[mat * 16 + seg] = t;
    }
}
__global__ void absmean_p2() {
    int slot = threadIdx.x;
    if (slot < 35) {
        float s = 0.f;
        #pragma unroll
        for (int k = 0; k < 16; k++) s += g_part[slot * 16 + k];
        int n = (slot < 2) ? (DR * DM) : (slot == 2 ? (NOPS * DR) : OPSZ);
        g_scales[slot] = fmaxf(s / (float)n, 1e-5f);
    }
}

__device__ __forceinline__ float tern(float w, float s) {
    return fminf(1.f, fmaxf(-1.f, rintf(w / s)));
}
__global__ void prep_all(const float* __restrict__ Wd, const float* __restrict__ Wu,
                         const float* __restrict__ Wo, const float* __restrict__ Wr,
                         const float* __restrict__ Wread, const float* __restrict__ Wwk,
                         const float* __restrict__ Wwv, const float* __restrict__ Wmix) {
    int i = blockIdx.x * 256 + threadIdx.x;
    if (i < 131072) {
        g_qdown[i] = __float2bfloat16(tern(Wd[i], g_scales[0]));
    } else if (i < 262144) {
        int j = i - 131072;
        g_qup[j] = __float2bfloat16(tern(Wu[j], g_scales[1]));
    } else if (i < 786432) {
        int j = i - 262144;
        g_qops[j] = __float2bfloat16(tern(Wo[j], g_scales[3 + j / OPSZ]));
    } else if (i < 790528) {
        int j = i - 786432;
        g_WrouterE[j] = tern(Wr[j], g_scales[2]) * g_scales[2];
    } else if (i < 806912) {
        int j = i - 790528;
        g_wread_h[j] = __float2bfloat16(Wread[j]);
    } else if (i < 823296) {
        int j = i - 806912;
        g_wwk_h[j] = __float2bfloat16(Wwk[j]);
    } else if (i < 839680) {
        int j = i - 823296;
        g_wwv_h[j] = __float2bfloat16(Wwv[j]);
    } else if (i < 872448) {
        int j = i - 839680;
        g_wmix_h[j] = __float2bfloat16(Wmix[j]);
    } else if (i < 872480) {
        g_counts[i - 872448] = 0;
    } else if (i < 872512) {
        g_cursor[i - 872480] = 0;
    }
}

// ======================= down GEMM (BM=128, round-10 proven) ===============
__global__ void __launch_bounds__(256)
mma_down(const float* __restrict__ hidden, const bf16* __restrict__ B,
         const float* __restrict__ alphaPtr) {
    char* smp = smraw;
    const uint32_t sBase = smem_u32(smp);
    const int tid = threadIdx.x, lane = tid & 31, wid = tid >> 5;
    const int wm = wid & 3, wn = wid >> 2;
    const int bm = blockIdx.x * 128;

    float acc[2][8][4];
    #pragma unroll
    for (int i = 0; i < 2; i++)
        #pragma unroll
        for (int j = 0; j < 8; j++)
            #pragma unroll
            for (int k = 0; k < 4; k++) acc[i][j][k] = 0.f;

    int arow[8], aq[8];
    #pragma unroll
    for (int i = 0; i < 8; i++) {
        int slot = i * 256 + tid;
        arow[i] = slot >> 4;
        aq[i]   = slot & 15;
    }
    int brow[4], bkq[4];
    #pragma unroll
    for (int i = 0; i < 4; i++) {
        int slot = i * 256 + tid;
        brow[i] = slot >> 3;
        bkq[i]  = (slot & 7) * 8;
    }
    auto load = [&](int c, int s) {
        int k0 = c << 6;
        uint32_t dF = sBase + (s ? DOWN_F1 : DOWN_F0);
        uint32_t dB = sBase + (s ? DOWN_B1 : DOWN_B0);
        #pragma unroll
        for (int i = 0; i < 8; i++)
            cp16(dF + (uint32_t)(arow[i] * F_STRIDE + aq[i] * 4) * 4,
                 hidden + (size_t)(bm + arow[i]) * DM + k0 + aq[i] * 4);
        #pragma unroll
        for (int i = 0; i < 4; i++)
            cp16(dB + (uint32_t)(brow[i] * AS_STRIDE + bkq[i]) * 2,
                 B + (size_t)brow[i] * DM + k0 + bkq[i]);
        CP_COMMIT();
    };
    const uint32_t aOff = A_OFF(wm, lane), bOff = B_OFF(wn, lane);

    load(0, 0);
    for (int c = 0; c < 16; c++) {
        int s = c & 1;
        if (c + 1 < 16) { load(c + 1, s ^ 1); CP_WAIT1(); }
        else CP_WAIT0();
        __syncthreads();
        const float* F = (const float*)(smp + (s ? DOWN_F1 : DOWN_F0));
        #pragma unroll
        for (int i = 0; i < 8; i++) {
            float4 v = *(const float4*)(F + arow[i] * F_STRIDE + aq[i] * 4);
            bf16 h0 = __float2bfloat16(v.x), h1 = __float2bfloat16(v.y);
            bf16 h2 = __float2bfloat16(v.z), h3 = __float2bfloat16(v.w);
            int eoff = arow[i] * AS_STRIDE + aq[i] * 4;
            bf16* pH = (bf16*)(smp + DOWN_AH) + eoff;
            bf16* pL = (bf16*)(smp + DOWN_AL) + eoff;
            pH[0] = h0; pH[1] = h1; pH[2] = h2; pH[3] = h3;
            pL[0] = __float2bfloat16(v.x - __bfloat162float(h0));
            pL[1] = __float2bfloat16(v.y - __bfloat162float(h1));
            pL[2] = __float2bfloat16(v.z - __bfloat162float(h2));
            pL[3] = __float2bfloat16(v.w - __bfloat162float(h3));
        }
        __syncthreads();
        uint32_t bAddr = sBase + (s ? DOWN_B1 : DOWN_B0) + bOff;
        compute_chunk(sBase + DOWN_AH + aOff, bAddr, acc);
        compute_chunk(sBase + DOWN_AL + aOff, bAddr, acc);
    }
    __syncthreads();

    float alpha = *alphaPtr;
    const int row0 = bm + wm * 32, col0 = wn * 64;
    #pragma unroll
    for (int mf = 0; mf < 2; mf++) {
        #pragma unroll
        for (int half = 0; half < 2; half++) {
            int r = row0 + mf * 16 + (lane >> 2) + half * 8;
            #pragma unroll
            for (int nf = 0; nf < 8; nf++) {
                int c = col0 + nf * 8 + (lane & 3) * 2;
                float vx = alpha * acc[mf][nf][half * 2];
                float vy = alpha * acc[mf][nf][half * 2 + 1];
                float* cp = g_reason + (size_t)r * DR + c;
                cp[0] = vx; cp[1] = vy;
                size_t o = (size_t)r * DR + c;
                g_reason_h[o]     = __float2bfloat16(vx);
                g_reason_h[o + 1] = __float2bfloat16(vy);
            }
        }
    }
}

// ======================= generic pipelined HMMA GEMM (up) ==================
__global__ void __launch_bounds__(256)
mma_gemm(const bf16* __restrict__ Ah, int lda,
         const bf16* __restrict__ Bh, int ldb,
         float* __restrict__ C, int ldc, int K,
         const float* __restrict__ alphaPtr,
         const float* __restrict__ res, int ldr)
{
    char* smp = smraw;
    const uint32_t sBase = smem_u32(smp);
    const int tid = threadIdx.x, lane = tid & 31, wid = tid >> 5;
    const int wm = wid & 3, wn = wid >> 2;
    const int bm = blockIdx.x * 128, bn = blockIdx.y * 128;
    const int nk = K >> 6;

    float acc[2][8][4];
    #pragma unroll
    for (int i = 0; i < 2; i++)
        #pragma unroll
        for (int j = 0; j < 8; j++)
            #pragma unroll
            for (int k = 0; k < 4; k++) acc[i][j][k] = 0.f;

    int srow[4], skq[4];
    #pragma unroll
    for (int i = 0; i < 4; i++) {
        int slot = i * 256 + tid;
        srow[i] = slot >> 3;
        skq[i]  = (slot & 7) * 8;
    }
    auto load = [&](int c, int s) {
        int k0 = c << 6;
        const bf16* A = Ah + (size_t)bm * lda + k0;
        const bf16* B = Bh + (size_t)bn * ldb + k0;
        uint32_t dA = sBase + s * STAGE_BYTES;
        uint32_t dB = dA + TILE_BYTES;
        #pragma unroll
        for (int i = 0; i < 4; i++) {
            uint32_t off = (uint32_t)(srow[i] * AS_STRIDE + skq[i]) * 2;
            cp16(dA + off, A + (size_t)srow[i] * lda + skq[i]);
            cp16(dB + off, B + (size_t)srow[i] * ldb + skq[i]);
        }
        CP_COMMIT();
    };
    const uint32_t aOff = A_OFF(wm, lane), bOff = B_OFF(wn, lane);

    load(0, 0);
    for (int c = 0; c < nk; c++) {
        int s = c & 1;
        if (c + 1 < nk) { load(c + 1, (c + 1) & 1); CP_WAIT1(); }
        else CP_WAIT0();
        __syncthreads();
        compute_chunk(sBase + s * STAGE_BYTES + aOff,
                      sBase + s * STAGE_BYTES + TILE_BYTES + bOff, acc);
        __syncthreads();
    }

    float alpha = alphaPtr ? *alphaPtr : 1.0f;
    const int row0 = bm + wm * 32, col0 = bn + wn * 64;
    #pragma unroll
    for (int mf = 0; mf < 2; mf++) {
        #pragma unroll
        for (int half = 0; half < 2; half++) {
            int r = row0 + mf * 16 + (lane >> 2) + half * 8;
            #pragma unroll
            for (int nf = 0; nf < 8; nf++) {
                int c = col0 + nf * 8 + (lane & 3) * 2;
                float vx = alpha * acc[mf][nf][half * 2];
                float vy = alpha * acc[mf][nf][half * 2 + 1];
                if (res) {
                    const float* rp = res + (size_t)r * ldr + c;
                    vx += rp[0]; vy += rp[1];
                }
                float* cp = C + (size_t)r * ldc + c;
                cp[0] = vx; cp[1] = vy;
            }
        }
    }
}

// Dual-B 1-term: blockIdx.y selects {B0->C0} or {B1->C1}
__global__ void __launch_bounds__(256)
mma_gemm2(const bf16* __restrict__ A, int lda,
          const bf16* __restrict__ B0, const bf16* __restrict__ B1, int ldb,
          float* __restrict__ C0, float* __restrict__ C1, int ldc, int K)
{
    char* smp = smraw;
    const uint32_t sBase = smem_u32(smp);
    const int tid = threadIdx.x, lane = tid & 31, wid = tid >> 5;
    const int wm = wid & 3, wn = wid >> 2;
    const int bm = blockIdx.x * 128;
    const bf16* B = blockIdx.y ? B1 : B0;
    float* C = blockIdx.y ? C1 : C0;
    const int nk = K >> 6;

    float acc[2][8][4];
    #pragma unroll
    for (int i = 0; i < 2; i++)
        #pragma unroll
        for (int j = 0; j < 8; j++)
            #pragma unroll
            for (int k = 0; k < 4; k++) acc[i][j][k] = 0.f;

    int srow[4], skq[4];
    #pragma unroll
    for (int i = 0; i < 4; i++) {
        int slot = i * 256 + tid;
        srow[i] = slot >> 3;
        skq[i]  = (slot & 7) * 8;
    }
    auto load = [&](int c, int s) {
        int k0 = c << 6;
        const bf16* Ap = A + (size_t)bm * lda + k0;
        const bf16* Bp = B + k0;
        uint32_t dA = sBase + s * STAGE_BYTES;
        uint32_t dB = dA + TILE_BYTES;
        #pragma unroll
        for (int i = 0; i < 4; i++) {
            uint32_t off = (uint32_t)(srow[i] * AS_STRIDE + skq[i]) * 2;
            cp16(dA + off, Ap + (size_t)srow[i] * lda + skq[i]);
            cp16(dB + off, Bp + (size_t)srow[i] * ldb + skq[i]);
        }
        CP_COMMIT();
    };
    const uint32_t aOff = A_OFF(wm, lane), bOff = B_OFF(wn, lane);

    load(0, 0);
    for (int c = 0; c < nk; c++) {
        int s = c & 1;
        if (c + 1 < nk) { load(c + 1, (c + 1) & 1); CP_WAIT1(); }
        else CP_WAIT0();
        __syncthreads();
        compute_chunk(sBase + s * STAGE_BYTES + aOff,
                      sBase + s * STAGE_BYTES + TILE_BYTES + bOff, acc);
        __syncthreads();
    }
    const int row0 = bm + wm * 32, col0 = wn * 64;
    #pragma unroll
    for (int mf = 0; mf < 2; mf++) {
        #pragma unroll
        for (int half = 0; half < 2; half++) {
            int r = row0 + mf * 16 + (lane >> 2) + half * 8;
            #pragma unroll
            for (int nf = 0; nf < 8; nf++) {
                int c = col0 + nf * 8 + (lane & 3) * 2;
                float* cp = C + (size_t)r * ldc + c;
                cp[0] = acc[mf][nf][half * 2];
                cp[1] = acc[mf][nf][half * 2 + 1];
            }
        }
    }
}

// ======================= unified expert + key launch =======================
__global__ void __launch_bounds__(256)
pass_gemm() {
    char* smp = smraw;
    __shared__ int rowid[128];
    const uint32_t sBase = smem_u32(smp);
    const int tid = threadIdx.x, lane = tid & 31, wid = tid >> 5;
    const int wm = wid & 3, wn = wid >> 2;
    const int b = blockIdx.x;

    int srow[4], skq[4];
    #pragma unroll
    for (int i = 0; i < 4; i++) {
        int slot = i * 256 + tid;
        srow[i] = slot >> 3;
        skq[i]  = (slot & 7) * 8;
    }
    const uint32_t aOff = A_OFF(wm, lane), bOff = B_OFF(wn, lane);

    if (b >= 256) {
        // ---- key = reason_h @ wread^T ----
        const int bm = (b - 256) * 128;
        float acc[2][8][4];
        #pragma unroll
        for (int i = 0; i < 2; i++)
            #pragma unroll
            for (int j = 0; j < 8; j++)
                #pragma unroll
                for (int k = 0; k < 4; k++) acc[i][j][k] = 0.f;
        auto load = [&](int c, int s) {
            int k0 = c << 6;
            uint32_t dA = sBase + s * STAGE_BYTES;
            uint32_t dB = dA + TILE_BYTES;
            #pragma unroll
            for (int i = 0; i < 4; i++) {
                uint32_t off = (uint32_t)(srow[i] * AS_STRIDE + skq[i]) * 2;
                cp16(dA + off, g_reason_h + (size_t)(bm + srow[i]) * DR + k0 + skq[i]);
                cp16(dB + off, g_wread_h + (size_t)srow[i] * DR + k0 + skq[i]);
            }
            CP_COMMIT();
        };
        load(0, 0);
        #pragma unroll
        for (int c = 0; c < 2; c++) {
            int s = c & 1;
            if (c < 1) { load(1, 1); CP_WAIT1(); }
            else CP_WAIT0();
            __syncthreads();
            compute_chunk(sBase + s * STAGE_BYTES + aOff,
                          sBase + s * STAGE_BYTES + TILE_BYTES + bOff, acc);
            __syncthreads();
        }
        const int row0 = bm + wm * 32, col0 = wn * 64;
        #pragma unroll
        for (int mf = 0; mf < 2; mf++) {
            #pragma unroll
            for (int half = 0; half < 2; half++) {
                int r = row0 + mf * 16 + (lane >> 2) + half * 8;
                #pragma unroll
                for (int nf = 0; nf < 8; nf++) {
                    int c = col0 + nf * 8 + (lane & 3) * 2;
                    float* cp = g_key + (size_t)r * DR + c;
                    cp[0] = acc[mf][nf][half * 2];
                    cp[1] = acc[mf][nf][half * 2 + 1];
                }
            }
        }
        return;
    }

    // ---- expert path ----
    const int op = b >> 3;
    int start = 0;
    #pragma unroll
    for (int k = 0; k < NOPS; k++) if (k < op) start += g_counts[k];
    const int cnt = g_counts[op];
    const float alpha = g_scales[3 + op];
    const bf16* B0 = g_qops + (size_t)op * OPSZ;

    auto load = [&](int c, int s) {
        int k0 = c << 6;
        uint32_t dA = sBase + s * STAGE_BYTES;
        uint32_t dB = dA + TILE_BYTES;
        #pragma unroll
        for (int i = 0; i < 4; i++) {
            int grow = rowid[srow[i]];
            if (grow < 0) grow = 0;
            uint32_t off = (uint32_t)(srow[i] * AS_STRIDE + skq[i]) * 2;
            cp16(dA + off, g_reason_h + (size_t)grow * DR + k0 + skq[i]);
            cp16(dB + off, B0 + (size_t)srow[i] * DR + k0 + skq[i]);
        }
        CP_COMMIT();
    };

    for (int t0 = (b & 7) * 128; t0 < cnt; t0 += 8 * 128) {
        __syncthreads();
        if (tid < 128) rowid[tid] = (t0 + tid < cnt) ? g_perm[start + t0 + tid] : -1;
        __syncthreads();
        float acc[2][8][4];
        #pragma unroll
        for (int i = 0; i < 2; i++)
            #pragma unroll
            for (int j = 0; j < 8; j++)
                #pragma unroll
                for (int k = 0; k < 4; k++) acc[i][j][k] = 0.f;

        load(0, 0);
        #pragma unroll
        for (int c = 0; c < 2; c++) {
            int s = c & 1;
            if (c < 1) { load(1, 1); CP_WAIT1(); }
            else CP_WAIT0();
            __syncthreads();
            compute_chunk(sBase + s * STAGE_BYTES + aOff,
                          sBase + s * STAGE_BYTES + TILE_BYTES + bOff, acc);
            __syncthreads();
        }
        const int row0 = wm * 32, col0 = wn * 64;
        #pragma unroll
        for (int mf = 0; mf < 2; mf++) {
            #pragma unroll
            for (int half = 0; half < 2; half++) {
                int rl = row0 + mf * 16 + (lane >> 2) + half * 8;
                if (t0 + rl < cnt) {
                    float* cp0 = g_contrib + (size_t)(start + t0 + rl) * DR;
                    #pragma unroll
                    for (int nf = 0; nf < 8; nf++) {
                        int c = col0 + nf * 8 + (lane & 3) * 2;
                        cp0[c]     = alpha * acc[mf][nf][half * 2];
                        cp0[c + 1] = alpha * acc[mf][nf][half * 2 + 1];
                    }
                }
            }
        }
    }
}

// ======================= mix GEMM + fused LayerNorm (+ counter reset) ======
__global__ void __launch_bounds__(256)
mma_mix_ln(const bf16* __restrict__ A, const bf16* __restrict__ B,
           const float* __restrict__ gamma, const float* __restrict__ beta)
{
    char* smp = smraw;
    const uint32_t sBase = smem_u32(smp);
    float* tmpsm = (float*)smp;
    __shared__ float musm[128], rssm[128];
    const int tid = threadIdx.x, lane = tid & 31, wid = tid >> 5;
    const int wm = wid & 3, wn = wid >> 2;
    const int bm = blockIdx.x * 128;
    const int nk = 4;

    float acc[2][8][4];
    #pragma unroll
    for (int i = 0; i < 2; i++)
        #pragma unroll
        for (int j = 0; j < 8; j++)
            #pragma unroll
            for (int k = 0; k < 4; k++) acc[i][j][k] = 0.f;

    int srow[4], skq[4];
    #pragma unroll
    for (int i = 0; i < 4; i++) {
        int slot = i * 256 + tid;
        srow[i] = slot >> 3;
        skq[i]  = (slot & 7) * 8;
    }
    auto load = [&](int c, int s) {
        int k0 = c << 6;
        const bf16* Ap = A + (size_t)bm * 256 + k0;
        const bf16* Bp = B + k0;
        uint32_t dA = sBase + s * STAGE_BYTES;
        uint32_t dB = dA + TILE_BYTES;
        #pragma unroll
        for (int i = 0; i < 4; i++) {
            uint32_t off = (uint32_t)(srow[i] * AS_STRIDE + skq[i]) * 2;
            cp16(dA + off, Ap + (size_t)srow[i] * 256 + skq[i]);
            cp16(dB + off, Bp + (size_t)srow[i] * 256 + skq[i]);
        }
        CP_COMMIT();
    };
    const uint32_t aOff = A_OFF(wm, lane), bOff = B_OFF(wn, lane);

    load(0, 0);
    for (int c = 0; c < nk; c++) {
        int s = c & 1;
        if (c + 1 < nk) { load(c + 1, (c + 1) & 1); CP_WAIT1(); }
        else CP_WAIT0();
        __syncthreads();
        compute_chunk(sBase + s * STAGE_BYTES + aOff,
                      sBase + s * STAGE_BYTES + TILE_BYTES + bOff, acc);
        __syncthreads();
    }

    const int row0 = wm * 32, col0 = wn * 64;
    #pragma unroll
    for (int mf = 0; mf < 2; mf++) {
        #pragma unroll
        for (int half = 0; half < 2; half++) {
            int r = row0 + mf * 16 + (lane >> 2) + half * 8;
            #pragma unroll
            for (int nf = 0; nf < 8; nf++) {
                int c = col0 + nf * 8 + (lane & 3) * 2;
                const float* rp = g_reason + (size_t)(bm + r) * DR + c;
                tmpsm[r * 129 + c]     = acc[mf][nf][half * 2]     + rp[0];
                tmpsm[r * 129 + c + 1] = acc[mf][nf][half * 2 + 1] + rp[1];
            }
        }
    }
    __syncthreads();
    if (tid < 128) {
        float mu = 0.f, sq = 0.f;
        #pragma unroll 8
        for (int k = 0; k < 128; k++) {
            float v = tmpsm[tid * 129 + k];
            mu += v; sq += v * v;
        }
        mu *= (1.f / 128.f);
        float var = sq * (1.f / 128.f) - mu * mu;
        musm[tid] = mu;
        rssm[tid] = rsqrtf(var + 1e-5f);
    }
    __syncthreads();
    for (int idx = tid; idx < 128 * 32; idx += 256) {
        int r = idx >> 5, c = (idx & 31) * 4;
        float mu = musm[r], rs = rssm[r];
        float o0 = (tmpsm[r * 129 + c]     - mu) * rs * gamma[c]     + beta[c];
        float o1 = (tmpsm[r * 129 + c + 1] - mu) * rs * gamma[c + 1] + beta[c + 1];
        float o2 = (tmpsm[r * 129 + c + 2] - mu) * rs * gamma[c + 2] + beta[c + 2];
        float o3 = (tmpsm[r * 129 + c + 3] - mu) * rs * gamma[c + 3] + beta[c + 3];
        size_t o = (size_t)(bm + r) * DR + c;
        *(float4*)(g_reason + o) = make_float4(o0, o1, o2, o3);
        g_reason_h[o]     = __float2bfloat16(o0);
        g_reason_h[o + 1] = __float2bfloat16(o1);
        g_reason_h[o + 2] = __float2bfloat16(o2);
        g_reason_h[o + 3] = __float2bfloat16(o3);
    }
    if (blockIdx.x == 0 && tid < NOPS) { g_counts[tid] = 0; g_cursor[tid] = 0; }
}

// ======================= router / bookkeeping ==============================
__global__ void __launch_bounds__(128)
router_kernel() {
    __shared__ float Wsm[NOPS][DR + 1];
    __shared__ float rsm[4][DR];
    int tid = threadIdx.x;
    for (int i = tid; i < NOPS * DR; i += 128) Wsm[i >> 7][i & 127] = g_WrouterE[i];
    __syncthreads();
    int warp = tid >> 5, lane = tid & 31;
    for (int t = blockIdx.x * 4 + warp; t < M_TOK; t += gridDim.x * 4) {
        float4 v = ((const float4*)(g_reason + (size_t)t * DR))[lane];
        ((float4*)rsm[warp])[lane] = v;
        __syncwarp();
        float logit = 0.f;
        #pragma unroll 8
        for (int k = 0; k < DR; k++) logit += rsm[warp][k] * Wsm[lane][k];
        float m1 = logit; int i1 = lane;
        #pragma unroll
        for (int o = 16; o; o >>= 1) {
            float om = __shfl_xor_sync(~0u, m1, o);
            int   oi = __shfl_xor_sync(~0u, i1, o);
            if (om > m1 || (om == m1 && oi < i1)) { m1 = om; i1 = oi; }
        }
        float l2 = (lane == i1) ? -CUDART_INF_F : logit;
        float m2 = l2; int i2 = lane;
        #pragma unroll
        for (int o = 16; o; o >>= 1) {
            float om = __shfl_xor_sync(~0u, m2, o);
            int   oi = __shfl_xor_sync(~0u, i2, o);
            if (om > m2 || (om == m2 && oi < i2)) { m2 = om; i2 = oi; }
        }
        if (lane == 0) {
            float e = expf(m2 - m1);
            g_idx[2*t]   = i1; g_idx[2*t+1] = i2;
            g_w[2*t]     = 1.f / (1.f + e);
            g_w[2*t+1]   = e / (1.f + e);
            atomicAdd(&g_counts[i1], 1);
            atomicAdd(&g_counts[i2], 1);
        }
        __syncwarp();
    }
}
__global__ void scatter2() {
    int i = blockIdx.x * blockDim.x + threadIdx.x;
    if (i < NASSIGN) {
        int op = g_idx[i];
        int base = 0;
        for (int k = 0; k < op; k++) base += g_counts[k];
        int p = base + atomicAdd(&g_cursor[op], 1);
        g_perm[p] = i >> 1;
        g_pos[i]  = p;
    }
}

__global__ void __launch_bounds__(128)
combine_memread(const float* __restrict__ slots) {
    __shared__ float ssm[NSLOTS][DR + 1];
    __shared__ float rsm[4][DR];
    __shared__ float attn_s[4][NSLOTS];
    int tid = threadIdx.x;
    for (int i = tid; i < NSLOTS * DR; i += 128) ssm[i >> 7][i & 127] = slots[i];
    __syncthreads();
    int warp = tid >> 5, lane = tid & 31;
    const float inv_sqrt_d = 0.08838834764831845f;
    for (int t = blockIdx.x * 4 + warp; t < M_TOK; t += gridDim.x * 4) {
        int p0 = g_pos[2*t], p1 = g_pos[2*t+1];
        float w0 = g_w[2*t], w1 = g_w[2*t+1];
        float4 c0 = ((const float4*)(g_contrib + (size_t)p0 * DR))[lane];
        float4 c1 = ((const float4*)(g_contrib + (size_t)p1 * DR))[lane];
        size_t ob = (size_t)t * 256 + lane * 4;
        g_cat_h[ob]     = __float2bfloat16(w0 * c0.x + w1 * c1.x);
        g_cat_h[ob + 1] = __float2bfloat16(w0 * c0.y + w1 * c1.y);
        g_cat_h[ob + 2] = __float2bfloat16(w0 * c0.z + w1 * c1.z);
        g_cat_h[ob + 3] = __float2bfloat16(w0 * c0.w + w1 * c1.w);
        float4 v = ((const float4*)(g_key + (size_t)t * DR))[lane];
        ((float4*)rsm[warp])[lane] = v;
        __syncwarp();
        float logit = -CUDART_INF_F;
        if (lane < NSLOTS) {
            float s = 0.f;
            #pragma unroll 8
            for (int k = 0; k < DR; k++) s += rsm[warp][k] * ssm[lane][k];
            logit = s * inv_sqrt_d;
        }
        float mx = logit;
        #pragma unroll
        for (int o = 16; o; o >>= 1) mx = fmaxf(mx, __shfl_xor_sync(~0u, mx, o));
        float e = (lane < NSLOTS) ? expf(logit - mx) : 0.f;
        float se = e;
        #pragma unroll
        for (int o = 16; o; o >>= 1) se += __shfl_xor_sync(~0u, se, o);
        if (lane < NSLOTS) attn_s[warp][lane] = e / se;
        __syncwarp();
        float ov[4] = {0.f, 0.f, 0.f, 0.f};
        #pragma unroll
        for (int s2 = 0; s2 < NSLOTS; s2++) {
            float a = attn_s[warp][s2];
            ov[0] += a * ssm[s2][lane*4+0];
            ov[1] += a * ssm[s2][lane*4+1];
            ov[2] += a * ssm[s2][lane*4+2];
            ov[3] += a * ssm[s2][lane*4+3];
        }
        g_cat_h[ob + 128] = __float2bfloat16(ov[0]);
        g_cat_h[ob + 129] = __float2bfloat16(ov[1]);
        g_cat_h[ob + 130] = __float2bfloat16(ov[2]);
        g_cat_h[ob + 131] = __float2bfloat16(ov[3]);
        __syncwarp();
    }
}

__global__ void __launch_bounds__(128)
write_kernel(const float* __restrict__ slots, const float* __restrict__ Wg,
             const float* __restrict__ wsp) {
    __shared__ float ssm[NSLOTS][DR + 1];
    __shared__ float wgs[DR];
    __shared__ float rsm[4][DR];
    __shared__ float attn_s[4][NSLOTS];
    int tid = threadIdx.x;
    for (int i = tid; i < NSLOTS * DR; i += 128) ssm[i >> 7][i & 127] = slots[i];
    wgs[tid] = Wg[tid];
    __syncthreads();
    int warp = tid >> 5, lane = tid & 31;
    float ws = *wsp;
    const float inv_sqrt_d = 0.08838834764831845f;
    for (int t = blockIdx.x * 4 + warp; t < M_TOK; t += gridDim.x * 4) {
        float4 r = ((const float4*)(g_reason + (size_t)t * DR))[lane];
        float4 wg4 = ((const float4*)wgs)[lane];
        float gd = r.x*wg4.x + r.y*wg4.y + r.z*wg4.z + r.w*wg4.w;
        #pragma unroll
        for (int o = 16; o; o >>= 1) gd += __shfl_xor_sync(~0u, gd, o);
        float wg = 1.f / (1.f + expf(-gd));
        float4 k4 = ((const float4*)(g_key + (size_t)t * DR))[lane];
        ((float4*)rsm[warp])[lane] = k4;
        __syncwarp();
        float logit = -CUDART_INF_F;
        if (lane < NSLOTS) {
            float sdot = 0.f;
            #pragma unroll 8
            for (int k = 0; k < DR; k++) sdot += rsm[warp][k] * ssm[lane][k];
            logit = sdot * inv_sqrt_d;
        }
        float mx = logit;
        #pragma unroll
        for (int o = 16; o; o >>= 1) mx = fmaxf(mx, __shfl_xor_sync(~0u, mx, o));
        float e = (lane < NSLOTS) ? expf(logit - mx) : 0.f;
        float se = e;
        #pragma unroll
        for (int o = 16; o; o >>= 1) se += __shfl_xor_sync(~0u, se, o);
        if (lane < NSLOTS) attn_s[warp][lane] = e / se;
        __syncwarp();
        float4 wv = ((const float4*)(g_tmp + (size_t)t * DR))[lane];
        float ov[4];
        ov[0] = wg * wv.x; ov[1] = wg * wv.y; ov[2] = wg * wv.z; ov[3] = wg * wv.w;
        #pragma unroll
        for (int s2 = 0; s2 < NSLOTS; s2++) {
            float a = 0.1f * attn_s[warp][s2];
            ov[0] += a * ssm[s2][lane*4+0];
            ov[1] += a * ssm[s2][lane*4+1];
            ov[2] += a * ssm[s2][lane*4+2];
            ov[3] += a * ssm[s2][lane*4+3];
        }
        float o4[4];
        o4[0] = r.x + ws * ov[0]; o4[1] = r.y + ws * ov[1];
        o4[2] = r.z + ws * ov[2]; o4[3] = r.w + ws * ov[3];
        size_t o = (size_t)t * DR + lane * 4;
        *(float4*)(g_reason + o) = make_float4(o4[0], o4[1], o4[2], o4[3]);
        g_reason_h[o]     = __float2bfloat16(o4[0]);
        g_reason_h[o + 1] = __float2bfloat16(o4[1]);
        g_reason_h[o + 2] = __float2bfloat16(o4[2]);
        g_reason_h[o + 3] = __float2bfloat16(o4[3]);
        __syncwarp();
    }
}

// ======================= launch ============================================
extern "C" void kernel_launch(void* const* d_in, const int* in_sizes, int n_in,
                              void* d_out, int out_size) {
    const float* hidden   = (const float*)d_in[0];
    const float* W_down   = (const float*)d_in[2];
    const float* W_up     = (const float*)d_in[3];
    const float* ops      = (const float*)d_in[4];
    const float* W_router = (const float*)d_in[5];
    const float* slots    = (const float*)d_in[6];
    const float* W_read   = (const float*)d_in[7];
    const float* W_wk     = (const float*)d_in[8];
    const float* W_wg     = (const float*)d_in[9];
    const float* W_wv     = (const float*)d_in[10];
    const float* W_mix    = (const float*)d_in[11];
    const float* gamma    = (const float*)d_in[12];
    const float* beta     = (const float*)d_in[13];
    const float* wscale   = (const float*)d_in[14];
    float* out = (float*)d_out;

    static bool attr_done = false;
    if (!attr_done) {
        cudaFuncSetAttribute(mma_down,   cudaFuncAttributeMaxDynamicSharedMemorySize, SMEM_DOWN);
        cudaFuncSetAttribute(mma_gemm,   cudaFuncAttributeMaxDynamicSharedMemorySize, SMEM_PIPE);
        cudaFuncSetAttribute(mma_gemm2,  cudaFuncAttributeMaxDynamicSharedMemorySize, SMEM_PIPE);
        cudaFuncSetAttribute(mma_mix_ln, cudaFuncAttributeMaxDynamicSharedMemorySize, SMEM_PIPE);
        cudaFuncSetAttribute(pass_gemm,  cudaFuncAttributeMaxDynamicSharedMemorySize, SMEM_PIPE);
        attr_done = true;
    }

    float *pTmp, *pKey, *pScales;
    bf16 *pReasH, *pCatH, *pQdown, *pQup, *pWwkH, *pWwvH, *pWmixH;
    cudaGetSymbolAddress((void**)&pTmp,    g_tmp);
    cudaGetSymbolAddress((void**)&pKey,    g_key);
    cudaGetSymbolAddress((void**)&pScales, g_scales);
    cudaGetSymbolAddress((void**)&pReasH,  g_reason_h);
    cudaGetSymbolAddress((void**)&pCatH,   g_cat_h);
    cudaGetSymbolAddress((void**)&pQdown,  g_qdown);
    cudaGetSymbolAddress((void**)&pQup,    g_qup);
    cudaGetSymbolAddress((void**)&pWwkH,   g_wwk_h);
    cudaGetSymbolAddress((void**)&pWwvH,   g_wwv_h);
    cudaGetSymbolAddress((void**)&pWmixH,  g_wmix_h);

    absmean_all<<<dim3(16, 35), 256>>>(W_down, W_up, W_router, ops);
    absmean_p2<<<1, 64>>>();
    prep_all<<<3409, 256>>>(W_down, W_up, ops, W_router, W_read, W_wk, W_wv, W_mix);

    mma_down<<<128, 256, SMEM_DOWN>>>(hidden, pQdown, pScales + 0);

    for (int pass = 0; pass < DEPTH; pass++) {
        router_kernel<<<296, 128>>>();
        scatter2<<<NASSIGN/256, 256>>>();
        pass_gemm<<<384, 256, SMEM_PIPE>>>();
        combine_memread<<<296, 128>>>(slots);
        mma_mix_ln<<<M_TOK/128, 256, SMEM_PIPE>>>(pCatH, pWmixH, gamma, beta);
    }

    mma_gemm2<<<dim3(M_TOK/128, 2), 256, SMEM_PIPE>>>(pReasH, DR, pWwkH, pWwvH, DR,
        pKey, pTmp, DR, DR);
    write_kernel<<<296, 128>>>(slots, W_wg, wscale);

    mma_gemm<<<dim3(M_TOK/128, DM/128), 256, SMEM_PIPE>>>(pReasH, DR, pQup, DR,
        out, DM, DR, pScales + 1, hidden, DM);
}

// round 17
// speedup vs baseline: 4.8212x; 1.0704x over previous
#include <cuda_runtime.h>
#include <cuda_bf16.h>
#include <math.h>
#include <math_constants.h>
#include <stdint.h>

#define M_TOK 16384
#define DM    1024
#define DR    128
#define NOPS  32
#define NSLOTS 16
#define OPSZ  (DR*DR)
#define NASSIGN (M_TOK*2)
#define DEPTH 2

typedef __nv_bfloat16 bf16;

#define AS_STRIDE 72
#define TILE_BYTES (128 * AS_STRIDE * 2)   // 18432
#define STAGE_BYTES (2 * TILE_BYTES)
#define SMEM_PIPE (2 * STAGE_BYTES)        // 73728

// mma_down smem (BM=128, 3-stage): AH | AL | B0 B1 B2 | F0 F1 F2
#define F_STRIDE 68
#define FTILE_BYTES (128 * F_STRIDE * 4)             // 34816
#define DOWN_AH   0
#define DOWN_AL   TILE_BYTES
#define DOWN_B(i) (2 * TILE_BYTES + (i) * TILE_BYTES)
#define DOWN_F(i) (5 * TILE_BYTES + (i) * FTILE_BYTES)
#define SMEM_DOWN (5 * TILE_BYTES + 3 * FTILE_BYTES) // 196608

extern __shared__ __align__(16) char smraw[];

// ======================= PTX helpers =======================================
__device__ __forceinline__ uint32_t smem_u32(const void* p) {
    uint32_t a;
    asm("{ .reg .u64 t; cvta.to.shared.u64 t, %1; cvt.u32.u64 %0, t; }" : "=r"(a) : "l"(p));
    return a;
}
__device__ __forceinline__ void ldsm_x4(uint32_t& r0, uint32_t& r1, uint32_t& r2,
                                        uint32_t& r3, uint32_t addr) {
    asm volatile("ldmatrix.sync.aligned.m8n8.x4.shared.b16 {%0,%1,%2,%3}, [%4];"
                 : "=r"(r0), "=r"(r1), "=r"(r2), "=r"(r3) : "r"(addr));
}
__device__ __forceinline__ void mma_bf16(float* d, const uint32_t* a, const uint32_t* b) {
    asm volatile(
        "mma.sync.aligned.m16n8k16.row.col.f32.bf16.bf16.f32 "
        "{%0,%1,%2,%3}, {%4,%5,%6,%7}, {%8,%9}, {%0,%1,%2,%3};"
        : "+f"(d[0]), "+f"(d[1]), "+f"(d[2]), "+f"(d[3])
        : "r"(a[0]), "r"(a[1]), "r"(a[2]), "r"(a[3]), "r"(b[0]), "r"(b[1]));
}
__device__ __forceinline__ void cp16(uint32_t smem, const void* gmem) {
    asm volatile("cp.async.cg.shared.global [%0], [%1], 16;" :: "r"(smem), "l"(gmem));
}
#define CP_COMMIT() asm volatile("cp.async.commit_group;" ::: "memory")
#define CP_WAIT2()  asm volatile("cp.async.wait_group 2;" ::: "memory")
#define CP_WAIT1()  asm volatile("cp.async.wait_group 1;" ::: "memory")
#define CP_WAIT0()  asm volatile("cp.async.wait_group 0;" ::: "memory")

#define A_OFF(wm, lane) ((uint32_t)((((wm) * 32 + ((lane) & 15)) * AS_STRIDE + ((lane) >> 4) * 8) * 2))
#define B_OFF(wn, lane) ((uint32_t)((((wn) * 64 + (((lane) >> 4) & 1) * 8 + ((lane) & 7)) * AS_STRIDE + (((lane) >> 3) & 1) * 8) * 2))

__device__ __forceinline__ void compute_chunk(uint32_t aAddr, uint32_t bAddr,
                                              float acc[2][8][4]) {
    #pragma unroll
    for (int kk = 0; kk < 4; kk++) {
        uint32_t a[2][4], b[4][4];
        #pragma unroll
        for (int mf = 0; mf < 2; mf++)
            ldsm_x4(a[mf][0], a[mf][1], a[mf][2], a[mf][3],
                    aAddr + (uint32_t)((mf * 16 * AS_STRIDE + kk * 16) * 2));
        #pragma unroll
        for (int nfp = 0; nfp < 4; nfp++)
            ldsm_x4(b[nfp][0], b[nfp][1], b[nfp][2], b[nfp][3],
                    bAddr + (uint32_t)((nfp * 16 * AS_STRIDE + kk * 16) * 2));
        #pragma unroll
        for (int mf = 0; mf < 2; mf++)
            #pragma unroll
            for (int nf = 0; nf < 8; nf++)
                mma_bf16(acc[mf][nf], a[mf], &b[nf >> 1][(nf & 1) * 2]);
    }
}

// ======================= scratch ===========================================
__device__ float g_reason [M_TOK*DR];
__device__ float g_tmp    [M_TOK*DR];
__device__ float g_key    [M_TOK*DR];
__device__ float g_contrib[NASSIGN*DR];
__device__ bf16  g_reason_h[M_TOK*DR];
__device__ bf16  g_cat_h  [M_TOK*2*DR];
__device__ bf16  g_qdown  [DR*DM];
__device__ bf16  g_qup    [DM*DR];
__device__ bf16  g_qops   [NOPS*OPSZ];
__device__ bf16  g_wread_h[OPSZ];
__device__ bf16  g_wwk_h  [OPSZ];
__device__ bf16  g_wwv_h  [OPSZ];
__device__ bf16  g_wmix_h [DR*2*DR];
__device__ float g_WrouterE[NOPS*DR];
__device__ float g_scales [40];
__device__ float g_part   [40*16];
__device__ int   g_idx    [NASSIGN];
__device__ float g_w      [NASSIGN];
__device__ int   g_counts [NOPS];
__device__ int   g_cursor [NOPS];
__device__ int   g_perm   [NASSIGN];
__device__ int   g_pos    [NASSIGN];

// ======================= scale computation =================================
__global__ void absmean_all(const float* __restrict__ Wd, const float* __restrict__ Wu,
                            const float* __restrict__ Wr, const float* __restrict__ Wo) {
    int mat = blockIdx.y, seg = blockIdx.x;
    const float* src;
    int n;
    if (mat == 0)      { src = Wd; n = DR * DM; }
    else if (mat == 1) { src = Wu; n = DR * DM; }
    else if (mat == 2) { src = Wr; n = NOPS * DR; }
    else               { src = Wo + (size_t)(mat - 3) * OPSZ; n = OPSZ; }
    int segn = n >> 4;
    const float* p = src + (size_t)seg * segn;
    float s = 0.f;
    for (int i = threadIdx.x; i < segn; i += blockDim.x) s += fabsf(p[i]);
    __shared__ float red[8];
    int lane = threadIdx.x & 31, wid = threadIdx.x >> 5;
    #pragma unroll
    for (int o = 16; o; o >>= 1) s += __shfl_xor_sync(~0u, s, o);
    if (lane == 0) red[wid] = s;
    __syncthreads();
    if (threadIdx.x == 0) {
        float t = 0.f;
        for (int k = 0; k < (int)(blockDim.x >> 5); k++) t += red[k];
        g_part[mat * 16 + seg] = t;
    }
}
__global__ void absmean_p2() {
    int slot = threadIdx.x;
    if (slot < 35) {
        float s = 0.f;
        #pragma unroll
        for (int k = 0; k < 16; k++) s += g_part[slot * 16 + k];
        int n = (slot < 2) ? (DR * DM) : (slot == 2 ? (NOPS * DR) : OPSZ);
        g_scales[slot] = fmaxf(s / (float)n, 1e-5f);
    }
}

__device__ __forceinline__ float tern(float w, float s) {
    return fminf(1.f, fmaxf(-1.f, rintf(w / s)));
}
__global__ void prep_all(const float* __restrict__ Wd, const float* __restrict__ Wu,
                         const float* __restrict__ Wo, const float* __restrict__ Wr,
                         const float* __restrict__ Wread, const float* __restrict__ Wwk,
                         const float* __restrict__ Wwv, const float* __restrict__ Wmix) {
    int i = blockIdx.x * 256 + threadIdx.x;
    if (i < 131072) {
        g_qdown[i] = __float2bfloat16(tern(Wd[i], g_scales[0]));
    } else if (i < 262144) {
        int j = i - 131072;
        g_qup[j] = __float2bfloat16(tern(Wu[j], g_scales[1]));
    } else if (i < 786432) {
        int j = i - 262144;
        g_qops[j] = __float2bfloat16(tern(Wo[j], g_scales[3 + j / OPSZ]));
    } else if (i < 790528) {
        int j = i - 786432;
        g_WrouterE[j] = tern(Wr[j], g_scales[2]) * g_scales[2];
    } else if (i < 806912) {
        int j = i - 790528;
        g_wread_h[j] = __float2bfloat16(Wread[j]);
    } else if (i < 823296) {
        int j = i - 806912;
        g_wwk_h[j] = __float2bfloat16(Wwk[j]);
    } else if (i < 839680) {
        int j = i - 823296;
        g_wwv_h[j] = __float2bfloat16(Wwv[j]);
    } else if (i < 872448) {
        int j = i - 839680;
        g_wmix_h[j] = __float2bfloat16(Wmix[j]);
    } else if (i < 872480) {
        g_counts[i - 872448] = 0;
    } else if (i < 872512) {
        g_cursor[i - 872480] = 0;
    }
}

// ======================= down GEMM (BM=128, 3-stage pipeline) ==============
__global__ void __launch_bounds__(256)
mma_down(const float* __restrict__ hidden, const bf16* __restrict__ B,
         const float* __restrict__ alphaPtr) {
    char* smp = smraw;
    const uint32_t sBase = smem_u32(smp);
    const int tid = threadIdx.x, lane = tid & 31, wid = tid >> 5;
    const int wm = wid & 3, wn = wid >> 2;
    const int bm = blockIdx.x * 128;

    float acc[2][8][4];
    #pragma unroll
    for (int i = 0; i < 2; i++)
        #pragma unroll
        for (int j = 0; j < 8; j++)
            #pragma unroll
            for (int k = 0; k < 4; k++) acc[i][j][k] = 0.f;

    int arow[8], aq[8];
    #pragma unroll
    for (int i = 0; i < 8; i++) {
        int slot = i * 256 + tid;
        arow[i] = slot >> 4;
        aq[i]   = slot & 15;
    }
    int brow[4], bkq[4];
    #pragma unroll
    for (int i = 0; i < 4; i++) {
        int slot = i * 256 + tid;
        brow[i] = slot >> 3;
        bkq[i]  = (slot & 7) * 8;
    }
    auto load = [&](int c, int s) {
        int k0 = c << 6;
        uint32_t dF = sBase + DOWN_F(s);
        uint32_t dB = sBase + DOWN_B(s);
        #pragma unroll
        for (int i = 0; i < 8; i++)
            cp16(dF + (uint32_t)(arow[i] * F_STRIDE + aq[i] * 4) * 4,
                 hidden + (size_t)(bm + arow[i]) * DM + k0 + aq[i] * 4);
        #pragma unroll
        for (int i = 0; i < 4; i++)
            cp16(dB + (uint32_t)(brow[i] * AS_STRIDE + bkq[i]) * 2,
                 B + (size_t)brow[i] * DM + k0 + bkq[i]);
        CP_COMMIT();
    };
    const uint32_t aOff = A_OFF(wm, lane), bOff = B_OFF(wn, lane);

    load(0, 0);
    load(1, 1);
    int s = 0;
    for (int c = 0; c < 16; c++) {
        if (c + 2 < 16) { load(c + 2, (c + 2) % 3); CP_WAIT2(); }
        else if (c + 1 < 16) CP_WAIT1();
        else CP_WAIT0();
        __syncthreads();
        const float* F = (const float*)(smp + DOWN_F(s));
        #pragma unroll
        for (int i = 0; i < 8; i++) {
            float4 v = *(const float4*)(F + arow[i] * F_STRIDE + aq[i] * 4);
            bf16 h0 = __float2bfloat16(v.x), h1 = __float2bfloat16(v.y);
            bf16 h2 = __float2bfloat16(v.z), h3 = __float2bfloat16(v.w);
            int eoff = arow[i] * AS_STRIDE + aq[i] * 4;
            bf16* pH = (bf16*)(smp + DOWN_AH) + eoff;
            bf16* pL = (bf16*)(smp + DOWN_AL) + eoff;
            pH[0] = h0; pH[1] = h1; pH[2] = h2; pH[3] = h3;
            pL[0] = __float2bfloat16(v.x - __bfloat162float(h0));
            pL[1] = __float2bfloat16(v.y - __bfloat162float(h1));
            pL[2] = __float2bfloat16(v.z - __bfloat162float(h2));
            pL[3] = __float2bfloat16(v.w - __bfloat162float(h3));
        }
        __syncthreads();
        uint32_t bAddr = sBase + DOWN_B(s) + bOff;
        compute_chunk(sBase + DOWN_AH + aOff, bAddr, acc);
        compute_chunk(sBase + DOWN_AL + aOff, bAddr, acc);
        s = (s + 1 == 3) ? 0 : s + 1;
    }
    __syncthreads();

    float alpha = *alphaPtr;
    const int row0 = bm + wm * 32, col0 = wn * 64;
    #pragma unroll
    for (int mf = 0; mf < 2; mf++) {
        #pragma unroll
        for (int half = 0; half < 2; half++) {
            int r = row0 + mf * 16 + (lane >> 2) + half * 8;
            #pragma unroll
            for (int nf = 0; nf < 8; nf++) {
                int c = col0 + nf * 8 + (lane & 3) * 2;
                float vx = alpha * acc[mf][nf][half * 2];
                float vy = alpha * acc[mf][nf][half * 2 + 1];
                float* cp = g_reason + (size_t)r * DR + c;
                cp[0] = vx; cp[1] = vy;
                size_t o = (size_t)r * DR + c;
                g_reason_h[o]     = __float2bfloat16(vx);
                g_reason_h[o + 1] = __float2bfloat16(vy);
            }
        }
    }
}

// ======================= generic pipelined HMMA GEMM (up) ==================
__global__ void __launch_bounds__(256)
mma_gemm(const bf16* __restrict__ Ah, int lda,
         const bf16* __restrict__ Bh, int ldb,
         float* __restrict__ C, int ldc, int K,
         const float* __restrict__ alphaPtr,
         const float* __restrict__ res, int ldr)
{
    char* smp = smraw;
    const uint32_t sBase = smem_u32(smp);
    const int tid = threadIdx.x, lane = tid & 31, wid = tid >> 5;
    const int wm = wid & 3, wn = wid >> 2;
    const int bm = blockIdx.x * 128, bn = blockIdx.y * 128;
    const int nk = K >> 6;

    float acc[2][8][4];
    #pragma unroll
    for (int i = 0; i < 2; i++)
        #pragma unroll
        for (int j = 0; j < 8; j++)
            #pragma unroll
            for (int k = 0; k < 4; k++) acc[i][j][k] = 0.f;

    int srow[4], skq[4];
    #pragma unroll
    for (int i = 0; i < 4; i++) {
        int slot = i * 256 + tid;
        srow[i] = slot >> 3;
        skq[i]  = (slot & 7) * 8;
    }
    auto load = [&](int c, int s) {
        int k0 = c << 6;
        const bf16* A = Ah + (size_t)bm * lda + k0;
        const bf16* B = Bh + (size_t)bn * ldb + k0;
        uint32_t dA = sBase + s * STAGE_BYTES;
        uint32_t dB = dA + TILE_BYTES;
        #pragma unroll
        for (int i = 0; i < 4; i++) {
            uint32_t off = (uint32_t)(srow[i] * AS_STRIDE + skq[i]) * 2;
            cp16(dA + off, A + (size_t)srow[i] * lda + skq[i]);
            cp16(dB + off, B + (size_t)srow[i] * ldb + skq[i]);
        }
        CP_COMMIT();
    };
    const uint32_t aOff = A_OFF(wm, lane), bOff = B_OFF(wn, lane);

    load(0, 0);
    for (int c = 0; c < nk; c++) {
        int s = c & 1;
        if (c + 1 < nk) { load(c + 1, (c + 1) & 1); CP_WAIT1(); }
        else CP_WAIT0();
        __syncthreads();
        compute_chunk(sBase + s * STAGE_BYTES + aOff,
                      sBase + s * STAGE_BYTES + TILE_BYTES + bOff, acc);
        __syncthreads();
    }

    float alpha = alphaPtr ? *alphaPtr : 1.0f;
    const int row0 = bm + wm * 32, col0 = bn + wn * 64;
    #pragma unroll
    for (int mf = 0; mf < 2; mf++) {
        #pragma unroll
        for (int half = 0; half < 2; half++) {
            int r = row0 + mf * 16 + (lane >> 2) + half * 8;
            #pragma unroll
            for (int nf = 0; nf < 8; nf++) {
                int c = col0 + nf * 8 + (lane & 3) * 2;
                float vx = alpha * acc[mf][nf][half * 2];
                float vy = alpha * acc[mf][nf][half * 2 + 1];
                if (res) {
                    const float* rp = res + (size_t)r * ldr + c;
                    vx += rp[0]; vy += rp[1];
                }
                float* cp = C + (size_t)r * ldc + c;
                cp[0] = vx; cp[1] = vy;
            }
        }
    }
}

// Dual-B 1-term: blockIdx.y selects {B0->C0} or {B1->C1}
__global__ void __launch_bounds__(256)
mma_gemm2(const bf16* __restrict__ A, int lda,
          const bf16* __restrict__ B0, const bf16* __restrict__ B1, int ldb,
          float* __restrict__ C0, float* __restrict__ C1, int ldc, int K)
{
    char* smp = smraw;
    const uint32_t sBase = smem_u32(smp);
    const int tid = threadIdx.x, lane = tid & 31, wid = tid >> 5;
    const int wm = wid & 3, wn = wid >> 2;
    const int bm = blockIdx.x * 128;
    const bf16* B = blockIdx.y ? B1 : B0;
    float* C = blockIdx.y ? C1 : C0;
    const int nk = K >> 6;

    float acc[2][8][4];
    #pragma unroll
    for (int i = 0; i < 2; i++)
        #pragma unroll
        for (int j = 0; j < 8; j++)
            #pragma unroll
            for (int k = 0; k < 4; k++) acc[i][j][k] = 0.f;

    int srow[4], skq[4];
    #pragma unroll
    for (int i = 0; i < 4; i++) {
        int slot = i * 256 + tid;
        srow[i] = slot >> 3;
        skq[i]  = (slot & 7) * 8;
    }
    auto load = [&](int c, int s) {
        int k0 = c << 6;
        const bf16* Ap = A + (size_t)bm * lda + k0;
        const bf16* Bp = B + k0;
        uint32_t dA = sBase + s * STAGE_BYTES;
        uint32_t dB = dA + TILE_BYTES;
        #pragma unroll
        for (int i = 0; i < 4; i++) {
            uint32_t off = (uint32_t)(srow[i] * AS_STRIDE + skq[i]) * 2;
            cp16(dA + off, Ap + (size_t)srow[i] * lda + skq[i]);
            cp16(dB + off, Bp + (size_t)srow[i] * ldb + skq[i]);
        }
        CP_COMMIT();
    };
    const uint32_t aOff = A_OFF(wm, lane), bOff = B_OFF(wn, lane);

    load(0, 0);
    for (int c = 0; c < nk; c++) {
        int s = c & 1;
        if (c + 1 < nk) { load(c + 1, (c + 1) & 1); CP_WAIT1(); }
        else CP_WAIT0();
        __syncthreads();
        compute_chunk(sBase + s * STAGE_BYTES + aOff,
                      sBase + s * STAGE_BYTES + TILE_BYTES + bOff, acc);
        __syncthreads();
    }
    const int row0 = bm + wm * 32, col0 = wn * 64;
    #pragma unroll
    for (int mf = 0; mf < 2; mf++) {
        #pragma unroll
        for (int half = 0; half < 2; half++) {
            int r = row0 + mf * 16 + (lane >> 2) + half * 8;
            #pragma unroll
            for (int nf = 0; nf < 8; nf++) {
                int c = col0 + nf * 8 + (lane & 3) * 2;
                float* cp = C + (size_t)r * ldc + c;
                cp[0] = acc[mf][nf][half * 2];
                cp[1] = acc[mf][nf][half * 2 + 1];
            }
        }
    }
}

// ======================= unified expert + key launch =======================
__global__ void __launch_bounds__(256)
pass_gemm() {
    char* smp = smraw;
    __shared__ int rowid[128];
    const uint32_t sBase = smem_u32(smp);
    const int tid = threadIdx.x, lane = tid & 31, wid = tid >> 5;
    const int wm = wid & 3, wn = wid >> 2;
    const int b = blockIdx.x;

    int srow[4], skq[4];
    #pragma unroll
    for (int i = 0; i < 4; i++) {
        int slot = i * 256 + tid;
        srow[i] = slot >> 3;
        skq[i]  = (slot & 7) * 8;
    }
    const uint32_t aOff = A_OFF(wm, lane), bOff = B_OFF(wn, lane);

    if (b >= 256) {
        // ---- key = reason_h @ wread^T ----
        const int bm = (b - 256) * 128;
        float acc[2][8][4];
        #pragma unroll
        for (int i = 0; i < 2; i++)
            #pragma unroll
            for (int j = 0; j < 8; j++)
                #pragma unroll
                for (int k = 0; k < 4; k++) acc[i][j][k] = 0.f;
        auto load = [&](int c, int s) {
            int k0 = c << 6;
            uint32_t dA = sBase + s * STAGE_BYTES;
            uint32_t dB = dA + TILE_BYTES;
            #pragma unroll
            for (int i = 0; i < 4; i++) {
                uint32_t off = (uint32_t)(srow[i] * AS_STRIDE + skq[i]) * 2;
                cp16(dA + off, g_reason_h + (size_t)(bm + srow[i]) * DR + k0 + skq[i]);
                cp16(dB + off, g_wread_h + (size_t)srow[i] * DR + k0 + skq[i]);
            }
            CP_COMMIT();
        };
        load(0, 0);
        #pragma unroll
        for (int c = 0; c < 2; c++) {
            int s = c & 1;
            if (c < 1) { load(1, 1); CP_WAIT1(); }
            else CP_WAIT0();
            __syncthreads();
            compute_chunk(sBase + s * STAGE_BYTES + aOff,
                          sBase + s * STAGE_BYTES + TILE_BYTES + bOff, acc);
            __syncthreads();
        }
        const int row0 = bm + wm * 32, col0 = wn * 64;
        #pragma unroll
        for (int mf = 0; mf < 2; mf++) {
            #pragma unroll
            for (int half = 0; half < 2; half++) {
                int r = row0 + mf * 16 + (lane >> 2) + half * 8;
                #pragma unroll
                for (int nf = 0; nf < 8; nf++) {
                    int c = col0 + nf * 8 + (lane & 3) * 2;
                    float* cp = g_key + (size_t)r * DR + c;
                    cp[0] = acc[mf][nf][half * 2];
                    cp[1] = acc[mf][nf][half * 2 + 1];
                }
            }
        }
        return;
    }

    // ---- expert path ----
    const int op = b >> 3;
    int start = 0;
    #pragma unroll
    for (int k = 0; k < NOPS; k++) if (k < op) start += g_counts[k];
    const int cnt = g_counts[op];
    const float alpha = g_scales[3 + op];
    const bf16* B0 = g_qops + (size_t)op * OPSZ;

    auto load = [&](int c, int s) {
        int k0 = c << 6;
        uint32_t dA = sBase + s * STAGE_BYTES;
        uint32_t dB = dA + TILE_BYTES;
        #pragma unroll
        for (int i = 0; i < 4; i++) {
            int grow = rowid[srow[i]];
            if (grow < 0) grow = 0;
            uint32_t off = (uint32_t)(srow[i] * AS_STRIDE + skq[i]) * 2;
            cp16(dA + off, g_reason_h + (size_t)grow * DR + k0 + skq[i]);
            cp16(dB + off, B0 + (size_t)srow[i] * DR + k0 + skq[i]);
        }
        CP_COMMIT();
    };

    for (int t0 = (b & 7) * 128; t0 < cnt; t0 += 8 * 128) {
        __syncthreads();
        if (tid < 128) rowid[tid] = (t0 + tid < cnt) ? g_perm[start + t0 + tid] : -1;
        __syncthreads();
        float acc[2][8][4];
        #pragma unroll
        for (int i = 0; i < 2; i++)
            #pragma unroll
            for (int j = 0; j < 8; j++)
                #pragma unroll
                for (int k = 0; k < 4; k++) acc[i][j][k] = 0.f;

        load(0, 0);
        #pragma unroll
        for (int c = 0; c < 2; c++) {
            int s = c & 1;
            if (c < 1) { load(1, 1); CP_WAIT1(); }
            else CP_WAIT0();
            __syncthreads();
            compute_chunk(sBase + s * STAGE_BYTES + aOff,
                          sBase + s * STAGE_BYTES + TILE_BYTES + bOff, acc);
            __syncthreads();
        }
        const int row0 = wm * 32, col0 = wn * 64;
        #pragma unroll
        for (int mf = 0; mf < 2; mf++) {
            #pragma unroll
            for (int half = 0; half < 2; half++) {
                int rl = row0 + mf * 16 + (lane >> 2) + half * 8;
                if (t0 + rl < cnt) {
                    float* cp0 = g_contrib + (size_t)(start + t0 + rl) * DR;
                    #pragma unroll
                    for (int nf = 0; nf < 8; nf++) {
                        int c = col0 + nf * 8 + (lane & 3) * 2;
                        cp0[c]     = alpha * acc[mf][nf][half * 2];
                        cp0[c + 1] = alpha * acc[mf][nf][half * 2 + 1];
                    }
                }
            }
        }
    }
}

// ======================= mix GEMM + fused LayerNorm (+ counter reset) ======
__global__ void __launch_bounds__(256)
mma_mix_ln(const bf16* __restrict__ A, const bf16* __restrict__ B,
           const float* __restrict__ gamma, const float* __restrict__ beta)
{
    char* smp = smraw;
    const uint32_t sBase = smem_u32(smp);
    float* tmpsm = (float*)smp;
    __shared__ float musm[128], rssm[128];
    const int tid = threadIdx.x, lane = tid & 31, wid = tid >> 5;
    const int wm = wid & 3, wn = wid >> 2;
    const int bm = blockIdx.x * 128;
    const int nk = 4;

    float acc[2][8][4];
    #pragma unroll
    for (int i = 0; i < 2; i++)
        #pragma unroll
        for (int j = 0; j < 8; j++)
            #pragma unroll
            for (int k = 0; k < 4; k++) acc[i][j][k] = 0.f;

    int srow[4], skq[4];
    #pragma unroll
    for (int i = 0; i < 4; i++) {
        int slot = i * 256 + tid;
        srow[i] = slot >> 3;
        skq[i]  = (slot & 7) * 8;
    }
    auto load = [&](int c, int s) {
        int k0 = c << 6;
        const bf16* Ap = A + (size_t)bm * 256 + k0;
        const bf16* Bp = B + k0;
        uint32_t dA = sBase + s * STAGE_BYTES;
        uint32_t dB = dA + TILE_BYTES;
        #pragma unroll
        for (int i = 0; i < 4; i++) {
            uint32_t off = (uint32_t)(srow[i] * AS_STRIDE + skq[i]) * 2;
            cp16(dA + off, Ap + (size_t)srow[i] * 256 + skq[i]);
            cp16(dB + off, Bp + (size_t)srow[i] * 256 + skq[i]);
        }
        CP_COMMIT();
    };
    const uint32_t aOff = A_OFF(wm, lane), bOff = B_OFF(wn, lane);

    load(0, 0);
    for (int c = 0; c < nk; c++) {
        int s = c & 1;
        if (c + 1 < nk) { load(c + 1, (c + 1) & 1); CP_WAIT1(); }
        else CP_WAIT0();
        __syncthreads();
        compute_chunk(sBase + s * STAGE_BYTES + aOff,
                      sBase + s * STAGE_BYTES + TILE_BYTES + bOff, acc);
        __syncthreads();
    }

    const int row0 = wm * 32, col0 = wn * 64;
    #pragma unroll
    for (int mf = 0; mf < 2; mf++) {
        #pragma unroll
        for (int half = 0; half < 2; half++) {
            int r = row0 + mf * 16 + (lane >> 2) + half * 8;
            #pragma unroll
            for (int nf = 0; nf < 8; nf++) {
                int c = col0 + nf * 8 + (lane & 3) * 2;
                const float* rp = g_reason + (size_t)(bm + r) * DR + c;
                tmpsm[r * 129 + c]     = acc[mf][nf][half * 2]     + rp[0];
                tmpsm[r * 129 + c + 1] = acc[mf][nf][half * 2 + 1] + rp[1];
            }
        }
    }
    __syncthreads();
    if (tid < 128) {
        float mu = 0.f, sq = 0.f;
        #pragma unroll 8
        for (int k = 0; k < 128; k++) {
            float v = tmpsm[tid * 129 + k];
            mu += v; sq += v * v;
        }
        mu *= (1.f / 128.f);
        float var = sq * (1.f / 128.f) - mu * mu;
        musm[tid] = mu;
        rssm[tid] = rsqrtf(var + 1e-5f);
    }
    __syncthreads();
    for (int idx = tid; idx < 128 * 32; idx += 256) {
        int r = idx >> 5, c = (idx & 31) * 4;
        float mu = musm[r], rs = rssm[r];
        float o0 = (tmpsm[r * 129 + c]     - mu) * rs * gamma[c]     + beta[c];
        float o1 = (tmpsm[r * 129 + c + 1] - mu) * rs * gamma[c + 1] + beta[c + 1];
        float o2 = (tmpsm[r * 129 + c + 2] - mu) * rs * gamma[c + 2] + beta[c + 2];
        float o3 = (tmpsm[r * 129 + c + 3] - mu) * rs * gamma[c + 3] + beta[c + 3];
        size_t o = (size_t)(bm + r) * DR + c;
        *(float4*)(g_reason + o) = make_float4(o0, o1, o2, o3);
        g_reason_h[o]     = __float2bfloat16(o0);
        g_reason_h[o + 1] = __float2bfloat16(o1);
        g_reason_h[o + 2] = __float2bfloat16(o2);
        g_reason_h[o + 3] = __float2bfloat16(o3);
    }
    if (blockIdx.x == 0 && tid < NOPS) { g_counts[tid] = 0; g_cursor[tid] = 0; }
}

// ======================= router / bookkeeping ==============================
__global__ void __launch_bounds__(128)
router_kernel() {
    __shared__ float Wsm[NOPS][DR + 1];
    __shared__ float rsm[4][DR];
    int tid = threadIdx.x;
    for (int i = tid; i < NOPS * DR; i += 128) Wsm[i >> 7][i & 127] = g_WrouterE[i];
    __syncthreads();
    int warp = tid >> 5, lane = tid & 31;
    for (int t = blockIdx.x * 4 + warp; t < M_TOK; t += gridDim.x * 4) {
        float4 v = ((const float4*)(g_reason + (size_t)t * DR))[lane];
        ((float4*)rsm[warp])[lane] = v;
        __syncwarp();
        float logit = 0.f;
        #pragma unroll 8
        for (int k = 0; k < DR; k++) logit += rsm[warp][k] * Wsm[lane][k];
        float m1 = logit; int i1 = lane;
        #pragma unroll
        for (int o = 16; o; o >>= 1) {
            float om = __shfl_xor_sync(~0u, m1, o);
            int   oi = __shfl_xor_sync(~0u, i1, o);
            if (om > m1 || (om == m1 && oi < i1)) { m1 = om; i1 = oi; }
        }
        float l2 = (lane == i1) ? -CUDART_INF_F : logit;
        float m2 = l2; int i2 = lane;
        #pragma unroll
        for (int o = 16; o; o >>= 1) {
            float om = __shfl_xor_sync(~0u, m2, o);
            int   oi = __shfl_xor_sync(~0u, i2, o);
            if (om > m2 || (om == m2 && oi < i2)) { m2 = om; i2 = oi; }
        }
        if (lane == 0) {
            float e = expf(m2 - m1);
            g_idx[2*t]   = i1; g_idx[2*t+1] = i2;
            g_w[2*t]     = 1.f / (1.f + e);
            g_w[2*t+1]   = e / (1.f + e);
            atomicAdd(&g_counts[i1], 1);
            atomicAdd(&g_counts[i2], 1);
        }
        __syncwarp();
    }
}
__global__ void scatter2() {
    int i = blockIdx.x * blockDim.x + threadIdx.x;
    if (i < NASSIGN) {
        int op = g_idx[i];
        int base = 0;
        for (int k = 0; k < op; k++) base += g_counts[k];
        int p = base + atomicAdd(&g_cursor[op], 1);
        g_perm[p] = i >> 1;
        g_pos[i]  = p;
    }
}

__global__ void __launch_bounds__(128)
combine_memread(const float* __restrict__ slots) {
    __shared__ float ssm[NSLOTS][DR + 1];
    __shared__ float rsm[4][DR];
    __shared__ float attn_s[4][NSLOTS];
    int tid = threadIdx.x;
    for (int i = tid; i < NSLOTS * DR; i += 128) ssm[i >> 7][i & 127] = slots[i];
    __syncthreads();
    int warp = tid >> 5, lane = tid & 31;
    const float inv_sqrt_d = 0.08838834764831845f;
    for (int t = blockIdx.x * 4 + warp; t < M_TOK; t += gridDim.x * 4) {
        int p0 = g_pos[2*t], p1 = g_pos[2*t+1];
        float w0 = g_w[2*t], w1 = g_w[2*t+1];
        float4 c0 = ((const float4*)(g_contrib + (size_t)p0 * DR))[lane];
        float4 c1 = ((const float4*)(g_contrib + (size_t)p1 * DR))[lane];
        size_t ob = (size_t)t * 256 + lane * 4;
        g_cat_h[ob]     = __float2bfloat16(w0 * c0.x + w1 * c1.x);
        g_cat_h[ob + 1] = __float2bfloat16(w0 * c0.y + w1 * c1.y);
        g_cat_h[ob + 2] = __float2bfloat16(w0 * c0.z + w1 * c1.z);
        g_cat_h[ob + 3] = __float2bfloat16(w0 * c0.w + w1 * c1.w);
        float4 v = ((const float4*)(g_key + (size_t)t * DR))[lane];
        ((float4*)rsm[warp])[lane] = v;
        __syncwarp();
        float logit = -CUDART_INF_F;
        if (lane < NSLOTS) {
            float s = 0.f;
            #pragma unroll 8
            for (int k = 0; k < DR; k++) s += rsm[warp][k] * ssm[lane][k];
            logit = s * inv_sqrt_d;
        }
        float mx = logit;
        #pragma unroll
        for (int o = 16; o; o >>= 1) mx = fmaxf(mx, __shfl_xor_sync(~0u, mx, o));
        float e = (lane < NSLOTS) ? expf(logit - mx) : 0.f;
        float se = e;
        #pragma unroll
        for (int o = 16; o; o >>= 1) se += __shfl_xor_sync(~0u, se, o);
        if (lane < NSLOTS) attn_s[warp][lane] = e / se;
        __syncwarp();
        float ov[4] = {0.f, 0.f, 0.f, 0.f};
        #pragma unroll
        for (int s2 = 0; s2 < NSLOTS; s2++) {
            float a = attn_s[warp][s2];
            ov[0] += a * ssm[s2][lane*4+0];
            ov[1] += a * ssm[s2][lane*4+1];
            ov[2] += a * ssm[s2][lane*4+2];
            ov[3] += a * ssm[s2][lane*4+3];
        }
        g_cat_h[ob + 128] = __float2bfloat16(ov[0]);
        g_cat_h[ob + 129] = __float2bfloat16(ov[1]);
        g_cat_h[ob + 130] = __float2bfloat16(ov[2]);
        g_cat_h[ob + 131] = __float2bfloat16(ov[3]);
        __syncwarp();
    }
}

__global__ void __launch_bounds__(128)
write_kernel(const float* __restrict__ slots, const float* __restrict__ Wg,
             const float* __restrict__ wsp) {
    __shared__ float ssm[NSLOTS][DR + 1];
    __shared__ float wgs[DR];
    __shared__ float rsm[4][DR];
    __shared__ float attn_s[4][NSLOTS];
    int tid = threadIdx.x;
    for (int i = tid; i < NSLOTS * DR; i += 128) ssm[i >> 7][i & 127] = slots[i];
    wgs[tid] = Wg[tid];
    __syncthreads();
    int warp = tid >> 5, lane = tid & 31;
    float ws = *wsp;
    const float inv_sqrt_d = 0.08838834764831845f;
    for (int t = blockIdx.x * 4 + warp; t < M_TOK; t += gridDim.x * 4) {
        float4 r = ((const float4*)(g_reason + (size_t)t * DR))[lane];
        float4 wg4 = ((const float4*)wgs)[lane];
        float gd = r.x*wg4.x + r.y*wg4.y + r.z*wg4.z + r.w*wg4.w;
        #pragma unroll
        for (int o = 16; o; o >>= 1) gd += __shfl_xor_sync(~0u, gd, o);
        float wg = 1.f / (1.f + expf(-gd));
        float4 k4 = ((const float4*)(g_key + (size_t)t * DR))[lane];
        ((float4*)rsm[warp])[lane] = k4;
        __syncwarp();
        float logit = -CUDART_INF_F;
        if (lane < NSLOTS) {
            float sdot = 0.f;
            #pragma unroll 8
            for (int k = 0; k < DR; k++) sdot += rsm[warp][k] * ssm[lane][k];
            logit = sdot * inv_sqrt_d;
        }
        float mx = logit;
        #pragma unroll
        for (int o = 16; o; o >>= 1) mx = fmaxf(mx, __shfl_xor_sync(~0u, mx, o));
        float e = (lane < NSLOTS) ? expf(logit - mx) : 0.f;
        float se = e;
        #pragma unroll
        for (int o = 16; o; o >>= 1) se += __shfl_xor_sync(~0u, se, o);
        if (lane < NSLOTS) attn_s[warp][lane] = e / se;
        __syncwarp();
        float4 wv = ((const float4*)(g_tmp + (size_t)t * DR))[lane];
        float ov[4];
        ov[0] = wg * wv.x; ov[1] = wg * wv.y; ov[2] = wg * wv.z; ov[3] = wg * wv.w;
        #pragma unroll
        for (int s2 = 0; s2 < NSLOTS; s2++) {
            float a = 0.1f * attn_s[warp][s2];
            ov[0] += a * ssm[s2][lane*4+0];
            ov[1] += a * ssm[s2][lane*4+1];
            ov[2] += a * ssm[s2][lane*4+2];
            ov[3] += a * ssm[s2][lane*4+3];
        }
        float o4[4];
        o4[0] = r.x + ws * ov[0]; o4[1] = r.y + ws * ov[1];
        o4[2] = r.z + ws * ov[2]; o4[3] = r.w + ws * ov[3];
        size_t o = (size_t)t * DR + lane * 4;
        *(float4*)(g_reason + o) = make_float4(o4[0], o4[1], o4[2], o4[3]);
        g_reason_h[o]     = __float2bfloat16(o4[0]);
        g_reason_h[o + 1] = __float2bfloat16(o4[1]);
        g_reason_h[o + 2] = __float2bfloat16(o4[2]);
        g_reason_h[o + 3] = __float2bfloat16(o4[3]);
        __syncwarp();
    }
}

// ======================= launch ============================================
extern "C" void kernel_launch(void* const* d_in, const int* in_sizes, int n_in,
                              void* d_out, int out_size) {
    const float* hidden   = (const float*)d_in[0];
    const float* W_down   = (const float*)d_in[2];
    const float* W_up     = (const float*)d_in[3];
    const float* ops      = (const float*)d_in[4];
    const float* W_router = (const float*)d_in[5];
    const float* slots    = (const float*)d_in[6];
    const float* W_read   = (const float*)d_in[7];
    const float* W_wk     = (const float*)d_in[8];
    const float* W_wg     = (const float*)d_in[9];
    const float* W_wv     = (const float*)d_in[10];
    const float* W_mix    = (const float*)d_in[11];
    const float* gamma    = (const float*)d_in[12];
    const float* beta     = (const float*)d_in[13];
    const float* wscale   = (const float*)d_in[14];
    float* out = (float*)d_out;

    static bool attr_done = false;
    if (!attr_done) {
        cudaFuncSetAttribute(mma_down,   cudaFuncAttributeMaxDynamicSharedMemorySize, SMEM_DOWN);
        cudaFuncSetAttribute(mma_gemm,   cudaFuncAttributeMaxDynamicSharedMemorySize, SMEM_PIPE);
        cudaFuncSetAttribute(mma_gemm2,  cudaFuncAttributeMaxDynamicSharedMemorySize, SMEM_PIPE);
        cudaFuncSetAttribute(mma_mix_ln, cudaFuncAttributeMaxDynamicSharedMemorySize, SMEM_PIPE);
        cudaFuncSetAttribute(pass_gemm,  cudaFuncAttributeMaxDynamicSharedMemorySize, SMEM_PIPE);
        attr_done = true;
    }

    float *pTmp, *pKey, *pScales;
    bf16 *pReasH, *pCatH, *pQdown, *pQup, *pWwkH, *pWwvH, *pWmixH;
    cudaGetSymbolAddress((void**)&pTmp,    g_tmp);
    cudaGetSymbolAddress((void**)&pKey,    g_key);
    cudaGetSymbolAddress((void**)&pScales, g_scales);
    cudaGetSymbolAddress((void**)&pReasH,  g_reason_h);
    cudaGetSymbolAddress((void**)&pCatH,   g_cat_h);
    cudaGetSymbolAddress((void**)&pQdown,  g_qdown);
    cudaGetSymbolAddress((void**)&pQup,    g_qup);
    cudaGetSymbolAddress((void**)&pWwkH,   g_wwk_h);
    cudaGetSymbolAddress((void**)&pWwvH,   g_wwv_h);
    cudaGetSymbolAddress((void**)&pWmixH,  g_wmix_h);

    absmean_all<<<dim3(16, 35), 256>>>(W_down, W_up, W_router, ops);
    absmean_p2<<<1, 64>>>();
    prep_all<<<3409, 256>>>(W_down, W_up, ops, W_router, W_read, W_wk, W_wv, W_mix);

    mma_down<<<128, 256, SMEM_DOWN>>>(hidden, pQdown, pScales + 0);

    for (int pass = 0; pass < DEPTH; pass++) {
        router_kernel<<<592, 128>>>();
        scatter2<<<NASSIGN/256, 256>>>();
        pass_gemm<<<384, 256, SMEM_PIPE>>>();
        combine_memread<<<592, 128>>>(slots);
        mma_mix_ln<<<M_TOK/128, 256, SMEM_PIPE>>>(pCatH, pWmixH, gamma, beta);
    }

    mma_gemm2<<<dim3(M_TOK/128, 2), 256, SMEM_PIPE>>>(pReasH, DR, pWwkH, pWwvH, DR,
        pKey, pTmp, DR, DR);
    write_kernel<<<592, 128>>>(slots, W_wg, wscale);

    mma_gemm<<<dim3(M_TOK/128, DM/128), 256, SMEM_PIPE>>>(pReasH, DR, pQup, DR,
        out, DM, DR, pScales + 1, hidden, DM);
}